// round 12
// baseline (speedup 1.0000x reference)
#include <cuda_runtime.h>
#include <cuda_bf16.h>
#include <cuda_fp16.h>
#include <math.h>
#include <stdint.h>

#define T_SEQ 2048
#define C_DIM 1024
#define NH    16
#define NKV   4
#define DHD   64
#define WINSZ 128
#define PSTR  1664          /* Q(1024) | K(256) | V(256) | gate(16 + 112 pad) */
#define KOFF  1024
#define VOFF  1280
#define GOFF  1536
#define GATE_BLK 12

// ---------------- scratch ----------------
__device__ float g_P[T_SEQ * PSTR];
__device__ float g_D[NH * T_SEQ];
__device__ float g_L[NH * T_SEQ];
__device__ float g_Y[T_SEQ * C_DIM];
__device__ __half g_Xh[T_SEQ * C_DIM];
__device__ __half g_Xl[T_SEQ * C_DIM];
__device__ __half g_Yh[T_SEQ * C_DIM];
__device__ __half g_Wp_h[PSTR * C_DIM];
__device__ __half g_Wp_l[PSTR * C_DIM];
__device__ __half g_Wc_h[C_DIM * C_DIM];
__device__ __half g_Wc_l[C_DIM * C_DIM];

__device__ __forceinline__ float neg_inf() { return __int_as_float(0xff800000); }
__device__ __forceinline__ float log_sigmoid_f(float x) {
    return fminf(x, 0.f) - log1pf(expf(-fabsf(x)));
}
__device__ __forceinline__ uint32_t cvta_smem(const void* p) {
    uint32_t a;
    asm("{ .reg .u64 t; cvta.to.shared.u64 t, %1; cvt.u32.u64 %0, t; }" : "=r"(a) : "l"(p));
    return a;
}
__device__ __forceinline__ uint32_t pack2bf(float a, float b) {
    __nv_bfloat162 t = __floats2bfloat162_rn(a, b);
    return *reinterpret_cast<uint32_t*>(&t);
}
__device__ __forceinline__ uint32_t pack2h(float a, float b) {
    __half2 t = __floats2half2_rn(a, b);
    return *reinterpret_cast<uint32_t*>(&t);
}
__device__ __forceinline__ void ldsm4(uint32_t* r, uint32_t addr) {
    asm volatile("ldmatrix.sync.aligned.m8n8.x4.shared.b16 {%0,%1,%2,%3}, [%4];"
                 : "=r"(r[0]), "=r"(r[1]), "=r"(r[2]), "=r"(r[3]) : "r"(addr));
}
__device__ __forceinline__ void ldsm4t(uint32_t* r, uint32_t addr) {
    asm volatile("ldmatrix.sync.aligned.m8n8.x4.trans.shared.b16 {%0,%1,%2,%3}, [%4];"
                 : "=r"(r[0]), "=r"(r[1]), "=r"(r[2]), "=r"(r[3]) : "r"(addr));
}
__device__ __forceinline__ void mma_bf16(float* c, const uint32_t* a, const uint32_t* b) {
    asm volatile(
        "mma.sync.aligned.m16n8k16.row.col.f32.bf16.bf16.f32 "
        "{%0,%1,%2,%3}, {%4,%5,%6,%7}, {%8,%9}, {%0,%1,%2,%3};"
        : "+f"(c[0]), "+f"(c[1]), "+f"(c[2]), "+f"(c[3])
        : "r"(a[0]), "r"(a[1]), "r"(a[2]), "r"(a[3]), "r"(b[0]), "r"(b[1]));
}
__device__ __forceinline__ void mma_fp16(float* c, const uint32_t* a, const uint32_t* b) {
    asm volatile(
        "mma.sync.aligned.m16n8k16.row.col.f32.f16.f16.f32 "
        "{%0,%1,%2,%3}, {%4,%5,%6,%7}, {%8,%9}, {%0,%1,%2,%3};"
        : "+f"(c[0]), "+f"(c[1]), "+f"(c[2]), "+f"(c[3])
        : "r"(a[0]), "r"(a[1]), "r"(a[2]), "r"(a[3]), "r"(b[0]), "r"(b[1]));
}
__device__ __forceinline__ void sts8(uint32_t addr, uint32_t a, uint32_t b) {
    asm volatile("st.shared.v2.b32 [%0], {%1,%2};" :: "r"(addr), "r"(a), "r"(b) : "memory");
}
__device__ __forceinline__ void cpasync16(uint32_t dst, const void* src) {
    asm volatile("cp.async.cg.shared.global [%0], [%1], 16;" :: "r"(dst), "l"(src) : "memory");
}
#define CP_COMMIT() asm volatile("cp.async.commit_group;" ::: "memory")
#define CP_WAIT(n)  asm volatile("cp.async.wait_group %0;" :: "n"(n) : "memory")

// swizzled offset within a 128x16 (16-bit elem) tile (4KB)
__device__ __forceinline__ uint32_t phys16(int row, int c) {
    return (uint32_t)((row >> 2) * 128 + (((((row & 3) * 2) + c) ^ ((row >> 2) & 1)) * 16));
}

// load 64x64 fp32 tile -> split bf16 hi/lo into swizzled smem (attn kernel)
__device__ __forceinline__ void load_split_tile(
    const float* __restrict__ gsrc, uint32_t smH, uint32_t smL, int tid)
{
#pragma unroll
    for (int i = 0; i < 4; i++) {
        int f = tid + i * 256;
        int r = f >> 4, q4 = f & 15;
        float4 v = *reinterpret_cast<const float4*>(gsrc + (size_t)r * PSTR + q4 * 4);
        float hx = __bfloat162float(__float2bfloat16_rn(v.x));
        float hy = __bfloat162float(__float2bfloat16_rn(v.y));
        float hz = __bfloat162float(__float2bfloat16_rn(v.z));
        float hw = __bfloat162float(__float2bfloat16_rn(v.w));
        uint32_t phys = (uint32_t)r * 128u + (uint32_t)(((q4 >> 1) ^ (r & 7)) * 16) + (uint32_t)((q4 & 1) * 8);
        sts8(smH + phys, pack2bf(hx, hy), pack2bf(hz, hw));
        sts8(smL + phys, pack2bf(v.x - hx, v.y - hy), pack2bf(v.z - hz, v.w - hw));
    }
}

// ---------------- merged weight transpose + fp16 split ----------------
__global__ __launch_bounds__(256) void transpose_split_all(
    const float* __restrict__ Wq, const float* __restrict__ Wk,
    const float* __restrict__ Wv, const float* __restrict__ Wc,
    const float* __restrict__ Wg, const float* __restrict__ rmsw,
    __half* __restrict__ Wph, __half* __restrict__ Wpl,
    __half* __restrict__ Wch, __half* __restrict__ Wcl)
{
    int z = blockIdx.z;
    const float* W; __half *Th, *Tl; int N, rowOff = 0; bool useScale = false;
    if (z == 0)      { W = Wq; Th = Wph; Tl = Wpl; N = 1024; }
    else if (z == 1) { W = Wk; Th = Wph; Tl = Wpl; N = 256; rowOff = KOFF; }
    else if (z == 2) { W = Wv; Th = Wph; Tl = Wpl; N = 256; rowOff = VOFF; }
    else if (z == 3) { W = Wc; Th = Wch; Tl = Wcl; N = 1024; useScale = true; }
    else             { W = Wg; Th = Wph; Tl = Wpl; N = 16;  rowOff = GOFF; }
    int n0 = blockIdx.x * 32;
    if (n0 >= N) return;
    int k0 = blockIdx.y * 32;

    __shared__ float s[32][33];
    int tx = threadIdx.x & 31, ty = threadIdx.x >> 5;
#pragma unroll
    for (int i = 0; i < 4; i++) {
        int r = ty + i * 8;
        if (n0 + tx < N) {
            float v = W[(size_t)(k0 + r) * N + n0 + tx];
            if (useScale) v *= rmsw[k0 + r];
            s[r][tx] = v;
        }
    }
    __syncthreads();
#pragma unroll
    for (int i = 0; i < 4; i++) {
        int r = ty + i * 8;
        if (n0 + r < N) {
            float v = s[tx][r];
            __half h = __float2half_rn(v);
            Th[(size_t)(rowOff + n0 + r) * C_DIM + k0 + tx] = h;
            Tl[(size_t)(rowOff + n0 + r) * C_DIM + k0 + tx] = __float2half_rn(v - __half2float(h));
        }
    }
}

// ---------------- activation fp16 split (x) ----------------
__global__ __launch_bounds__(256) void split_act(
    const float* __restrict__ X, __half* __restrict__ Ah, __half* __restrict__ Al)
{
    int t = blockIdx.x, tid = threadIdx.x;
    float4 v = *reinterpret_cast<const float4*>(X + (size_t)t * C_DIM + tid * 4);
    float h0 = __half2float(__float2half_rn(v.x));
    float h1 = __half2float(__float2half_rn(v.y));
    float h2 = __half2float(__float2half_rn(v.z));
    float h3 = __half2float(__float2half_rn(v.w));
    uint2 hh = make_uint2(pack2h(h0, h1), pack2h(h2, h3));
    uint2 ll = make_uint2(pack2h(v.x - h0, v.y - h1), pack2h(v.z - h2, v.w - h3));
    *reinterpret_cast<uint2*>(Ah + (size_t)t * C_DIM + tid * 4) = hh;
    *reinterpret_cast<uint2*>(Al + (size_t)t * C_DIM + tid * 4) = ll;
}

// ---------------- Y -> fp16 with fused RMSNorm row scale ----------------
__global__ __launch_bounds__(256) void norm_to_fp16(
    const float* __restrict__ X, __half* __restrict__ Ah)
{
    int t = blockIdx.x, tid = threadIdx.x;
    float4 v = *reinterpret_cast<const float4*>(X + (size_t)t * C_DIM + tid * 4);
    float ss = v.x * v.x + v.y * v.y + v.z * v.z + v.w * v.w;
#pragma unroll
    for (int off = 16; off; off >>= 1) ss += __shfl_xor_sync(0xffffffff, ss, off);
    __shared__ float red[8];
    if ((tid & 31) == 0) red[tid >> 5] = ss;
    __syncthreads();
    float s = red[0];
#pragma unroll
    for (int i = 1; i < 8; i++) s += red[i];
    float scale = rsqrtf(s * (1.f / (float)C_DIM) + 1e-5f);
    uint2 hh = make_uint2(pack2h(v.x * scale, v.y * scale), pack2h(v.z * scale, v.w * scale));
    *reinterpret_cast<uint2*>(Ah + (size_t)t * C_DIM + tid * 4) = hh;
}

// ---------------- proj GEMM: fp16 A x (Bh+Bl), k-tile 32, 3 stages ----------------
// stage 32KB: A[0:8K) | Bh[8K:16K) | Bl[16K:24K) | Al[24K:32K) (Al only for gate CTAs)
// Each 8KB tile = two 128x16 subtiles (4KB each, phys16-swizzled).
__global__ __launch_bounds__(256, 2) void gemm_proj_f16(
    const __half* __restrict__ Ah, const __half* __restrict__ Al,
    const __half* __restrict__ Bh, const __half* __restrict__ Bl,
    float* __restrict__ C, int M, int N, int K)
{
    extern __shared__ char smc[];
    uint32_t sb = cvta_smem(smc);
    const uint32_t STG = 32768u;

    int tid = threadIdx.x, lane = tid & 31, warp = tid >> 5;
    int wm = warp & 3, wn = warp >> 2;
    int m0 = blockIdx.y * 128, n0 = blockIdx.x * 128;
    bool prec = ((int)blockIdx.x == GATE_BLK);

    int lrow = tid >> 1;
    uint32_t dSub = (tid & 1) ? 4096u : 0u;
    uint32_t p0 = phys16(lrow, 0), p1 = phys16(lrow, 1);
    int so = (tid & 1) * 16;
    const __half* gA  = Ah + (size_t)(m0 + lrow) * K + so;
    const __half* gAl = Al + (size_t)(m0 + lrow) * K + so;
    const __half* gBh = Bh + (size_t)(n0 + lrow) * K + so;
    const __half* gBl = Bl + (size_t)(n0 + lrow) * K + so;

    int nkt = K / 32;
    float acc[2][8][4] = {};

#pragma unroll
    for (int p = 0; p < 2; p++) {
        uint32_t st = sb + (uint32_t)p * STG;
        int kb = p * 32;
        cpasync16(st + dSub + p0,           gA + kb);
        cpasync16(st + dSub + p1,           gA + kb + 8);
        cpasync16(st + 8192u + dSub + p0,   gBh + kb);
        cpasync16(st + 8192u + dSub + p1,   gBh + kb + 8);
        cpasync16(st + 16384u + dSub + p0,  gBl + kb);
        cpasync16(st + 16384u + dSub + p1,  gBl + kb + 8);
        if (prec) {
            cpasync16(st + 24576u + dSub + p0, gAl + kb);
            cpasync16(st + 24576u + dSub + p1, gAl + kb + 8);
        }
        CP_COMMIT();
    }

    int aRow = (lane & 15), aC = lane >> 4;
    int bRowBase = (lane & 7) + ((lane >> 4) << 3);
    int bC = (lane >> 3) & 1;

    for (int kt = 0; kt < nkt; ++kt) {
        if (kt + 2 < nkt) { CP_WAIT(1); } else { CP_WAIT(0); }
        __syncthreads();

        uint32_t st = sb + (uint32_t)(kt % 3) * STG;
#pragma unroll
        for (int s = 0; s < 2; s++) {
            uint32_t sA  = st + (uint32_t)s * 4096u;
            uint32_t sBh = st + 8192u + (uint32_t)s * 4096u;
            uint32_t sBl = st + 16384u + (uint32_t)s * 4096u;
            uint32_t sAl = st + 24576u + (uint32_t)s * 4096u;

            uint32_t ah[2][4], al[2][4];
#pragma unroll
            for (int t = 0; t < 2; t++) {
                int r = wm * 32 + t * 16 + aRow;
                ldsm4(ah[t], sA + phys16(r, aC));
            }
            if (prec) {
#pragma unroll
                for (int t = 0; t < 2; t++) {
                    int r = wm * 32 + t * 16 + aRow;
                    ldsm4(al[t], sAl + phys16(r, aC));
                }
            }
#pragma unroll
            for (int g = 0; g < 4; g++) {
                int r = wn * 64 + g * 16 + bRowBase;
                uint32_t bh[4], bl[4];
                ldsm4(bh, sBh + phys16(r, bC));
                ldsm4(bl, sBl + phys16(r, bC));
#pragma unroll
                for (int t = 0; t < 2; t++)
#pragma unroll
                    for (int jj = 0; jj < 2; jj++) {
                        int j = g * 2 + jj;
                        mma_fp16(acc[t][j], ah[t], &bh[2 * jj]);
                        mma_fp16(acc[t][j], ah[t], &bl[2 * jj]);
                    }
                if (prec) {
#pragma unroll
                    for (int t = 0; t < 2; t++)
#pragma unroll
                        for (int jj = 0; jj < 2; jj++)
                            mma_fp16(acc[t][g * 2 + jj], al[t], &bh[2 * jj]);
                }
            }
        }

        if (kt + 2 < nkt) {
            uint32_t st2 = sb + (uint32_t)((kt + 2) % 3) * STG;
            int kb = (kt + 2) * 32;
            cpasync16(st2 + dSub + p0,           gA + kb);
            cpasync16(st2 + dSub + p1,           gA + kb + 8);
            cpasync16(st2 + 8192u + dSub + p0,   gBh + kb);
            cpasync16(st2 + 8192u + dSub + p1,   gBh + kb + 8);
            cpasync16(st2 + 16384u + dSub + p0,  gBl + kb);
            cpasync16(st2 + 16384u + dSub + p1,  gBl + kb + 8);
            if (prec) {
                cpasync16(st2 + 24576u + dSub + p0, gAl + kb);
                cpasync16(st2 + 24576u + dSub + p1, gAl + kb + 8);
            }
            CP_COMMIT();
        }
    }

    // RoPE epilogue (Q,K head columns only)
    if ((n0 + wn * 64) < 1280) {
#pragma unroll
        for (int j = 0; j < 4; j++) {
#pragma unroll
            for (int e = 0; e < 2; e++) {
                int d = j * 8 + 2 * (lane & 3) + e;
                float invf = expf(-(float)(2 * d) * (9.210340371976184f / 64.f));
#pragma unroll
                for (int mt = 0; mt < 2; mt++) {
#pragma unroll
                    for (int rh = 0; rh < 2; rh++) {
                        int trow = m0 + wm * 32 + mt * 16 + (lane >> 2) + rh * 8;
                        float sn, cs;
                        sincosf((float)trow * invf, &sn, &cs);
                        int k = 2 * rh + e;
                        float a = acc[mt][j][k], b = acc[mt][j + 4][k];
                        acc[mt][j][k]     = a * cs - b * sn;
                        acc[mt][j + 4][k] = b * cs + a * sn;
                    }
                }
            }
        }
    }

#pragma unroll
    for (int t = 0; t < 2; t++) {
        int r0 = m0 + wm * 32 + t * 16 + (lane >> 2);
#pragma unroll
        for (int j = 0; j < 8; j++) {
            int col = n0 + wn * 64 + j * 8 + 2 * (lane & 3);
            *reinterpret_cast<float2*>(C + (size_t)r0 * N + col) = make_float2(acc[t][j][0], acc[t][j][1]);
            *reinterpret_cast<float2*>(C + (size_t)(r0 + 8) * N + col) = make_float2(acc[t][j][2], acc[t][j][3]);
        }
    }
}

// ---------------- out GEMM: fp16 A x (Bh+Bl), k-tile 32, 3 stages ----------------
// stage 24KB: A[0:8K) | Bh[8K:16K) | Bl[16K:24K)
__global__ __launch_bounds__(256, 2) void gemm_out_f16(
    const __half* __restrict__ Ah, const __half* __restrict__ Bh,
    const __half* __restrict__ Bl, float* __restrict__ C,
    int M, int N, int K)
{
    extern __shared__ char smc[];
    uint32_t sb = cvta_smem(smc);
    const uint32_t STG = 24576u;

    int tid = threadIdx.x, lane = tid & 31, warp = tid >> 5;
    int wm = warp & 3, wn = warp >> 2;
    int m0 = blockIdx.y * 128, n0 = blockIdx.x * 128;

    int lrow = tid >> 1;
    uint32_t dSub = (tid & 1) ? 4096u : 0u;
    uint32_t p0 = phys16(lrow, 0), p1 = phys16(lrow, 1);
    int so = (tid & 1) * 16;
    const __half* gA  = Ah + (size_t)(m0 + lrow) * K + so;
    const __half* gBh = Bh + (size_t)(n0 + lrow) * K + so;
    const __half* gBl = Bl + (size_t)(n0 + lrow) * K + so;

    int nkt = K / 32;
    float acc[2][8][4] = {};

#pragma unroll
    for (int p = 0; p < 2; p++) {
        uint32_t st = sb + (uint32_t)p * STG;
        int kb = p * 32;
        cpasync16(st + dSub + p0,          gA + kb);
        cpasync16(st + dSub + p1,          gA + kb + 8);
        cpasync16(st + 8192u + dSub + p0,  gBh + kb);
        cpasync16(st + 8192u + dSub + p1,  gBh + kb + 8);
        cpasync16(st + 16384u + dSub + p0, gBl + kb);
        cpasync16(st + 16384u + dSub + p1, gBl + kb + 8);
        CP_COMMIT();
    }

    int aRow = (lane & 15), aC = lane >> 4;
    int bRowBase = (lane & 7) + ((lane >> 4) << 3);
    int bC = (lane >> 3) & 1;

    for (int kt = 0; kt < nkt; ++kt) {
        if (kt + 2 < nkt) { CP_WAIT(1); } else { CP_WAIT(0); }
        __syncthreads();

        uint32_t st = sb + (uint32_t)(kt % 3) * STG;
#pragma unroll
        for (int s = 0; s < 2; s++) {
            uint32_t sA  = st + (uint32_t)s * 4096u;
            uint32_t sBh = st + 8192u + (uint32_t)s * 4096u;
            uint32_t sBl = st + 16384u + (uint32_t)s * 4096u;

            uint32_t ah[2][4];
#pragma unroll
            for (int t = 0; t < 2; t++) {
                int r = wm * 32 + t * 16 + aRow;
                ldsm4(ah[t], sA + phys16(r, aC));
            }
#pragma unroll
            for (int g = 0; g < 4; g++) {
                int r = wn * 64 + g * 16 + bRowBase;
                uint32_t bh[4], bl[4];
                ldsm4(bh, sBh + phys16(r, bC));
                ldsm4(bl, sBl + phys16(r, bC));
#pragma unroll
                for (int t = 0; t < 2; t++)
#pragma unroll
                    for (int jj = 0; jj < 2; jj++) {
                        int j = g * 2 + jj;
                        mma_fp16(acc[t][j], ah[t], &bh[2 * jj]);
                        mma_fp16(acc[t][j], ah[t], &bl[2 * jj]);
                    }
            }
        }

        if (kt + 2 < nkt) {
            uint32_t st2 = sb + (uint32_t)((kt + 2) % 3) * STG;
            int kb = (kt + 2) * 32;
            cpasync16(st2 + dSub + p0,          gA + kb);
            cpasync16(st2 + dSub + p1,          gA + kb + 8);
            cpasync16(st2 + 8192u + dSub + p0,  gBh + kb);
            cpasync16(st2 + 8192u + dSub + p1,  gBh + kb + 8);
            cpasync16(st2 + 16384u + dSub + p0, gBl + kb);
            cpasync16(st2 + 16384u + dSub + p1, gBl + kb + 8);
            CP_COMMIT();
        }
    }

#pragma unroll
    for (int t = 0; t < 2; t++) {
        int r0 = m0 + wm * 32 + t * 16 + (lane >> 2);
#pragma unroll
        for (int j = 0; j < 8; j++) {
            int col = n0 + wn * 64 + j * 8 + 2 * (lane & 3);
            *reinterpret_cast<float2*>(C + (size_t)r0 * N + col) = make_float2(acc[t][j][0], acc[t][j][1]);
            *reinterpret_cast<float2*>(C + (size_t)(r0 + 8) * N + col) = make_float2(acc[t][j][2], acc[t][j][3]);
        }
    }
}

// ---------------- per-head scan (warp-shuffle) ----------------
__global__ __launch_bounds__(256) void scan_kernel(
    const float* __restrict__ P, const float* __restrict__ bg,
    float* __restrict__ D, float* __restrict__ L)
{
    int h = blockIdx.x, tid = threadIdx.x, lane = tid & 31, wid = tid >> 5;
    float b = bg[h];
    float vals[8];
    float run = 0.f;
#pragma unroll
    for (int i = 0; i < 8; i++) {
        int t = tid * 8 + i;
        float gg = P[(size_t)t * PSTR + GOFF + h] + b;
        run += log_sigmoid_f(gg);
        vals[i] = run;
        L[h * T_SEQ + t] = log_sigmoid_f(-gg);
    }
    float x = run;
#pragma unroll
    for (int off = 1; off < 32; off <<= 1) {
        float y = __shfl_up_sync(0xffffffff, x, off);
        if (lane >= off) x += y;
    }
    __shared__ float wsum[8];
    if (lane == 31) wsum[wid] = x;
    __syncthreads();
    float woff = 0.f;
#pragma unroll
    for (int w = 0; w < 8; w++) if (w < wid) woff += wsum[w];
    float excl = x - run + woff;
#pragma unroll
    for (int i = 0; i < 8; i++) D[h * T_SEQ + tid * 8 + i] = vals[i] + excl;
}

// ---------------- fused attention (register-P, bf16x3) ----------------
#define OFF_Q  0u
#define OFF_K  16384u
#define OFF_V  32768u
#define OFF_S  49152u
#define SSTR   132
#define OFF_SC (49152u + 64u * SSTR * 4u)

__device__ __forceinline__ void pv_mma(
    uint32_t sbV, uint32_t pah[2][4], uint32_t pal[2][4],
    float (*oacc)[4], int wn, int lane)
{
#pragma unroll
    for (int u = 0; u < 2; u++) {
        int vrow = wn * 32 + u * 16 + (lane & 15);
        uint32_t vb = sbV + (uint32_t)vrow * 128u;
#pragma unroll
        for (int gg = 0; gg < 4; gg++) {
            int cch = 2 * gg + (lane >> 4);
            uint32_t vh[4], vl[4];
            ldsm4t(vh, vb + (uint32_t)((cch ^ (vrow & 7)) * 16));
            ldsm4t(vl, vb + 8192u + (uint32_t)((cch ^ (vrow & 7)) * 16));
#pragma unroll
            for (int jj = 0; jj < 2; jj++) {
                int j = gg * 2 + jj;
                mma_bf16(oacc[j], pah[u], &vh[2 * jj]);
                mma_bf16(oacc[j], pah[u], &vl[2 * jj]);
                mma_bf16(oacc[j], pal[u], &vh[2 * jj]);
            }
        }
    }
}

__global__ __launch_bounds__(256, 2) void attn_fused(
    const float* __restrict__ P, const float* __restrict__ D,
    const float* __restrict__ L, float* __restrict__ Y)
{
    extern __shared__ char smc[];
    uint32_t sb = cvta_smem(smc);
    float* smS  = reinterpret_cast<float*>(smc + OFF_S);
    float* Dq   = reinterpret_cast<float*>(smc + OFF_SC);
    float* rowE = Dq + 64;
    float* Ds   = rowE + 64;
    float* Ls   = Ds + 64;
    float* colE = Ls + 64;

    int qt = blockIdx.x, h = blockIdx.y;
    int kvh = h >> 2;
    int tid = threadIdx.x, lane = tid & 31, warp = tid >> 5;
    int wm = warp & 3, wn = warp >> 2;
    int t0 = qt * 64;
    int w0 = (t0 / WINSZ) * WINSZ;
    int wt0 = w0 / 64;
    int nk = t0 - w0 + 64;

    load_split_tile(P + (size_t)t0 * PSTR + h * DHD, sb + OFF_Q, sb + OFF_Q + 8192u, tid);
    if (tid < 64) Dq[tid] = D[h * T_SEQ + t0 + tid];
    __syncthreads();
    float dq0 = Dq[0];
    if (tid < 64) rowE[tid] = expf(Dq[tid] - dq0);

    int fr0 = wm * 16 + (lane >> 2);
    int fcb = wn * 32 + 2 * (lane & 3);

    float oacc[8][4] = {};

    for (int st = qt; st >= 0; --st) {
        int s0 = st * 64;
        bool inwin = (st >= wt0);
        if (!inwin) {
            float dend = D[h * T_SEQ + s0 + 63];
            if (dq0 - dend < -88.f) break;
        }
        __syncthreads();

        load_split_tile(P + (size_t)s0 * PSTR + KOFF + kvh * DHD, sb + OFF_K, sb + OFF_K + 8192u, tid);
        load_split_tile(P + (size_t)s0 * PSTR + VOFF + kvh * DHD, sb + OFF_V, sb + OFF_V + 8192u, tid);
        if (tid < 64) {
            float ds = D[h * T_SEQ + s0 + tid];
            float ls = L[h * T_SEQ + s0 + tid];
            Ds[tid] = ds; Ls[tid] = ls;
            colE[tid] = expf(dq0 - ds + ls);
        }
        __syncthreads();

        float sacc[4][4] = {};
        {
            int arow = wm * 16 + (lane & 15);
            int asel = lane >> 4;
            int nrow = wn * 32 + (lane & 7) + ((lane >> 4) << 3);
            int bsel = (lane >> 3) & 1;
#pragma unroll
            for (int ks = 0; ks < 4; ks++) {
                uint32_t ah[4], al[4];
                uint32_t abase = sb + OFF_Q + (uint32_t)arow * 128u;
                ldsm4(ah, abase + (uint32_t)(((2 * ks + asel) ^ (arow & 7)) * 16));
                ldsm4(al, abase + 8192u + (uint32_t)(((2 * ks + asel) ^ (arow & 7)) * 16));
                uint32_t bh[2][4], bl[2][4];
#pragma unroll
                for (int g = 0; g < 2; g++) {
                    int r = nrow + g * 16;
                    uint32_t bbase = sb + OFF_K + (uint32_t)r * 128u;
                    ldsm4(bh[g], bbase + (uint32_t)(((2 * ks + bsel) ^ (r & 7)) * 16));
                    ldsm4(bl[g], bbase + 8192u + (uint32_t)(((2 * ks + bsel) ^ (r & 7)) * 16));
                }
#pragma unroll
                for (int j = 0; j < 4; j++) {
                    const uint32_t* b2h = &bh[j >> 1][2 * (j & 1)];
                    const uint32_t* b2l = &bl[j >> 1][2 * (j & 1)];
                    mma_bf16(sacc[j], ah, b2h);
                    mma_bf16(sacc[j], ah, b2l);
                    mma_bf16(sacc[j], al, b2h);
                }
            }
        }

        uint32_t pah[2][4], pal[2][4];
        {
            int colbase = s0 - w0;
#pragma unroll
            for (int j = 0; j < 4; j++) {
                int cj = fcb + 8 * j;
#pragma unroll
                for (int half = 0; half < 2; half++) {
                    int r = fr0 + half * 8;
                    float v0 = sacc[j][2 * half], v1 = sacc[j][2 * half + 1];
                    if (inwin) {
                        float l0 = (s0 + cj     <= t0 + r) ? v0 * 0.125f : neg_inf();
                        float l1 = (s0 + cj + 1 <= t0 + r) ? v1 * 0.125f : neg_inf();
                        *reinterpret_cast<float2*>(&smS[r * SSTR + colbase + cj]) = make_float2(l0, l1);
                    }
                    float p0, p1;
                    if (st == qt) {
                        p0 = (cj     <= r) ? v0 * expf(Dq[r] - Ds[cj] + Ls[cj]) : 0.f;
                        p1 = (cj + 1 <= r) ? v1 * expf(Dq[r] - Ds[cj + 1] + Ls[cj + 1]) : 0.f;
                    } else {
                        float re = rowE[r];
                        p0 = v0 * (re * colE[cj]);
                        p1 = v1 * (re * colE[cj + 1]);
                    }
                    float h0 = __bfloat162float(__float2bfloat16_rn(p0));
                    float h1 = __bfloat162float(__float2bfloat16_rn(p1));
                    int u = j >> 1, ri = (j & 1) * 2 + half;
                    pah[u][ri] = pack2bf(h0, h1);
                    pal[u][ri] = pack2bf(p0 - h0, p1 - h1);
                }
            }
        }

        pv_mma(sb + OFF_V, pah, pal, oacc, wn, lane);
    }

    __syncthreads();
    {
        int r = tid >> 2, g = tid & 3;
        float m = neg_inf();
        for (int c = g; c < nk; c += 4) m = fmaxf(m, smS[r * SSTR + c]);
        m = fmaxf(m, __shfl_xor_sync(0xffffffff, m, 1));
        m = fmaxf(m, __shfl_xor_sync(0xffffffff, m, 2));
        float sum = 0.f;
        for (int c = g; c < nk; c += 4) {
            float e = expf(smS[r * SSTR + c] - m);
            smS[r * SSTR + c] = e;
            sum += e;
        }
        sum += __shfl_xor_sync(0xffffffff, sum, 1);
        sum += __shfl_xor_sync(0xffffffff, sum, 2);
        float inv = 1.f / sum;
        for (int c = g; c < nk; c += 4) smS[r * SSTR + c] *= inv;
    }

    for (int kh = 0; kh < (nk >> 6); kh++) {
        __syncthreads();
        load_split_tile(P + (size_t)(w0 + kh * 64) * PSTR + VOFF + kvh * DHD, sb + OFF_V, sb + OFF_V + 8192u, tid);
        __syncthreads();
        uint32_t pah[2][4], pal[2][4];
#pragma unroll
        for (int u = 0; u < 2; u++) {
            int bc = kh * 64 + wn * 32 + u * 16 + 2 * (lane & 3);
            float2 f0 = *reinterpret_cast<const float2*>(&smS[fr0 * SSTR + bc]);
            float2 f1 = *reinterpret_cast<const float2*>(&smS[(fr0 + 8) * SSTR + bc]);
            float2 f2 = *reinterpret_cast<const float2*>(&smS[fr0 * SSTR + bc + 8]);
            float2 f3 = *reinterpret_cast<const float2*>(&smS[(fr0 + 8) * SSTR + bc + 8]);
            float h, h2;
            h = __bfloat162float(__float2bfloat16_rn(f0.x));
            h2 = __bfloat162float(__float2bfloat16_rn(f0.y));
            pah[u][0] = pack2bf(h, h2); pal[u][0] = pack2bf(f0.x - h, f0.y - h2);
            h = __bfloat162float(__float2bfloat16_rn(f1.x));
            h2 = __bfloat162float(__float2bfloat16_rn(f1.y));
            pah[u][1] = pack2bf(h, h2); pal[u][1] = pack2bf(f1.x - h, f1.y - h2);
            h = __bfloat162float(__float2bfloat16_rn(f2.x));
            h2 = __bfloat162float(__float2bfloat16_rn(f2.y));
            pah[u][2] = pack2bf(h, h2); pal[u][2] = pack2bf(f2.x - h, f2.y - h2);
            h = __bfloat162float(__float2bfloat16_rn(f3.x));
            h2 = __bfloat162float(__float2bfloat16_rn(f3.y));
            pah[u][3] = pack2bf(h, h2); pal[u][3] = pack2bf(f3.x - h, f3.y - h2);
        }
        pv_mma(sb + OFF_V, pah, pal, oacc, wn, lane);
    }

    __syncthreads();
    float* redb = reinterpret_cast<float*>(smc + OFF_K);
    if (wn == 1) {
        int base = (wm * 32 + lane) * 32;
#pragma unroll
        for (int j = 0; j < 8; j++)
#pragma unroll
            for (int k = 0; k < 4; k++) redb[base + j * 4 + k] = oacc[j][k];
    }
    __syncthreads();
    if (wn == 0) {
        int base = (wm * 32 + lane) * 32;
#pragma unroll
        for (int j = 0; j < 8; j++) {
            float o0 = oacc[j][0] + redb[base + j * 4 + 0];
            float o1 = oacc[j][1] + redb[base + j * 4 + 1];
            float o2 = oacc[j][2] + redb[base + j * 4 + 2];
            float o3 = oacc[j][3] + redb[base + j * 4 + 3];
            int col = h * DHD + j * 8 + 2 * (lane & 3);
            *reinterpret_cast<float2*>(Y + (size_t)(t0 + fr0) * C_DIM + col) = make_float2(o0, o1);
            *reinterpret_cast<float2*>(Y + (size_t)(t0 + fr0 + 8) * C_DIM + col) = make_float2(o2, o3);
        }
    }
}

// ---------------- launch ----------------
extern "C" void kernel_launch(void* const* d_in, const int* in_sizes, int n_in,
                              void* d_out, int out_size)
{
    (void)in_sizes; (void)n_in; (void)out_size;
    const float* x    = (const float*)d_in[0];
    const float* Wq   = (const float*)d_in[1];
    const float* Wk   = (const float*)d_in[2];
    const float* Wv   = (const float*)d_in[3];
    const float* Wc   = (const float*)d_in[4];
    const float* Wg   = (const float*)d_in[5];
    const float* bg   = (const float*)d_in[6];
    const float* rmsw = (const float*)d_in[7];
    float* out = (float*)d_out;

    float *P, *D, *L, *Y;
    __half *Xh, *Xl, *Yh, *Wph, *Wpl, *Wch, *Wcl;
    cudaGetSymbolAddress((void**)&P, g_P);
    cudaGetSymbolAddress((void**)&D, g_D);
    cudaGetSymbolAddress((void**)&L, g_L);
    cudaGetSymbolAddress((void**)&Y, g_Y);
    cudaGetSymbolAddress((void**)&Xh, g_Xh);
    cudaGetSymbolAddress((void**)&Xl, g_Xl);
    cudaGetSymbolAddress((void**)&Yh, g_Yh);
    cudaGetSymbolAddress((void**)&Wph, g_Wp_h);
    cudaGetSymbolAddress((void**)&Wpl, g_Wp_l);
    cudaGetSymbolAddress((void**)&Wch, g_Wc_h);
    cudaGetSymbolAddress((void**)&Wcl, g_Wc_l);

    transpose_split_all<<<dim3(32, 32, 5), 256>>>(Wq, Wk, Wv, Wc, Wg, rmsw, Wph, Wpl, Wch, Wcl);
    split_act<<<T_SEQ, 256>>>(x, Xh, Xl);

    size_t smemP = 3 * 32768;
    cudaFuncSetAttribute(gemm_proj_f16, cudaFuncAttributeMaxDynamicSharedMemorySize, (int)smemP);
    gemm_proj_f16<<<dim3(PSTR / 128, T_SEQ / 128), 256, smemP>>>(Xh, Xl, Wph, Wpl, P, T_SEQ, PSTR, C_DIM);

    scan_kernel<<<NH, 256>>>(P, bg, D, L);

    size_t smemA = OFF_SC + 6 * 64 * sizeof(float);
    cudaFuncSetAttribute(attn_fused, cudaFuncAttributeMaxDynamicSharedMemorySize, (int)smemA);
    attn_fused<<<dim3(T_SEQ / 64, NH), 256, smemA>>>(P, D, L, Y);

    norm_to_fp16<<<T_SEQ, 256>>>(Y, Yh);

    size_t smemO = 3 * 24576;
    cudaFuncSetAttribute(gemm_out_f16, cudaFuncAttributeMaxDynamicSharedMemorySize, (int)smemO);
    gemm_out_f16<<<dim3(C_DIM / 128, T_SEQ / 128), 256, smemO>>>(Yh, Wch, Wcl, out, T_SEQ, C_DIM, C_DIM);
}

// round 13
// speedup vs baseline: 1.2023x; 1.2023x over previous
#include <cuda_runtime.h>
#include <cuda_bf16.h>
#include <cuda_fp16.h>
#include <math.h>
#include <stdint.h>

#define T_SEQ 2048
#define C_DIM 1024
#define NH    16
#define NKV   4
#define DHD   64
#define WINSZ 128
#define PSTR  1664          /* Q(1024) | K(256) | V(256) | gate(16 + 112 pad) */
#define KOFF  1024
#define VOFF  1280
#define GOFF  1536
#define GATE_BLK 12

// ---------------- scratch ----------------
__device__ float g_P[T_SEQ * PSTR];
__device__ float g_D[NH * T_SEQ];
__device__ float g_L[NH * T_SEQ];
__device__ float g_Y[T_SEQ * C_DIM];
__device__ __half g_Xh[T_SEQ * C_DIM];
__device__ __half g_Xl[T_SEQ * C_DIM];
__device__ __half g_Yh[T_SEQ * C_DIM];
__device__ __half g_Wp_h[PSTR * C_DIM];
__device__ __half g_Wp_l[PSTR * C_DIM];
__device__ __half g_Wc_h[C_DIM * C_DIM];
__device__ __half g_Wc_l[C_DIM * C_DIM];

__device__ __forceinline__ float neg_inf() { return __int_as_float(0xff800000); }
__device__ __forceinline__ float log_sigmoid_f(float x) {
    return fminf(x, 0.f) - log1pf(expf(-fabsf(x)));
}
__device__ __forceinline__ uint32_t cvta_smem(const void* p) {
    uint32_t a;
    asm("{ .reg .u64 t; cvta.to.shared.u64 t, %1; cvt.u32.u64 %0, t; }" : "=r"(a) : "l"(p));
    return a;
}
__device__ __forceinline__ uint32_t pack2bf(float a, float b) {
    __nv_bfloat162 t = __floats2bfloat162_rn(a, b);
    return *reinterpret_cast<uint32_t*>(&t);
}
__device__ __forceinline__ uint32_t pack2h(float a, float b) {
    __half2 t = __floats2half2_rn(a, b);
    return *reinterpret_cast<uint32_t*>(&t);
}
__device__ __forceinline__ void ldsm4(uint32_t* r, uint32_t addr) {
    asm volatile("ldmatrix.sync.aligned.m8n8.x4.shared.b16 {%0,%1,%2,%3}, [%4];"
                 : "=r"(r[0]), "=r"(r[1]), "=r"(r[2]), "=r"(r[3]) : "r"(addr));
}
__device__ __forceinline__ void ldsm4t(uint32_t* r, uint32_t addr) {
    asm volatile("ldmatrix.sync.aligned.m8n8.x4.trans.shared.b16 {%0,%1,%2,%3}, [%4];"
                 : "=r"(r[0]), "=r"(r[1]), "=r"(r[2]), "=r"(r[3]) : "r"(addr));
}
__device__ __forceinline__ void mma_bf16(float* c, const uint32_t* a, const uint32_t* b) {
    asm volatile(
        "mma.sync.aligned.m16n8k16.row.col.f32.bf16.bf16.f32 "
        "{%0,%1,%2,%3}, {%4,%5,%6,%7}, {%8,%9}, {%0,%1,%2,%3};"
        : "+f"(c[0]), "+f"(c[1]), "+f"(c[2]), "+f"(c[3])
        : "r"(a[0]), "r"(a[1]), "r"(a[2]), "r"(a[3]), "r"(b[0]), "r"(b[1]));
}
__device__ __forceinline__ void mma_fp16(float* c, const uint32_t* a, const uint32_t* b) {
    asm volatile(
        "mma.sync.aligned.m16n8k16.row.col.f32.f16.f16.f32 "
        "{%0,%1,%2,%3}, {%4,%5,%6,%7}, {%8,%9}, {%0,%1,%2,%3};"
        : "+f"(c[0]), "+f"(c[1]), "+f"(c[2]), "+f"(c[3])
        : "r"(a[0]), "r"(a[1]), "r"(a[2]), "r"(a[3]), "r"(b[0]), "r"(b[1]));
}
__device__ __forceinline__ void sts8(uint32_t addr, uint32_t a, uint32_t b) {
    asm volatile("st.shared.v2.b32 [%0], {%1,%2};" :: "r"(addr), "r"(a), "r"(b) : "memory");
}
__device__ __forceinline__ void cpasync16(uint32_t dst, const void* src) {
    asm volatile("cp.async.cg.shared.global [%0], [%1], 16;" :: "r"(dst), "l"(src) : "memory");
}
#define CP_COMMIT() asm volatile("cp.async.commit_group;" ::: "memory")
#define CP_WAIT(n)  asm volatile("cp.async.wait_group %0;" :: "n"(n) : "memory")

// swizzled offset within a 128x16 (16-bit elem) tile (4KB)
__device__ __forceinline__ uint32_t phys16(int row, int c) {
    return (uint32_t)((row >> 2) * 128 + (((((row & 3) * 2) + c) ^ ((row >> 2) & 1)) * 16));
}

// load 64x64 fp32 tile -> split bf16 hi/lo into swizzled smem (attn kernel)
__device__ __forceinline__ void load_split_tile(
    const float* __restrict__ gsrc, uint32_t smH, uint32_t smL, int tid)
{
#pragma unroll
    for (int i = 0; i < 4; i++) {
        int f = tid + i * 256;
        int r = f >> 4, q4 = f & 15;
        float4 v = *reinterpret_cast<const float4*>(gsrc + (size_t)r * PSTR + q4 * 4);
        float hx = __bfloat162float(__float2bfloat16_rn(v.x));
        float hy = __bfloat162float(__float2bfloat16_rn(v.y));
        float hz = __bfloat162float(__float2bfloat16_rn(v.z));
        float hw = __bfloat162float(__float2bfloat16_rn(v.w));
        uint32_t phys = (uint32_t)r * 128u + (uint32_t)(((q4 >> 1) ^ (r & 7)) * 16) + (uint32_t)((q4 & 1) * 8);
        sts8(smH + phys, pack2bf(hx, hy), pack2bf(hz, hw));
        sts8(smL + phys, pack2bf(v.x - hx, v.y - hy), pack2bf(v.z - hz, v.w - hw));
    }
}

// ---------------- merged prepass: weight transpose + fp16 split + x split ----------------
// z=0..2: Wq/Wk/Wv -> Wp; z=3: Wc*rmsw -> Wc; z=4: Wg -> Wp rows GOFF..; z=5: x -> Xh/Xl
__global__ __launch_bounds__(256) void prepass_all(
    const float* __restrict__ Wq, const float* __restrict__ Wk,
    const float* __restrict__ Wv, const float* __restrict__ Wc,
    const float* __restrict__ Wg, const float* __restrict__ rmsw,
    const float* __restrict__ x,
    __half* __restrict__ Wph, __half* __restrict__ Wpl,
    __half* __restrict__ Wch, __half* __restrict__ Wcl,
    __half* __restrict__ Xh, __half* __restrict__ Xl)
{
    int z = blockIdx.z;
    if (z == 5) {
        // x split: 1024 (x,y) blocks, each handles 2 rows of 1024 floats
        int blk = blockIdx.y * 32 + blockIdx.x;
        int tid = threadIdx.x;
#pragma unroll
        for (int rr = 0; rr < 2; rr++) {
            int t = blk * 2 + rr;
            float4 v = *reinterpret_cast<const float4*>(x + (size_t)t * C_DIM + tid * 4);
            float h0 = __half2float(__float2half_rn(v.x));
            float h1 = __half2float(__float2half_rn(v.y));
            float h2 = __half2float(__float2half_rn(v.z));
            float h3 = __half2float(__float2half_rn(v.w));
            uint2 hh = make_uint2(pack2h(h0, h1), pack2h(h2, h3));
            uint2 ll = make_uint2(pack2h(v.x - h0, v.y - h1), pack2h(v.z - h2, v.w - h3));
            *reinterpret_cast<uint2*>(Xh + (size_t)t * C_DIM + tid * 4) = hh;
            *reinterpret_cast<uint2*>(Xl + (size_t)t * C_DIM + tid * 4) = ll;
        }
        return;
    }
    const float* W; __half *Th, *Tl; int N, rowOff = 0; bool useScale = false;
    if (z == 0)      { W = Wq; Th = Wph; Tl = Wpl; N = 1024; }
    else if (z == 1) { W = Wk; Th = Wph; Tl = Wpl; N = 256; rowOff = KOFF; }
    else if (z == 2) { W = Wv; Th = Wph; Tl = Wpl; N = 256; rowOff = VOFF; }
    else if (z == 3) { W = Wc; Th = Wch; Tl = Wcl; N = 1024; useScale = true; }
    else             { W = Wg; Th = Wph; Tl = Wpl; N = 16;  rowOff = GOFF; }
    int n0 = blockIdx.x * 32;
    if (n0 >= N) return;
    int k0 = blockIdx.y * 32;

    __shared__ float s[32][33];
    int tx = threadIdx.x & 31, ty = threadIdx.x >> 5;
#pragma unroll
    for (int i = 0; i < 4; i++) {
        int r = ty + i * 8;
        if (n0 + tx < N) {
            float v = W[(size_t)(k0 + r) * N + n0 + tx];
            if (useScale) v *= rmsw[k0 + r];
            s[r][tx] = v;
        }
    }
    __syncthreads();
#pragma unroll
    for (int i = 0; i < 4; i++) {
        int r = ty + i * 8;
        if (n0 + r < N) {
            float v = s[tx][r];
            __half h = __float2half_rn(v);
            Th[(size_t)(rowOff + n0 + r) * C_DIM + k0 + tx] = h;
            Tl[(size_t)(rowOff + n0 + r) * C_DIM + k0 + tx] = __float2half_rn(v - __half2float(h));
        }
    }
}

// ---------------- Y -> fp16 with fused RMSNorm row scale ----------------
__global__ __launch_bounds__(256) void norm_to_fp16(
    const float* __restrict__ X, __half* __restrict__ Ah)
{
    int t = blockIdx.x, tid = threadIdx.x;
    float4 v = *reinterpret_cast<const float4*>(X + (size_t)t * C_DIM + tid * 4);
    float ss = v.x * v.x + v.y * v.y + v.z * v.z + v.w * v.w;
#pragma unroll
    for (int off = 16; off; off >>= 1) ss += __shfl_xor_sync(0xffffffff, ss, off);
    __shared__ float red[8];
    if ((tid & 31) == 0) red[tid >> 5] = ss;
    __syncthreads();
    float s = red[0];
#pragma unroll
    for (int i = 1; i < 8; i++) s += red[i];
    float scale = rsqrtf(s * (1.f / (float)C_DIM) + 1e-5f);
    uint2 hh = make_uint2(pack2h(v.x * scale, v.y * scale), pack2h(v.z * scale, v.w * scale));
    *reinterpret_cast<uint2*>(Ah + (size_t)t * C_DIM + tid * 4) = hh;
}

// ---------------- proj GEMM: fp16 A x (Bh+Bl) 2-term; gate block adds al*bh ----------------
// stage 16KB: Ah@0 | Bh@4K | Bl@8K | Al@12K (Al only filled/used by gate CTAs)
__global__ __launch_bounds__(256, 2) void gemm_proj_f16(
    const __half* __restrict__ Ah, const __half* __restrict__ Al,
    const __half* __restrict__ Bh, const __half* __restrict__ Bl,
    float* __restrict__ C, int M, int N, int K)
{
    extern __shared__ char smc[];
    uint32_t sb = cvta_smem(smc);
    const uint32_t STG = 16384u;

    int tid = threadIdx.x, lane = tid & 31, warp = tid >> 5;
    int wm = warp & 3, wn = warp >> 2;
    int m0 = blockIdx.y * 128, n0 = blockIdx.x * 128;
    bool prec = ((int)blockIdx.x == GATE_BLK);

    int lrow = tid >> 1, lc = tid & 1;
    uint32_t ldst = phys16(lrow, lc);
    const __half* gA  = Ah + (size_t)(m0 + lrow) * K + lc * 8;
    const __half* gAl = Al + (size_t)(m0 + lrow) * K + lc * 8;
    const __half* gBh = Bh + (size_t)(n0 + lrow) * K + lc * 8;
    const __half* gBl = Bl + (size_t)(n0 + lrow) * K + lc * 8;

    int nkt = K / 16;
    float acc[2][8][4] = {};

#pragma unroll
    for (int p = 0; p < 2; p++) {
        uint32_t st = sb + (uint32_t)p * STG;
        cpasync16(st + ldst,          gA + p * 16);
        cpasync16(st + 4096u + ldst,  gBh + p * 16);
        cpasync16(st + 8192u + ldst,  gBl + p * 16);
        if (prec) cpasync16(st + 12288u + ldst, gAl + p * 16);
        CP_COMMIT();
    }

    int aRow = (lane & 15), aC = lane >> 4;
    int bRowBase = (lane & 7) + ((lane >> 4) << 3);
    int bC = (lane >> 3) & 1;

    for (int kt = 0; kt < nkt; ++kt) {
        if (kt + 2 < nkt) { CP_WAIT(1); } else { CP_WAIT(0); }
        __syncthreads();

        uint32_t st = sb + (uint32_t)(kt % 3) * STG;
        uint32_t ah[2][4], al[2][4];
#pragma unroll
        for (int t = 0; t < 2; t++) {
            int r = wm * 32 + t * 16 + aRow;
            ldsm4(ah[t], st + phys16(r, aC));
        }
        if (prec) {
#pragma unroll
            for (int t = 0; t < 2; t++) {
                int r = wm * 32 + t * 16 + aRow;
                ldsm4(al[t], st + 12288u + phys16(r, aC));
            }
        }
#pragma unroll
        for (int g = 0; g < 4; g++) {
            int r = wn * 64 + g * 16 + bRowBase;
            uint32_t bh[4], bl[4];
            ldsm4(bh, st + 4096u + phys16(r, bC));
            ldsm4(bl, st + 8192u + phys16(r, bC));
#pragma unroll
            for (int t = 0; t < 2; t++)
#pragma unroll
                for (int jj = 0; jj < 2; jj++) {
                    int j = g * 2 + jj;
                    mma_fp16(acc[t][j], ah[t], &bh[2 * jj]);
                    mma_fp16(acc[t][j], ah[t], &bl[2 * jj]);
                }
            if (prec) {
#pragma unroll
                for (int t = 0; t < 2; t++)
#pragma unroll
                    for (int jj = 0; jj < 2; jj++)
                        mma_fp16(acc[t][g * 2 + jj], al[t], &bh[2 * jj]);
            }
        }

        if (kt + 2 < nkt) {
            uint32_t st2 = sb + (uint32_t)((kt + 2) % 3) * STG;
            int ko = (kt + 2) * 16;
            cpasync16(st2 + ldst,          gA + ko);
            cpasync16(st2 + 4096u + ldst,  gBh + ko);
            cpasync16(st2 + 8192u + ldst,  gBl + ko);
            if (prec) cpasync16(st2 + 12288u + ldst, gAl + ko);
            CP_COMMIT();
        }
    }

    // RoPE epilogue (Q,K head columns only)
    if ((n0 + wn * 64) < 1280) {
#pragma unroll
        for (int j = 0; j < 4; j++) {
#pragma unroll
            for (int e = 0; e < 2; e++) {
                int d = j * 8 + 2 * (lane & 3) + e;
                float invf = expf(-(float)(2 * d) * (9.210340371976184f / 64.f));
#pragma unroll
                for (int mt = 0; mt < 2; mt++) {
#pragma unroll
                    for (int rh = 0; rh < 2; rh++) {
                        int trow = m0 + wm * 32 + mt * 16 + (lane >> 2) + rh * 8;
                        float sn, cs;
                        sincosf((float)trow * invf, &sn, &cs);
                        int k = 2 * rh + e;
                        float a = acc[mt][j][k], b = acc[mt][j + 4][k];
                        acc[mt][j][k]     = a * cs - b * sn;
                        acc[mt][j + 4][k] = b * cs + a * sn;
                    }
                }
            }
        }
    }

#pragma unroll
    for (int t = 0; t < 2; t++) {
        int r0 = m0 + wm * 32 + t * 16 + (lane >> 2);
#pragma unroll
        for (int j = 0; j < 8; j++) {
            int col = n0 + wn * 64 + j * 8 + 2 * (lane & 3);
            *reinterpret_cast<float2*>(C + (size_t)r0 * N + col) = make_float2(acc[t][j][0], acc[t][j][1]);
            *reinterpret_cast<float2*>(C + (size_t)(r0 + 8) * N + col) = make_float2(acc[t][j][2], acc[t][j][3]);
        }
    }
}

// ---------------- out GEMM: fp16 A (single) x (Bh+Bl), 2-term ----------------
__global__ __launch_bounds__(256, 2) void gemm_out_f16(
    const __half* __restrict__ Ah, const __half* __restrict__ Bh,
    const __half* __restrict__ Bl, float* __restrict__ C,
    int M, int N, int K)
{
    extern __shared__ char smc[];
    uint32_t sb = cvta_smem(smc);
    const uint32_t STG = 12288u;

    int tid = threadIdx.x, lane = tid & 31, warp = tid >> 5;
    int wm = warp & 3, wn = warp >> 2;
    int m0 = blockIdx.y * 128, n0 = blockIdx.x * 128;

    int lrow = tid >> 1, lc = tid & 1;
    uint32_t ldst = phys16(lrow, lc);
    const __half* gA = Ah + (size_t)(m0 + lrow) * K + lc * 8;
    const __half* gBh = Bh + (size_t)(n0 + lrow) * K + lc * 8;
    const __half* gBl = Bl + (size_t)(n0 + lrow) * K + lc * 8;

    int nkt = K / 16;
    float acc[2][8][4] = {};

#pragma unroll
    for (int p = 0; p < 2; p++) {
        uint32_t st = sb + (uint32_t)p * STG;
        cpasync16(st + ldst,          gA + p * 16);
        cpasync16(st + 4096u + ldst,  gBh + p * 16);
        cpasync16(st + 8192u + ldst,  gBl + p * 16);
        CP_COMMIT();
    }

    int aRow = (lane & 15), aC = lane >> 4;
    int bRowBase = (lane & 7) + ((lane >> 4) << 3);
    int bC = (lane >> 3) & 1;

    for (int kt = 0; kt < nkt; ++kt) {
        if (kt + 2 < nkt) { CP_WAIT(1); } else { CP_WAIT(0); }
        __syncthreads();

        uint32_t st = sb + (uint32_t)(kt % 3) * STG;
        uint32_t ah[2][4];
#pragma unroll
        for (int t = 0; t < 2; t++) {
            int r = wm * 32 + t * 16 + aRow;
            ldsm4(ah[t], st + phys16(r, aC));
        }
#pragma unroll
        for (int g = 0; g < 4; g++) {
            int r = wn * 64 + g * 16 + bRowBase;
            uint32_t bh[4], bl[4];
            ldsm4(bh, st + 4096u + phys16(r, bC));
            ldsm4(bl, st + 8192u + phys16(r, bC));
#pragma unroll
            for (int t = 0; t < 2; t++)
#pragma unroll
                for (int jj = 0; jj < 2; jj++) {
                    int j = g * 2 + jj;
                    mma_fp16(acc[t][j], ah[t], &bh[2 * jj]);
                    mma_fp16(acc[t][j], ah[t], &bl[2 * jj]);
                }
        }

        if (kt + 2 < nkt) {
            uint32_t st2 = sb + (uint32_t)((kt + 2) % 3) * STG;
            int ko = (kt + 2) * 16;
            cpasync16(st2 + ldst,          gA + ko);
            cpasync16(st2 + 4096u + ldst,  gBh + ko);
            cpasync16(st2 + 8192u + ldst,  gBl + ko);
            CP_COMMIT();
        }
    }

#pragma unroll
    for (int t = 0; t < 2; t++) {
        int r0 = m0 + wm * 32 + t * 16 + (lane >> 2);
#pragma unroll
        for (int j = 0; j < 8; j++) {
            int col = n0 + wn * 64 + j * 8 + 2 * (lane & 3);
            *reinterpret_cast<float2*>(C + (size_t)r0 * N + col) = make_float2(acc[t][j][0], acc[t][j][1]);
            *reinterpret_cast<float2*>(C + (size_t)(r0 + 8) * N + col) = make_float2(acc[t][j][2], acc[t][j][3]);
        }
    }
}

// ---------------- per-head scan (warp-shuffle) ----------------
__global__ __launch_bounds__(256) void scan_kernel(
    const float* __restrict__ P, const float* __restrict__ bg,
    float* __restrict__ D, float* __restrict__ L)
{
    int h = blockIdx.x, tid = threadIdx.x, lane = tid & 31, wid = tid >> 5;
    float b = bg[h];
    float vals[8];
    float run = 0.f;
#pragma unroll
    for (int i = 0; i < 8; i++) {
        int t = tid * 8 + i;
        float gg = P[(size_t)t * PSTR + GOFF + h] + b;
        run += log_sigmoid_f(gg);
        vals[i] = run;
        L[h * T_SEQ + t] = log_sigmoid_f(-gg);
    }
    float x = run;
#pragma unroll
    for (int off = 1; off < 32; off <<= 1) {
        float y = __shfl_up_sync(0xffffffff, x, off);
        if (lane >= off) x += y;
    }
    __shared__ float wsum[8];
    if (lane == 31) wsum[wid] = x;
    __syncthreads();
    float woff = 0.f;
#pragma unroll
    for (int w = 0; w < 8; w++) if (w < wid) woff += wsum[w];
    float excl = x - run + woff;
#pragma unroll
    for (int i = 0; i < 8; i++) D[h * T_SEQ + tid * 8 + i] = vals[i] + excl;
}

// ---------------- fused attention (register-P, bf16x3) ----------------
#define OFF_Q  0u
#define OFF_K  16384u
#define OFF_V  32768u
#define OFF_S  49152u
#define SSTR   132
#define OFF_SC (49152u + 64u * SSTR * 4u)

__device__ __forceinline__ void pv_mma(
    uint32_t sbV, uint32_t pah[2][4], uint32_t pal[2][4],
    float (*oacc)[4], int wn, int lane)
{
#pragma unroll
    for (int u = 0; u < 2; u++) {
        int vrow = wn * 32 + u * 16 + (lane & 15);
        uint32_t vb = sbV + (uint32_t)vrow * 128u;
#pragma unroll
        for (int gg = 0; gg < 4; gg++) {
            int cch = 2 * gg + (lane >> 4);
            uint32_t vh[4], vl[4];
            ldsm4t(vh, vb + (uint32_t)((cch ^ (vrow & 7)) * 16));
            ldsm4t(vl, vb + 8192u + (uint32_t)((cch ^ (vrow & 7)) * 16));
#pragma unroll
            for (int jj = 0; jj < 2; jj++) {
                int j = gg * 2 + jj;
                mma_bf16(oacc[j], pah[u], &vh[2 * jj]);
                mma_bf16(oacc[j], pah[u], &vl[2 * jj]);
                mma_bf16(oacc[j], pal[u], &vh[2 * jj]);
            }
        }
    }
}

__global__ __launch_bounds__(256, 2) void attn_fused(
    const float* __restrict__ P, const float* __restrict__ D,
    const float* __restrict__ L, float* __restrict__ Y)
{
    extern __shared__ char smc[];
    uint32_t sb = cvta_smem(smc);
    float* smS  = reinterpret_cast<float*>(smc + OFF_S);
    float* Dq   = reinterpret_cast<float*>(smc + OFF_SC);
    float* rowE = Dq + 64;
    float* Ds   = rowE + 64;
    float* Ls   = Ds + 64;
    float* colE = Ls + 64;

    int qt = blockIdx.x, h = blockIdx.y;
    int kvh = h >> 2;
    int tid = threadIdx.x, lane = tid & 31, warp = tid >> 5;
    int wm = warp & 3, wn = warp >> 2;
    int t0 = qt * 64;
    int w0 = (t0 / WINSZ) * WINSZ;
    int wt0 = w0 / 64;
    int nk = t0 - w0 + 64;

    load_split_tile(P + (size_t)t0 * PSTR + h * DHD, sb + OFF_Q, sb + OFF_Q + 8192u, tid);
    if (tid < 64) Dq[tid] = D[h * T_SEQ + t0 + tid];
    __syncthreads();
    float dq0 = Dq[0];
    if (tid < 64) rowE[tid] = expf(Dq[tid] - dq0);

    int fr0 = wm * 16 + (lane >> 2);
    int fcb = wn * 32 + 2 * (lane & 3);

    float oacc[8][4] = {};

    for (int st = qt; st >= 0; --st) {
        int s0 = st * 64;
        bool inwin = (st >= wt0);
        if (!inwin) {
            float dend = D[h * T_SEQ + s0 + 63];
            if (dq0 - dend < -88.f) break;
        }
        __syncthreads();

        load_split_tile(P + (size_t)s0 * PSTR + KOFF + kvh * DHD, sb + OFF_K, sb + OFF_K + 8192u, tid);
        load_split_tile(P + (size_t)s0 * PSTR + VOFF + kvh * DHD, sb + OFF_V, sb + OFF_V + 8192u, tid);
        if (tid < 64) {
            float ds = D[h * T_SEQ + s0 + tid];
            float ls = L[h * T_SEQ + s0 + tid];
            Ds[tid] = ds; Ls[tid] = ls;
            colE[tid] = expf(dq0 - ds + ls);
        }
        __syncthreads();

        float sacc[4][4] = {};
        {
            int arow = wm * 16 + (lane & 15);
            int asel = lane >> 4;
            int nrow = wn * 32 + (lane & 7) + ((lane >> 4) << 3);
            int bsel = (lane >> 3) & 1;
#pragma unroll
            for (int ks = 0; ks < 4; ks++) {
                uint32_t ah[4], al[4];
                uint32_t abase = sb + OFF_Q + (uint32_t)arow * 128u;
                ldsm4(ah, abase + (uint32_t)(((2 * ks + asel) ^ (arow & 7)) * 16));
                ldsm4(al, abase + 8192u + (uint32_t)(((2 * ks + asel) ^ (arow & 7)) * 16));
                uint32_t bh[2][4], bl[2][4];
#pragma unroll
                for (int g = 0; g < 2; g++) {
                    int r = nrow + g * 16;
                    uint32_t bbase = sb + OFF_K + (uint32_t)r * 128u;
                    ldsm4(bh[g], bbase + (uint32_t)(((2 * ks + bsel) ^ (r & 7)) * 16));
                    ldsm4(bl[g], bbase + 8192u + (uint32_t)(((2 * ks + bsel) ^ (r & 7)) * 16));
                }
#pragma unroll
                for (int j = 0; j < 4; j++) {
                    const uint32_t* b2h = &bh[j >> 1][2 * (j & 1)];
                    const uint32_t* b2l = &bl[j >> 1][2 * (j & 1)];
                    mma_bf16(sacc[j], ah, b2h);
                    mma_bf16(sacc[j], ah, b2l);
                    mma_bf16(sacc[j], al, b2h);
                }
            }
        }

        uint32_t pah[2][4], pal[2][4];
        {
            int colbase = s0 - w0;
#pragma unroll
            for (int j = 0; j < 4; j++) {
                int cj = fcb + 8 * j;
#pragma unroll
                for (int half = 0; half < 2; half++) {
                    int r = fr0 + half * 8;
                    float v0 = sacc[j][2 * half], v1 = sacc[j][2 * half + 1];
                    if (inwin) {
                        float l0 = (s0 + cj     <= t0 + r) ? v0 * 0.125f : neg_inf();
                        float l1 = (s0 + cj + 1 <= t0 + r) ? v1 * 0.125f : neg_inf();
                        *reinterpret_cast<float2*>(&smS[r * SSTR + colbase + cj]) = make_float2(l0, l1);
                    }
                    float p0, p1;
                    if (st == qt) {
                        p0 = (cj     <= r) ? v0 * expf(Dq[r] - Ds[cj] + Ls[cj]) : 0.f;
                        p1 = (cj + 1 <= r) ? v1 * expf(Dq[r] - Ds[cj + 1] + Ls[cj + 1]) : 0.f;
                    } else {
                        float re = rowE[r];
                        p0 = v0 * (re * colE[cj]);
                        p1 = v1 * (re * colE[cj + 1]);
                    }
                    float h0 = __bfloat162float(__float2bfloat16_rn(p0));
                    float h1 = __bfloat162float(__float2bfloat16_rn(p1));
                    int u = j >> 1, ri = (j & 1) * 2 + half;
                    pah[u][ri] = pack2bf(h0, h1);
                    pal[u][ri] = pack2bf(p0 - h0, p1 - h1);
                }
            }
        }

        pv_mma(sb + OFF_V, pah, pal, oacc, wn, lane);
    }

    __syncthreads();
    {
        int r = tid >> 2, g = tid & 3;
        float m = neg_inf();
        for (int c = g; c < nk; c += 4) m = fmaxf(m, smS[r * SSTR + c]);
        m = fmaxf(m, __shfl_xor_sync(0xffffffff, m, 1));
        m = fmaxf(m, __shfl_xor_sync(0xffffffff, m, 2));
        float sum = 0.f;
        for (int c = g; c < nk; c += 4) {
            float e = expf(smS[r * SSTR + c] - m);
            smS[r * SSTR + c] = e;
            sum += e;
        }
        sum += __shfl_xor_sync(0xffffffff, sum, 1);
        sum += __shfl_xor_sync(0xffffffff, sum, 2);
        float inv = 1.f / sum;
        for (int c = g; c < nk; c += 4) smS[r * SSTR + c] *= inv;
    }

    for (int kh = 0; kh < (nk >> 6); kh++) {
        __syncthreads();
        load_split_tile(P + (size_t)(w0 + kh * 64) * PSTR + VOFF + kvh * DHD, sb + OFF_V, sb + OFF_V + 8192u, tid);
        __syncthreads();
        uint32_t pah[2][4], pal[2][4];
#pragma unroll
        for (int u = 0; u < 2; u++) {
            int bc = kh * 64 + wn * 32 + u * 16 + 2 * (lane & 3);
            float2 f0 = *reinterpret_cast<const float2*>(&smS[fr0 * SSTR + bc]);
            float2 f1 = *reinterpret_cast<const float2*>(&smS[(fr0 + 8) * SSTR + bc]);
            float2 f2 = *reinterpret_cast<const float2*>(&smS[fr0 * SSTR + bc + 8]);
            float2 f3 = *reinterpret_cast<const float2*>(&smS[(fr0 + 8) * SSTR + bc + 8]);
            float h, h2;
            h = __bfloat162float(__float2bfloat16_rn(f0.x));
            h2 = __bfloat162float(__float2bfloat16_rn(f0.y));
            pah[u][0] = pack2bf(h, h2); pal[u][0] = pack2bf(f0.x - h, f0.y - h2);
            h = __bfloat162float(__float2bfloat16_rn(f1.x));
            h2 = __bfloat162float(__float2bfloat16_rn(f1.y));
            pah[u][1] = pack2bf(h, h2); pal[u][1] = pack2bf(f1.x - h, f1.y - h2);
            h = __bfloat162float(__float2bfloat16_rn(f2.x));
            h2 = __bfloat162float(__float2bfloat16_rn(f2.y));
            pah[u][2] = pack2bf(h, h2); pal[u][2] = pack2bf(f2.x - h, f2.y - h2);
            h = __bfloat162float(__float2bfloat16_rn(f3.x));
            h2 = __bfloat162float(__float2bfloat16_rn(f3.y));
            pah[u][3] = pack2bf(h, h2); pal[u][3] = pack2bf(f3.x - h, f3.y - h2);
        }
        pv_mma(sb + OFF_V, pah, pal, oacc, wn, lane);
    }

    __syncthreads();
    float* redb = reinterpret_cast<float*>(smc + OFF_K);
    if (wn == 1) {
        int base = (wm * 32 + lane) * 32;
#pragma unroll
        for (int j = 0; j < 8; j++)
#pragma unroll
            for (int k = 0; k < 4; k++) redb[base + j * 4 + k] = oacc[j][k];
    }
    __syncthreads();
    if (wn == 0) {
        int base = (wm * 32 + lane) * 32;
#pragma unroll
        for (int j = 0; j < 8; j++) {
            float o0 = oacc[j][0] + redb[base + j * 4 + 0];
            float o1 = oacc[j][1] + redb[base + j * 4 + 1];
            float o2 = oacc[j][2] + redb[base + j * 4 + 2];
            float o3 = oacc[j][3] + redb[base + j * 4 + 3];
            int col = h * DHD + j * 8 + 2 * (lane & 3);
            *reinterpret_cast<float2*>(Y + (size_t)(t0 + fr0) * C_DIM + col) = make_float2(o0, o1);
            *reinterpret_cast<float2*>(Y + (size_t)(t0 + fr0 + 8) * C_DIM + col) = make_float2(o2, o3);
        }
    }
}

// ---------------- launch ----------------
extern "C" void kernel_launch(void* const* d_in, const int* in_sizes, int n_in,
                              void* d_out, int out_size)
{
    (void)in_sizes; (void)n_in; (void)out_size;
    const float* x    = (const float*)d_in[0];
    const float* Wq   = (const float*)d_in[1];
    const float* Wk   = (const float*)d_in[2];
    const float* Wv   = (const float*)d_in[3];
    const float* Wc   = (const float*)d_in[4];
    const float* Wg   = (const float*)d_in[5];
    const float* bg   = (const float*)d_in[6];
    const float* rmsw = (const float*)d_in[7];
    float* out = (float*)d_out;

    float *P, *D, *L, *Y;
    __half *Xh, *Xl, *Yh, *Wph, *Wpl, *Wch, *Wcl;
    cudaGetSymbolAddress((void**)&P, g_P);
    cudaGetSymbolAddress((void**)&D, g_D);
    cudaGetSymbolAddress((void**)&L, g_L);
    cudaGetSymbolAddress((void**)&Y, g_Y);
    cudaGetSymbolAddress((void**)&Xh, g_Xh);
    cudaGetSymbolAddress((void**)&Xl, g_Xl);
    cudaGetSymbolAddress((void**)&Yh, g_Yh);
    cudaGetSymbolAddress((void**)&Wph, g_Wp_h);
    cudaGetSymbolAddress((void**)&Wpl, g_Wp_l);
    cudaGetSymbolAddress((void**)&Wch, g_Wc_h);
    cudaGetSymbolAddress((void**)&Wcl, g_Wc_l);

    // merged prepass: weight transposes + x split (z=5)
    prepass_all<<<dim3(32, 32, 6), 256>>>(Wq, Wk, Wv, Wc, Wg, rmsw, x,
                                          Wph, Wpl, Wch, Wcl, Xh, Xl);

    size_t smemP = 3 * 16384;
    cudaFuncSetAttribute(gemm_proj_f16, cudaFuncAttributeMaxDynamicSharedMemorySize, (int)smemP);
    gemm_proj_f16<<<dim3(PSTR / 128, T_SEQ / 128), 256, smemP>>>(Xh, Xl, Wph, Wpl, P, T_SEQ, PSTR, C_DIM);

    scan_kernel<<<NH, 256>>>(P, bg, D, L);

    size_t smemA = OFF_SC + 6 * 64 * sizeof(float);
    cudaFuncSetAttribute(attn_fused, cudaFuncAttributeMaxDynamicSharedMemorySize, (int)smemA);
    attn_fused<<<dim3(T_SEQ / 64, NH), 256, smemA>>>(P, D, L, Y);

    norm_to_fp16<<<T_SEQ, 256>>>(Y, Yh);

    size_t smemO = 3 * 12288;
    cudaFuncSetAttribute(gemm_out_f16, cudaFuncAttributeMaxDynamicSharedMemorySize, (int)smemO);
    gemm_out_f16<<<dim3(C_DIM / 128, T_SEQ / 128), 256, smemO>>>(Yh, Wch, Wcl, out, T_SEQ, C_DIM, C_DIM);
}

// round 14
// speedup vs baseline: 1.2146x; 1.0102x over previous
#include <cuda_runtime.h>
#include <cuda_bf16.h>
#include <cuda_fp16.h>
#include <math.h>
#include <stdint.h>

#define T_SEQ 2048
#define C_DIM 1024
#define NH    16
#define NKV   4
#define DHD   64
#define WINSZ 128
#define PSTR  1664          /* fp32 P stride (gate cols live at GOFF) */
#define QKV   1536          /* split bf16 P stride: Q(1024)|K(256)|V(256) */
#define KOFF  1024
#define VOFF  1280
#define GOFF  1536
#define GATE_BLK 12

// ---------------- scratch ----------------
__device__ float g_P[T_SEQ * PSTR];                 // only gate block written
__device__ __nv_bfloat16 g_Ph[T_SEQ * QKV];         // Q|K|V hi
__device__ __nv_bfloat16 g_Pl[T_SEQ * QKV];         // Q|K|V lo
__device__ float g_D[NH * T_SEQ];
__device__ float g_L[NH * T_SEQ];
__device__ float g_Y[T_SEQ * C_DIM];
__device__ __half g_Xh[T_SEQ * C_DIM];
__device__ __half g_Xl[T_SEQ * C_DIM];
__device__ __half g_Yh[T_SEQ * C_DIM];
__device__ __half g_Wp_h[PSTR * C_DIM];
__device__ __half g_Wp_l[PSTR * C_DIM];
__device__ __half g_Wc_h[C_DIM * C_DIM];
__device__ __half g_Wc_l[C_DIM * C_DIM];

__device__ __forceinline__ float neg_inf() { return __int_as_float(0xff800000); }
__device__ __forceinline__ float log_sigmoid_f(float x) {
    return fminf(x, 0.f) - log1pf(expf(-fabsf(x)));
}
__device__ __forceinline__ uint32_t cvta_smem(const void* p) {
    uint32_t a;
    asm("{ .reg .u64 t; cvta.to.shared.u64 t, %1; cvt.u32.u64 %0, t; }" : "=r"(a) : "l"(p));
    return a;
}
__device__ __forceinline__ uint32_t pack2bf(float a, float b) {
    __nv_bfloat162 t = __floats2bfloat162_rn(a, b);
    return *reinterpret_cast<uint32_t*>(&t);
}
__device__ __forceinline__ uint32_t pack2h(float a, float b) {
    __half2 t = __floats2half2_rn(a, b);
    return *reinterpret_cast<uint32_t*>(&t);
}
__device__ __forceinline__ void ldsm4(uint32_t* r, uint32_t addr) {
    asm volatile("ldmatrix.sync.aligned.m8n8.x4.shared.b16 {%0,%1,%2,%3}, [%4];"
                 : "=r"(r[0]), "=r"(r[1]), "=r"(r[2]), "=r"(r[3]) : "r"(addr));
}
__device__ __forceinline__ void ldsm4t(uint32_t* r, uint32_t addr) {
    asm volatile("ldmatrix.sync.aligned.m8n8.x4.trans.shared.b16 {%0,%1,%2,%3}, [%4];"
                 : "=r"(r[0]), "=r"(r[1]), "=r"(r[2]), "=r"(r[3]) : "r"(addr));
}
__device__ __forceinline__ void mma_bf16(float* c, const uint32_t* a, const uint32_t* b) {
    asm volatile(
        "mma.sync.aligned.m16n8k16.row.col.f32.bf16.bf16.f32 "
        "{%0,%1,%2,%3}, {%4,%5,%6,%7}, {%8,%9}, {%0,%1,%2,%3};"
        : "+f"(c[0]), "+f"(c[1]), "+f"(c[2]), "+f"(c[3])
        : "r"(a[0]), "r"(a[1]), "r"(a[2]), "r"(a[3]), "r"(b[0]), "r"(b[1]));
}
__device__ __forceinline__ void mma_fp16(float* c, const uint32_t* a, const uint32_t* b) {
    asm volatile(
        "mma.sync.aligned.m16n8k16.row.col.f32.f16.f16.f32 "
        "{%0,%1,%2,%3}, {%4,%5,%6,%7}, {%8,%9}, {%0,%1,%2,%3};"
        : "+f"(c[0]), "+f"(c[1]), "+f"(c[2]), "+f"(c[3])
        : "r"(a[0]), "r"(a[1]), "r"(a[2]), "r"(a[3]), "r"(b[0]), "r"(b[1]));
}
__device__ __forceinline__ void cpasync16(uint32_t dst, const void* src) {
    asm volatile("cp.async.cg.shared.global [%0], [%1], 16;" :: "r"(dst), "l"(src) : "memory");
}
#define CP_COMMIT() asm volatile("cp.async.commit_group;" ::: "memory")
#define CP_WAIT(n)  asm volatile("cp.async.wait_group %0;" :: "n"(n) : "memory")

// swizzled offset within a 128x16 (16-bit elem) tile (4KB)
__device__ __forceinline__ uint32_t phys16(int row, int c) {
    return (uint32_t)((row >> 2) * 128 + (((((row & 3) * 2) + c) ^ ((row >> 2) & 1)) * 16));
}

// cp.async a 64x64 bf16 tile pair (hi/lo) from pre-split global into swizzled smem.
// smem layout per tile: row r (128B), 16B chunk c at ((c^(r&7))*16) holding cols [8c,8c+8)
__device__ __forceinline__ void cp_tile(
    const __nv_bfloat16* __restrict__ gh, const __nv_bfloat16* __restrict__ gl,
    uint32_t smH, uint32_t smL, int tid)
{
#pragma unroll
    for (int i = 0; i < 2; i++) {
        int f = tid + i * 256;           // chunk id 0..511
        int r = f >> 3, c = f & 7;
        uint32_t off = (uint32_t)r * 128u + (uint32_t)((c ^ (r & 7)) * 16);
        cpasync16(smH + off, gh + (size_t)r * QKV + c * 8);
        cpasync16(smL + off, gl + (size_t)r * QKV + c * 8);
    }
}

// ---------------- merged prepass: weight transpose + fp16 split + x split ----------------
__global__ __launch_bounds__(256) void prepass_all(
    const float* __restrict__ Wq, const float* __restrict__ Wk,
    const float* __restrict__ Wv, const float* __restrict__ Wc,
    const float* __restrict__ Wg, const float* __restrict__ rmsw,
    const float* __restrict__ x,
    __half* __restrict__ Wph, __half* __restrict__ Wpl,
    __half* __restrict__ Wch, __half* __restrict__ Wcl,
    __half* __restrict__ Xh, __half* __restrict__ Xl)
{
    int z = blockIdx.z;
    if (z == 5) {
        int blk = blockIdx.y * 32 + blockIdx.x;
        int tid = threadIdx.x;
#pragma unroll
        for (int rr = 0; rr < 2; rr++) {
            int t = blk * 2 + rr;
            float4 v = *reinterpret_cast<const float4*>(x + (size_t)t * C_DIM + tid * 4);
            float h0 = __half2float(__float2half_rn(v.x));
            float h1 = __half2float(__float2half_rn(v.y));
            float h2 = __half2float(__float2half_rn(v.z));
            float h3 = __half2float(__float2half_rn(v.w));
            uint2 hh = make_uint2(pack2h(h0, h1), pack2h(h2, h3));
            uint2 ll = make_uint2(pack2h(v.x - h0, v.y - h1), pack2h(v.z - h2, v.w - h3));
            *reinterpret_cast<uint2*>(Xh + (size_t)t * C_DIM + tid * 4) = hh;
            *reinterpret_cast<uint2*>(Xl + (size_t)t * C_DIM + tid * 4) = ll;
        }
        return;
    }
    const float* W; __half *Th, *Tl; int N, rowOff = 0; bool useScale = false;
    if (z == 0)      { W = Wq; Th = Wph; Tl = Wpl; N = 1024; }
    else if (z == 1) { W = Wk; Th = Wph; Tl = Wpl; N = 256; rowOff = KOFF; }
    else if (z == 2) { W = Wv; Th = Wph; Tl = Wpl; N = 256; rowOff = VOFF; }
    else if (z == 3) { W = Wc; Th = Wch; Tl = Wcl; N = 1024; useScale = true; }
    else             { W = Wg; Th = Wph; Tl = Wpl; N = 16;  rowOff = GOFF; }
    int n0 = blockIdx.x * 32;
    if (n0 >= N) return;
    int k0 = blockIdx.y * 32;

    __shared__ float s[32][33];
    int tx = threadIdx.x & 31, ty = threadIdx.x >> 5;
#pragma unroll
    for (int i = 0; i < 4; i++) {
        int r = ty + i * 8;
        if (n0 + tx < N) {
            float v = W[(size_t)(k0 + r) * N + n0 + tx];
            if (useScale) v *= rmsw[k0 + r];
            s[r][tx] = v;
        }
    }
    __syncthreads();
#pragma unroll
    for (int i = 0; i < 4; i++) {
        int r = ty + i * 8;
        if (n0 + r < N) {
            float v = s[tx][r];
            __half h = __float2half_rn(v);
            Th[(size_t)(rowOff + n0 + r) * C_DIM + k0 + tx] = h;
            Tl[(size_t)(rowOff + n0 + r) * C_DIM + k0 + tx] = __float2half_rn(v - __half2float(h));
        }
    }
}

// ---------------- Y -> fp16 with fused RMSNorm row scale ----------------
__global__ __launch_bounds__(256) void norm_to_fp16(
    const float* __restrict__ X, __half* __restrict__ Ah)
{
    int t = blockIdx.x, tid = threadIdx.x;
    float4 v = *reinterpret_cast<const float4*>(X + (size_t)t * C_DIM + tid * 4);
    float ss = v.x * v.x + v.y * v.y + v.z * v.z + v.w * v.w;
#pragma unroll
    for (int off = 16; off; off >>= 1) ss += __shfl_xor_sync(0xffffffff, ss, off);
    __shared__ float red[8];
    if ((tid & 31) == 0) red[tid >> 5] = ss;
    __syncthreads();
    float s = red[0];
#pragma unroll
    for (int i = 1; i < 8; i++) s += red[i];
    float scale = rsqrtf(s * (1.f / (float)C_DIM) + 1e-5f);
    uint2 hh = make_uint2(pack2h(v.x * scale, v.y * scale), pack2h(v.z * scale, v.w * scale));
    *reinterpret_cast<uint2*>(Ah + (size_t)t * C_DIM + tid * 4) = hh;
}

// ---------------- proj GEMM: fp16 A x (Bh+Bl) 2-term; gate block adds al*bh ----------------
// Q/K/V blocks write split bf16 Ph/Pl; gate block writes fp32 P.
__global__ __launch_bounds__(256, 2) void gemm_proj_f16(
    const __half* __restrict__ Ah, const __half* __restrict__ Al,
    const __half* __restrict__ Bh, const __half* __restrict__ Bl,
    float* __restrict__ C, __nv_bfloat16* __restrict__ Ph,
    __nv_bfloat16* __restrict__ Pl, int M, int N, int K)
{
    extern __shared__ char smc[];
    uint32_t sb = cvta_smem(smc);
    const uint32_t STG = 16384u;

    int tid = threadIdx.x, lane = tid & 31, warp = tid >> 5;
    int wm = warp & 3, wn = warp >> 2;
    int m0 = blockIdx.y * 128, n0 = blockIdx.x * 128;
    bool prec = ((int)blockIdx.x == GATE_BLK);

    int lrow = tid >> 1, lc = tid & 1;
    uint32_t ldst = phys16(lrow, lc);
    const __half* gA  = Ah + (size_t)(m0 + lrow) * K + lc * 8;
    const __half* gAl = Al + (size_t)(m0 + lrow) * K + lc * 8;
    const __half* gBh = Bh + (size_t)(n0 + lrow) * K + lc * 8;
    const __half* gBl = Bl + (size_t)(n0 + lrow) * K + lc * 8;

    int nkt = K / 16;
    float acc[2][8][4] = {};

#pragma unroll
    for (int p = 0; p < 2; p++) {
        uint32_t st = sb + (uint32_t)p * STG;
        cpasync16(st + ldst,          gA + p * 16);
        cpasync16(st + 4096u + ldst,  gBh + p * 16);
        cpasync16(st + 8192u + ldst,  gBl + p * 16);
        if (prec) cpasync16(st + 12288u + ldst, gAl + p * 16);
        CP_COMMIT();
    }

    int aRow = (lane & 15), aC = lane >> 4;
    int bRowBase = (lane & 7) + ((lane >> 4) << 3);
    int bC = (lane >> 3) & 1;

    for (int kt = 0; kt < nkt; ++kt) {
        if (kt + 2 < nkt) { CP_WAIT(1); } else { CP_WAIT(0); }
        __syncthreads();

        uint32_t st = sb + (uint32_t)(kt % 3) * STG;
        uint32_t ah[2][4], al[2][4];
#pragma unroll
        for (int t = 0; t < 2; t++) {
            int r = wm * 32 + t * 16 + aRow;
            ldsm4(ah[t], st + phys16(r, aC));
        }
        if (prec) {
#pragma unroll
            for (int t = 0; t < 2; t++) {
                int r = wm * 32 + t * 16 + aRow;
                ldsm4(al[t], st + 12288u + phys16(r, aC));
            }
        }
#pragma unroll
        for (int g = 0; g < 4; g++) {
            int r = wn * 64 + g * 16 + bRowBase;
            uint32_t bh[4], bl[4];
            ldsm4(bh, st + 4096u + phys16(r, bC));
            ldsm4(bl, st + 8192u + phys16(r, bC));
#pragma unroll
            for (int t = 0; t < 2; t++)
#pragma unroll
                for (int jj = 0; jj < 2; jj++) {
                    int j = g * 2 + jj;
                    mma_fp16(acc[t][j], ah[t], &bh[2 * jj]);
                    mma_fp16(acc[t][j], ah[t], &bl[2 * jj]);
                }
            if (prec) {
#pragma unroll
                for (int t = 0; t < 2; t++)
#pragma unroll
                    for (int jj = 0; jj < 2; jj++)
                        mma_fp16(acc[t][g * 2 + jj], al[t], &bh[2 * jj]);
            }
        }

        if (kt + 2 < nkt) {
            uint32_t st2 = sb + (uint32_t)((kt + 2) % 3) * STG;
            int ko = (kt + 2) * 16;
            cpasync16(st2 + ldst,          gA + ko);
            cpasync16(st2 + 4096u + ldst,  gBh + ko);
            cpasync16(st2 + 8192u + ldst,  gBl + ko);
            if (prec) cpasync16(st2 + 12288u + ldst, gAl + ko);
            CP_COMMIT();
        }
    }

    // RoPE epilogue (Q,K head columns only)
    if ((n0 + wn * 64) < 1280) {
#pragma unroll
        for (int j = 0; j < 4; j++) {
#pragma unroll
            for (int e = 0; e < 2; e++) {
                int d = j * 8 + 2 * (lane & 3) + e;
                float invf = expf(-(float)(2 * d) * (9.210340371976184f / 64.f));
#pragma unroll
                for (int mt = 0; mt < 2; mt++) {
#pragma unroll
                    for (int rh = 0; rh < 2; rh++) {
                        int trow = m0 + wm * 32 + mt * 16 + (lane >> 2) + rh * 8;
                        float sn, cs;
                        sincosf((float)trow * invf, &sn, &cs);
                        int k = 2 * rh + e;
                        float a = acc[mt][j][k], b = acc[mt][j + 4][k];
                        acc[mt][j][k]     = a * cs - b * sn;
                        acc[mt][j + 4][k] = b * cs + a * sn;
                    }
                }
            }
        }
    }

    if (!prec) {
        // Q/K/V columns: write split bf16 (stride QKV)
#pragma unroll
        for (int t = 0; t < 2; t++) {
            int r0 = m0 + wm * 32 + t * 16 + (lane >> 2);
#pragma unroll
            for (int j = 0; j < 8; j++) {
                int col = n0 + wn * 64 + j * 8 + 2 * (lane & 3);
                float v0 = acc[t][j][0], v1 = acc[t][j][1];
                float v2 = acc[t][j][2], v3 = acc[t][j][3];
                float h0 = __bfloat162float(__float2bfloat16_rn(v0));
                float h1 = __bfloat162float(__float2bfloat16_rn(v1));
                float h2 = __bfloat162float(__float2bfloat16_rn(v2));
                float h3 = __bfloat162float(__float2bfloat16_rn(v3));
                *reinterpret_cast<uint32_t*>(Ph + (size_t)r0 * QKV + col) = pack2bf(h0, h1);
                *reinterpret_cast<uint32_t*>(Pl + (size_t)r0 * QKV + col) = pack2bf(v0 - h0, v1 - h1);
                *reinterpret_cast<uint32_t*>(Ph + (size_t)(r0 + 8) * QKV + col) = pack2bf(h2, h3);
                *reinterpret_cast<uint32_t*>(Pl + (size_t)(r0 + 8) * QKV + col) = pack2bf(v2 - h2, v3 - h3);
            }
        }
    } else {
        // gate block: fp32 P (scan reads it)
#pragma unroll
        for (int t = 0; t < 2; t++) {
            int r0 = m0 + wm * 32 + t * 16 + (lane >> 2);
#pragma unroll
            for (int j = 0; j < 8; j++) {
                int col = n0 + wn * 64 + j * 8 + 2 * (lane & 3);
                *reinterpret_cast<float2*>(C + (size_t)r0 * N + col) = make_float2(acc[t][j][0], acc[t][j][1]);
                *reinterpret_cast<float2*>(C + (size_t)(r0 + 8) * N + col) = make_float2(acc[t][j][2], acc[t][j][3]);
            }
        }
    }
}

// ---------------- out GEMM: fp16 A (single) x (Bh+Bl), 2-term ----------------
__global__ __launch_bounds__(256, 2) void gemm_out_f16(
    const __half* __restrict__ Ah, const __half* __restrict__ Bh,
    const __half* __restrict__ Bl, float* __restrict__ C,
    int M, int N, int K)
{
    extern __shared__ char smc[];
    uint32_t sb = cvta_smem(smc);
    const uint32_t STG = 12288u;

    int tid = threadIdx.x, lane = tid & 31, warp = tid >> 5;
    int wm = warp & 3, wn = warp >> 2;
    int m0 = blockIdx.y * 128, n0 = blockIdx.x * 128;

    int lrow = tid >> 1, lc = tid & 1;
    uint32_t ldst = phys16(lrow, lc);
    const __half* gA = Ah + (size_t)(m0 + lrow) * K + lc * 8;
    const __half* gBh = Bh + (size_t)(n0 + lrow) * K + lc * 8;
    const __half* gBl = Bl + (size_t)(n0 + lrow) * K + lc * 8;

    int nkt = K / 16;
    float acc[2][8][4] = {};

#pragma unroll
    for (int p = 0; p < 2; p++) {
        uint32_t st = sb + (uint32_t)p * STG;
        cpasync16(st + ldst,          gA + p * 16);
        cpasync16(st + 4096u + ldst,  gBh + p * 16);
        cpasync16(st + 8192u + ldst,  gBl + p * 16);
        CP_COMMIT();
    }

    int aRow = (lane & 15), aC = lane >> 4;
    int bRowBase = (lane & 7) + ((lane >> 4) << 3);
    int bC = (lane >> 3) & 1;

    for (int kt = 0; kt < nkt; ++kt) {
        if (kt + 2 < nkt) { CP_WAIT(1); } else { CP_WAIT(0); }
        __syncthreads();

        uint32_t st = sb + (uint32_t)(kt % 3) * STG;
        uint32_t ah[2][4];
#pragma unroll
        for (int t = 0; t < 2; t++) {
            int r = wm * 32 + t * 16 + aRow;
            ldsm4(ah[t], st + phys16(r, aC));
        }
#pragma unroll
        for (int g = 0; g < 4; g++) {
            int r = wn * 64 + g * 16 + bRowBase;
            uint32_t bh[4], bl[4];
            ldsm4(bh, st + 4096u + phys16(r, bC));
            ldsm4(bl, st + 8192u + phys16(r, bC));
#pragma unroll
            for (int t = 0; t < 2; t++)
#pragma unroll
                for (int jj = 0; jj < 2; jj++) {
                    int j = g * 2 + jj;
                    mma_fp16(acc[t][j], ah[t], &bh[2 * jj]);
                    mma_fp16(acc[t][j], ah[t], &bl[2 * jj]);
                }
        }

        if (kt + 2 < nkt) {
            uint32_t st2 = sb + (uint32_t)((kt + 2) % 3) * STG;
            int ko = (kt + 2) * 16;
            cpasync16(st2 + ldst,          gA + ko);
            cpasync16(st2 + 4096u + ldst,  gBh + ko);
            cpasync16(st2 + 8192u + ldst,  gBl + ko);
            CP_COMMIT();
        }
    }

#pragma unroll
    for (int t = 0; t < 2; t++) {
        int r0 = m0 + wm * 32 + t * 16 + (lane >> 2);
#pragma unroll
        for (int j = 0; j < 8; j++) {
            int col = n0 + wn * 64 + j * 8 + 2 * (lane & 3);
            *reinterpret_cast<float2*>(C + (size_t)r0 * N + col) = make_float2(acc[t][j][0], acc[t][j][1]);
            *reinterpret_cast<float2*>(C + (size_t)(r0 + 8) * N + col) = make_float2(acc[t][j][2], acc[t][j][3]);
        }
    }
}

// ---------------- per-head scan (warp-shuffle) ----------------
__global__ __launch_bounds__(256) void scan_kernel(
    const float* __restrict__ P, const float* __restrict__ bg,
    float* __restrict__ D, float* __restrict__ L)
{
    int h = blockIdx.x, tid = threadIdx.x, lane = tid & 31, wid = tid >> 5;
    float b = bg[h];
    float vals[8];
    float run = 0.f;
#pragma unroll
    for (int i = 0; i < 8; i++) {
        int t = tid * 8 + i;
        float gg = P[(size_t)t * PSTR + GOFF + h] + b;
        run += log_sigmoid_f(gg);
        vals[i] = run;
        L[h * T_SEQ + t] = log_sigmoid_f(-gg);
    }
    float x = run;
#pragma unroll
    for (int off = 1; off < 32; off <<= 1) {
        float y = __shfl_up_sync(0xffffffff, x, off);
        if (lane >= off) x += y;
    }
    __shared__ float wsum[8];
    if (lane == 31) wsum[wid] = x;
    __syncthreads();
    float woff = 0.f;
#pragma unroll
    for (int w = 0; w < 8; w++) if (w < wid) woff += wsum[w];
    float excl = x - run + woff;
#pragma unroll
    for (int i = 0; i < 8; i++) D[h * T_SEQ + tid * 8 + i] = vals[i] + excl;
}

// ---------------- fused attention (register-P, bf16x3, cp.async tiles) ----------------
#define OFF_Q  0u
#define OFF_K  16384u
#define OFF_V  32768u
#define OFF_S  49152u
#define SSTR   132
#define OFF_SC (49152u + 64u * SSTR * 4u)

__device__ __forceinline__ void pv_mma(
    uint32_t sbV, uint32_t pah[2][4], uint32_t pal[2][4],
    float (*oacc)[4], int wn, int lane)
{
#pragma unroll
    for (int u = 0; u < 2; u++) {
        int vrow = wn * 32 + u * 16 + (lane & 15);
        uint32_t vb = sbV + (uint32_t)vrow * 128u;
#pragma unroll
        for (int gg = 0; gg < 4; gg++) {
            int cch = 2 * gg + (lane >> 4);
            uint32_t vh[4], vl[4];
            ldsm4t(vh, vb + (uint32_t)((cch ^ (vrow & 7)) * 16));
            ldsm4t(vl, vb + 8192u + (uint32_t)((cch ^ (vrow & 7)) * 16));
#pragma unroll
            for (int jj = 0; jj < 2; jj++) {
                int j = gg * 2 + jj;
                mma_bf16(oacc[j], pah[u], &vh[2 * jj]);
                mma_bf16(oacc[j], pah[u], &vl[2 * jj]);
                mma_bf16(oacc[j], pal[u], &vh[2 * jj]);
            }
        }
    }
}

__global__ __launch_bounds__(256, 2) void attn_fused(
    const __nv_bfloat16* __restrict__ Ph, const __nv_bfloat16* __restrict__ Pl,
    const float* __restrict__ D, const float* __restrict__ L,
    float* __restrict__ Y)
{
    extern __shared__ char smc[];
    uint32_t sb = cvta_smem(smc);
    float* smS  = reinterpret_cast<float*>(smc + OFF_S);
    float* Dq   = reinterpret_cast<float*>(smc + OFF_SC);
    float* rowE = Dq + 64;
    float* Ds   = rowE + 64;
    float* Ls   = Ds + 64;
    float* colE = Ls + 64;

    int qt = blockIdx.x, h = blockIdx.y;
    int kvh = h >> 2;
    int tid = threadIdx.x, lane = tid & 31, warp = tid >> 5;
    int wm = warp & 3, wn = warp >> 2;
    int t0 = qt * 64;
    int w0 = (t0 / WINSZ) * WINSZ;
    int wt0 = w0 / 64;
    int nk = t0 - w0 + 64;

    cp_tile(Ph + (size_t)t0 * QKV + h * DHD, Pl + (size_t)t0 * QKV + h * DHD,
            sb + OFF_Q, sb + OFF_Q + 8192u, tid);
    CP_COMMIT();
    if (tid < 64) Dq[tid] = D[h * T_SEQ + t0 + tid];
    CP_WAIT(0);
    __syncthreads();
    float dq0 = Dq[0];
    if (tid < 64) rowE[tid] = expf(Dq[tid] - dq0);

    int fr0 = wm * 16 + (lane >> 2);
    int fcb = wn * 32 + 2 * (lane & 3);

    float oacc[8][4] = {};

    for (int st = qt; st >= 0; --st) {
        int s0 = st * 64;
        bool inwin = (st >= wt0);
        if (!inwin) {
            float dend = D[h * T_SEQ + s0 + 63];
            if (dq0 - dend < -88.f) break;
        }
        __syncthreads();

        cp_tile(Ph + (size_t)s0 * QKV + KOFF + kvh * DHD, Pl + (size_t)s0 * QKV + KOFF + kvh * DHD,
                sb + OFF_K, sb + OFF_K + 8192u, tid);
        cp_tile(Ph + (size_t)s0 * QKV + VOFF + kvh * DHD, Pl + (size_t)s0 * QKV + VOFF + kvh * DHD,
                sb + OFF_V, sb + OFF_V + 8192u, tid);
        CP_COMMIT();
        if (tid < 64) {
            float ds = D[h * T_SEQ + s0 + tid];
            float ls = L[h * T_SEQ + s0 + tid];
            Ds[tid] = ds; Ls[tid] = ls;
            colE[tid] = expf(dq0 - ds + ls);
        }
        CP_WAIT(0);
        __syncthreads();

        float sacc[4][4] = {};
        {
            int arow = wm * 16 + (lane & 15);
            int asel = lane >> 4;
            int nrow = wn * 32 + (lane & 7) + ((lane >> 4) << 3);
            int bsel = (lane >> 3) & 1;
#pragma unroll
            for (int ks = 0; ks < 4; ks++) {
                uint32_t ah[4], al[4];
                uint32_t abase = sb + OFF_Q + (uint32_t)arow * 128u;
                ldsm4(ah, abase + (uint32_t)(((2 * ks + asel) ^ (arow & 7)) * 16));
                ldsm4(al, abase + 8192u + (uint32_t)(((2 * ks + asel) ^ (arow & 7)) * 16));
                uint32_t bh[2][4], bl[2][4];
#pragma unroll
                for (int g = 0; g < 2; g++) {
                    int r = nrow + g * 16;
                    uint32_t bbase = sb + OFF_K + (uint32_t)r * 128u;
                    ldsm4(bh[g], bbase + (uint32_t)(((2 * ks + bsel) ^ (r & 7)) * 16));
                    ldsm4(bl[g], bbase + 8192u + (uint32_t)(((2 * ks + bsel) ^ (r & 7)) * 16));
                }
#pragma unroll
                for (int j = 0; j < 4; j++) {
                    const uint32_t* b2h = &bh[j >> 1][2 * (j & 1)];
                    const uint32_t* b2l = &bl[j >> 1][2 * (j & 1)];
                    mma_bf16(sacc[j], ah, b2h);
                    mma_bf16(sacc[j], ah, b2l);
                    mma_bf16(sacc[j], al, b2h);
                }
            }
        }

        uint32_t pah[2][4], pal[2][4];
        {
            int colbase = s0 - w0;
#pragma unroll
            for (int j = 0; j < 4; j++) {
                int cj = fcb + 8 * j;
#pragma unroll
                for (int half = 0; half < 2; half++) {
                    int r = fr0 + half * 8;
                    float v0 = sacc[j][2 * half], v1 = sacc[j][2 * half + 1];
                    if (inwin) {
                        float l0 = (s0 + cj     <= t0 + r) ? v0 * 0.125f : neg_inf();
                        float l1 = (s0 + cj + 1 <= t0 + r) ? v1 * 0.125f : neg_inf();
                        *reinterpret_cast<float2*>(&smS[r * SSTR + colbase + cj]) = make_float2(l0, l1);
                    }
                    float p0, p1;
                    if (st == qt) {
                        p0 = (cj     <= r) ? v0 * expf(Dq[r] - Ds[cj] + Ls[cj]) : 0.f;
                        p1 = (cj + 1 <= r) ? v1 * expf(Dq[r] - Ds[cj + 1] + Ls[cj + 1]) : 0.f;
                    } else {
                        float re = rowE[r];
                        p0 = v0 * (re * colE[cj]);
                        p1 = v1 * (re * colE[cj + 1]);
                    }
                    float h0 = __bfloat162float(__float2bfloat16_rn(p0));
                    float h1 = __bfloat162float(__float2bfloat16_rn(p1));
                    int u = j >> 1, ri = (j & 1) * 2 + half;
                    pah[u][ri] = pack2bf(h0, h1);
                    pal[u][ri] = pack2bf(p0 - h0, p1 - h1);
                }
            }
        }

        pv_mma(sb + OFF_V, pah, pal, oacc, wn, lane);
    }

    __syncthreads();
    {
        int r = tid >> 2, g = tid & 3;
        float m = neg_inf();
        for (int c = g; c < nk; c += 4) m = fmaxf(m, smS[r * SSTR + c]);
        m = fmaxf(m, __shfl_xor_sync(0xffffffff, m, 1));
        m = fmaxf(m, __shfl_xor_sync(0xffffffff, m, 2));
        float sum = 0.f;
        for (int c = g; c < nk; c += 4) {
            float e = expf(smS[r * SSTR + c] - m);
            smS[r * SSTR + c] = e;
            sum += e;
        }
        sum += __shfl_xor_sync(0xffffffff, sum, 1);
        sum += __shfl_xor_sync(0xffffffff, sum, 2);
        float inv = 1.f / sum;
        for (int c = g; c < nk; c += 4) smS[r * SSTR + c] *= inv;
    }

    for (int kh = 0; kh < (nk >> 6); kh++) {
        __syncthreads();
        cp_tile(Ph + (size_t)(w0 + kh * 64) * QKV + VOFF + kvh * DHD,
                Pl + (size_t)(w0 + kh * 64) * QKV + VOFF + kvh * DHD,
                sb + OFF_V, sb + OFF_V + 8192u, tid);
        CP_COMMIT();
        CP_WAIT(0);
        __syncthreads();
        uint32_t pah[2][4], pal[2][4];
#pragma unroll
        for (int u = 0; u < 2; u++) {
            int bc = kh * 64 + wn * 32 + u * 16 + 2 * (lane & 3);
            float2 f0 = *reinterpret_cast<const float2*>(&smS[fr0 * SSTR + bc]);
            float2 f1 = *reinterpret_cast<const float2*>(&smS[(fr0 + 8) * SSTR + bc]);
            float2 f2 = *reinterpret_cast<const float2*>(&smS[fr0 * SSTR + bc + 8]);
            float2 f3 = *reinterpret_cast<const float2*>(&smS[(fr0 + 8) * SSTR + bc + 8]);
            float h, h2;
            h = __bfloat162float(__float2bfloat16_rn(f0.x));
            h2 = __bfloat162float(__float2bfloat16_rn(f0.y));
            pah[u][0] = pack2bf(h, h2); pal[u][0] = pack2bf(f0.x - h, f0.y - h2);
            h = __bfloat162float(__float2bfloat16_rn(f1.x));
            h2 = __bfloat162float(__float2bfloat16_rn(f1.y));
            pah[u][1] = pack2bf(h, h2); pal[u][1] = pack2bf(f1.x - h, f1.y - h2);
            h = __bfloat162float(__float2bfloat16_rn(f2.x));
            h2 = __bfloat162float(__float2bfloat16_rn(f2.y));
            pah[u][2] = pack2bf(h, h2); pal[u][2] = pack2bf(f2.x - h, f2.y - h2);
            h = __bfloat162float(__float2bfloat16_rn(f3.x));
            h2 = __bfloat162float(__float2bfloat16_rn(f3.y));
            pah[u][3] = pack2bf(h, h2); pal[u][3] = pack2bf(f3.x - h, f3.y - h2);
        }
        pv_mma(sb + OFF_V, pah, pal, oacc, wn, lane);
    }

    __syncthreads();
    float* redb = reinterpret_cast<float*>(smc + OFF_K);
    if (wn == 1) {
        int base = (wm * 32 + lane) * 32;
#pragma unroll
        for (int j = 0; j < 8; j++)
#pragma unroll
            for (int k = 0; k < 4; k++) redb[base + j * 4 + k] = oacc[j][k];
    }
    __syncthreads();
    if (wn == 0) {
        int base = (wm * 32 + lane) * 32;
#pragma unroll
        for (int j = 0; j < 8; j++) {
            float o0 = oacc[j][0] + redb[base + j * 4 + 0];
            float o1 = oacc[j][1] + redb[base + j * 4 + 1];
            float o2 = oacc[j][2] + redb[base + j * 4 + 2];
            float o3 = oacc[j][3] + redb[base + j * 4 + 3];
            int col = h * DHD + j * 8 + 2 * (lane & 3);
            *reinterpret_cast<float2*>(Y + (size_t)(t0 + fr0) * C_DIM + col) = make_float2(o0, o1);
            *reinterpret_cast<float2*>(Y + (size_t)(t0 + fr0 + 8) * C_DIM + col) = make_float2(o2, o3);
        }
    }
}

// ---------------- launch ----------------
extern "C" void kernel_launch(void* const* d_in, const int* in_sizes, int n_in,
                              void* d_out, int out_size)
{
    (void)in_sizes; (void)n_in; (void)out_size;
    const float* x    = (const float*)d_in[0];
    const float* Wq   = (const float*)d_in[1];
    const float* Wk   = (const float*)d_in[2];
    const float* Wv   = (const float*)d_in[3];
    const float* Wc   = (const float*)d_in[4];
    const float* Wg   = (const float*)d_in[5];
    const float* bg   = (const float*)d_in[6];
    const float* rmsw = (const float*)d_in[7];
    float* out = (float*)d_out;

    float *P, *D, *L, *Y;
    __nv_bfloat16 *Ph, *Pl;
    __half *Xh, *Xl, *Yh, *Wph, *Wpl, *Wch, *Wcl;
    cudaGetSymbolAddress((void**)&P, g_P);
    cudaGetSymbolAddress((void**)&Ph, g_Ph);
    cudaGetSymbolAddress((void**)&Pl, g_Pl);
    cudaGetSymbolAddress((void**)&D, g_D);
    cudaGetSymbolAddress((void**)&L, g_L);
    cudaGetSymbolAddress((void**)&Y, g_Y);
    cudaGetSymbolAddress((void**)&Xh, g_Xh);
    cudaGetSymbolAddress((void**)&Xl, g_Xl);
    cudaGetSymbolAddress((void**)&Yh, g_Yh);
    cudaGetSymbolAddress((void**)&Wph, g_Wp_h);
    cudaGetSymbolAddress((void**)&Wpl, g_Wp_l);
    cudaGetSymbolAddress((void**)&Wch, g_Wc_h);
    cudaGetSymbolAddress((void**)&Wcl, g_Wc_l);

    prepass_all<<<dim3(32, 32, 6), 256>>>(Wq, Wk, Wv, Wc, Wg, rmsw, x,
                                          Wph, Wpl, Wch, Wcl, Xh, Xl);

    size_t smemP = 3 * 16384;
    cudaFuncSetAttribute(gemm_proj_f16, cudaFuncAttributeMaxDynamicSharedMemorySize, (int)smemP);
    gemm_proj_f16<<<dim3(PSTR / 128, T_SEQ / 128), 256, smemP>>>(Xh, Xl, Wph, Wpl, P, Ph, Pl, T_SEQ, PSTR, C_DIM);

    scan_kernel<<<NH, 256>>>(P, bg, D, L);

    size_t smemA = OFF_SC + 6 * 64 * sizeof(float);
    cudaFuncSetAttribute(attn_fused, cudaFuncAttributeMaxDynamicSharedMemorySize, (int)smemA);
    attn_fused<<<dim3(T_SEQ / 64, NH), 256, smemA>>>(Ph, Pl, D, L, Y);

    norm_to_fp16<<<T_SEQ, 256>>>(Y, Yh);

    size_t smemO = 3 * 12288;
    cudaFuncSetAttribute(gemm_out_f16, cudaFuncAttributeMaxDynamicSharedMemorySize, (int)smemO);
    gemm_out_f16<<<dim3(C_DIM / 128, T_SEQ / 128), 256, smemO>>>(Yh, Wch, Wcl, out, T_SEQ, C_DIM, C_DIM);
}

// round 15
// speedup vs baseline: 1.2154x; 1.0006x over previous
#include <cuda_runtime.h>
#include <cuda_bf16.h>
#include <cuda_fp16.h>
#include <math.h>
#include <stdint.h>

#define T_SEQ 2048
#define C_DIM 1024
#define NH    16
#define NKV   4
#define DHD   64
#define WINSZ 128
#define PSTR  1664          /* proj GEMM N (gate cols at GOFF) */
#define QKV   1536          /* split bf16 P stride: Q(1024)|K(256)|V(256) */
#define KOFF  1024
#define VOFF  1280
#define GOFF  1536
#define GATE_BLK 12

// ---------------- scratch ----------------
__device__ __nv_bfloat16 g_Ph[T_SEQ * QKV];         // Q|K|V hi
__device__ __nv_bfloat16 g_Pl[T_SEQ * QKV];         // Q|K|V lo
__device__ float g_G[NH * T_SEQ];                   // gate logits, [h][t]
__device__ float g_D[NH * T_SEQ];
__device__ float g_L[NH * T_SEQ];
__device__ float g_Y[T_SEQ * C_DIM];
__device__ __half g_Xh[T_SEQ * C_DIM];
__device__ __half g_Xl[T_SEQ * C_DIM];
__device__ __half g_Yh[T_SEQ * C_DIM];
__device__ __half g_Wp_h[PSTR * C_DIM];
__device__ __half g_Wp_l[PSTR * C_DIM];
__device__ __half g_Wc_h[C_DIM * C_DIM];
__device__ __half g_Wc_l[C_DIM * C_DIM];

__device__ __forceinline__ float neg_inf() { return __int_as_float(0xff800000); }
__device__ __forceinline__ float log_sigmoid_f(float x) {
    return fminf(x, 0.f) - log1pf(expf(-fabsf(x)));
}
__device__ __forceinline__ uint32_t cvta_smem(const void* p) {
    uint32_t a;
    asm("{ .reg .u64 t; cvta.to.shared.u64 t, %1; cvt.u32.u64 %0, t; }" : "=r"(a) : "l"(p));
    return a;
}
__device__ __forceinline__ uint32_t pack2bf(float a, float b) {
    __nv_bfloat162 t = __floats2bfloat162_rn(a, b);
    return *reinterpret_cast<uint32_t*>(&t);
}
__device__ __forceinline__ uint32_t pack2h(float a, float b) {
    __half2 t = __floats2half2_rn(a, b);
    return *reinterpret_cast<uint32_t*>(&t);
}
__device__ __forceinline__ void ldsm4(uint32_t* r, uint32_t addr) {
    asm volatile("ldmatrix.sync.aligned.m8n8.x4.shared.b16 {%0,%1,%2,%3}, [%4];"
                 : "=r"(r[0]), "=r"(r[1]), "=r"(r[2]), "=r"(r[3]) : "r"(addr));
}
__device__ __forceinline__ void ldsm4t(uint32_t* r, uint32_t addr) {
    asm volatile("ldmatrix.sync.aligned.m8n8.x4.trans.shared.b16 {%0,%1,%2,%3}, [%4];"
                 : "=r"(r[0]), "=r"(r[1]), "=r"(r[2]), "=r"(r[3]) : "r"(addr));
}
__device__ __forceinline__ void mma_bf16(float* c, const uint32_t* a, const uint32_t* b) {
    asm volatile(
        "mma.sync.aligned.m16n8k16.row.col.f32.bf16.bf16.f32 "
        "{%0,%1,%2,%3}, {%4,%5,%6,%7}, {%8,%9}, {%0,%1,%2,%3};"
        : "+f"(c[0]), "+f"(c[1]), "+f"(c[2]), "+f"(c[3])
        : "r"(a[0]), "r"(a[1]), "r"(a[2]), "r"(a[3]), "r"(b[0]), "r"(b[1]));
}
__device__ __forceinline__ void mma_fp16(float* c, const uint32_t* a, const uint32_t* b) {
    asm volatile(
        "mma.sync.aligned.m16n8k16.row.col.f32.f16.f16.f32 "
        "{%0,%1,%2,%3}, {%4,%5,%6,%7}, {%8,%9}, {%0,%1,%2,%3};"
        : "+f"(c[0]), "+f"(c[1]), "+f"(c[2]), "+f"(c[3])
        : "r"(a[0]), "r"(a[1]), "r"(a[2]), "r"(a[3]), "r"(b[0]), "r"(b[1]));
}
__device__ __forceinline__ void cpasync16(uint32_t dst, const void* src) {
    asm volatile("cp.async.cg.shared.global [%0], [%1], 16;" :: "r"(dst), "l"(src) : "memory");
}
#define CP_COMMIT() asm volatile("cp.async.commit_group;" ::: "memory")
#define CP_WAIT(n)  asm volatile("cp.async.wait_group %0;" :: "n"(n) : "memory")

// swizzled offset within a 128x16 (16-bit elem) tile (4KB)
__device__ __forceinline__ uint32_t phys16(int row, int c) {
    return (uint32_t)((row >> 2) * 128 + (((((row & 3) * 2) + c) ^ ((row >> 2) & 1)) * 16));
}

// cp.async a 64x64 bf16 tile pair (hi/lo) from pre-split global into swizzled smem.
__device__ __forceinline__ void cp_tile(
    const __nv_bfloat16* __restrict__ gh, const __nv_bfloat16* __restrict__ gl,
    uint32_t smH, uint32_t smL, int tid)
{
#pragma unroll
    for (int i = 0; i < 2; i++) {
        int f = tid + i * 256;           // chunk id 0..511
        int r = f >> 3, c = f & 7;
        uint32_t off = (uint32_t)r * 128u + (uint32_t)((c ^ (r & 7)) * 16);
        cpasync16(smH + off, gh + (size_t)r * QKV + c * 8);
        cpasync16(smL + off, gl + (size_t)r * QKV + c * 8);
    }
}

// ---------------- merged prepass: weight transpose + fp16 split + x split ----------------
__global__ __launch_bounds__(256) void prepass_all(
    const float* __restrict__ Wq, const float* __restrict__ Wk,
    const float* __restrict__ Wv, const float* __restrict__ Wc,
    const float* __restrict__ Wg, const float* __restrict__ rmsw,
    const float* __restrict__ x,
    __half* __restrict__ Wph, __half* __restrict__ Wpl,
    __half* __restrict__ Wch, __half* __restrict__ Wcl,
    __half* __restrict__ Xh, __half* __restrict__ Xl)
{
    int z = blockIdx.z;
    if (z == 5) {
        int blk = blockIdx.y * 32 + blockIdx.x;
        int tid = threadIdx.x;
#pragma unroll
        for (int rr = 0; rr < 2; rr++) {
            int t = blk * 2 + rr;
            float4 v = *reinterpret_cast<const float4*>(x + (size_t)t * C_DIM + tid * 4);
            float h0 = __half2float(__float2half_rn(v.x));
            float h1 = __half2float(__float2half_rn(v.y));
            float h2 = __half2float(__float2half_rn(v.z));
            float h3 = __half2float(__float2half_rn(v.w));
            uint2 hh = make_uint2(pack2h(h0, h1), pack2h(h2, h3));
            uint2 ll = make_uint2(pack2h(v.x - h0, v.y - h1), pack2h(v.z - h2, v.w - h3));
            *reinterpret_cast<uint2*>(Xh + (size_t)t * C_DIM + tid * 4) = hh;
            *reinterpret_cast<uint2*>(Xl + (size_t)t * C_DIM + tid * 4) = ll;
        }
        return;
    }
    const float* W; __half *Th, *Tl; int N, rowOff = 0; bool useScale = false;
    if (z == 0)      { W = Wq; Th = Wph; Tl = Wpl; N = 1024; }
    else if (z == 1) { W = Wk; Th = Wph; Tl = Wpl; N = 256; rowOff = KOFF; }
    else if (z == 2) { W = Wv; Th = Wph; Tl = Wpl; N = 256; rowOff = VOFF; }
    else if (z == 3) { W = Wc; Th = Wch; Tl = Wcl; N = 1024; useScale = true; }
    else             { W = Wg; Th = Wph; Tl = Wpl; N = 16;  rowOff = GOFF; }
    int n0 = blockIdx.x * 32;
    if (n0 >= N) return;
    int k0 = blockIdx.y * 32;

    __shared__ float s[32][33];
    int tx = threadIdx.x & 31, ty = threadIdx.x >> 5;
#pragma unroll
    for (int i = 0; i < 4; i++) {
        int r = ty + i * 8;
        if (n0 + tx < N) {
            float v = W[(size_t)(k0 + r) * N + n0 + tx];
            if (useScale) v *= rmsw[k0 + r];
            s[r][tx] = v;
        }
    }
    __syncthreads();
#pragma unroll
    for (int i = 0; i < 4; i++) {
        int r = ty + i * 8;
        if (n0 + r < N) {
            float v = s[tx][r];
            __half h = __float2half_rn(v);
            Th[(size_t)(rowOff + n0 + r) * C_DIM + k0 + tx] = h;
            Tl[(size_t)(rowOff + n0 + r) * C_DIM + k0 + tx] = __float2half_rn(v - __half2float(h));
        }
    }
}

// ---------------- Y -> fp16 with fused RMSNorm row scale ----------------
__global__ __launch_bounds__(256) void norm_to_fp16(
    const float* __restrict__ X, __half* __restrict__ Ah)
{
    int t = blockIdx.x, tid = threadIdx.x;
    float4 v = *reinterpret_cast<const float4*>(X + (size_t)t * C_DIM + tid * 4);
    float ss = v.x * v.x + v.y * v.y + v.z * v.z + v.w * v.w;
#pragma unroll
    for (int off = 16; off; off >>= 1) ss += __shfl_xor_sync(0xffffffff, ss, off);
    __shared__ float red[8];
    if ((tid & 31) == 0) red[tid >> 5] = ss;
    __syncthreads();
    float s = red[0];
#pragma unroll
    for (int i = 1; i < 8; i++) s += red[i];
    float scale = rsqrtf(s * (1.f / (float)C_DIM) + 1e-5f);
    uint2 hh = make_uint2(pack2h(v.x * scale, v.y * scale), pack2h(v.z * scale, v.w * scale));
    *reinterpret_cast<uint2*>(Ah + (size_t)t * C_DIM + tid * 4) = hh;
}

// ---------------- proj GEMM: fp16 A x (Bh+Bl) 2-term; gate block adds al*bh ----------------
// Q/K/V blocks write split bf16 Ph/Pl; gate block writes transposed fp32 G[h][t].
__global__ __launch_bounds__(256, 2) void gemm_proj_f16(
    const __half* __restrict__ Ah, const __half* __restrict__ Al,
    const __half* __restrict__ Bh, const __half* __restrict__ Bl,
    float* __restrict__ G, __nv_bfloat16* __restrict__ Ph,
    __nv_bfloat16* __restrict__ Pl, int M, int N, int K)
{
    extern __shared__ char smc[];
    uint32_t sb = cvta_smem(smc);
    const uint32_t STG = 16384u;

    int tid = threadIdx.x, lane = tid & 31, warp = tid >> 5;
    int wm = warp & 3, wn = warp >> 2;
    int m0 = blockIdx.y * 128, n0 = blockIdx.x * 128;
    bool prec = ((int)blockIdx.x == GATE_BLK);

    int lrow = tid >> 1, lc = tid & 1;
    uint32_t ldst = phys16(lrow, lc);
    const __half* gA  = Ah + (size_t)(m0 + lrow) * K + lc * 8;
    const __half* gAl = Al + (size_t)(m0 + lrow) * K + lc * 8;
    const __half* gBh = Bh + (size_t)(n0 + lrow) * K + lc * 8;
    const __half* gBl = Bl + (size_t)(n0 + lrow) * K + lc * 8;

    int nkt = K / 16;
    float acc[2][8][4] = {};

#pragma unroll
    for (int p = 0; p < 2; p++) {
        uint32_t st = sb + (uint32_t)p * STG;
        cpasync16(st + ldst,          gA + p * 16);
        cpasync16(st + 4096u + ldst,  gBh + p * 16);
        cpasync16(st + 8192u + ldst,  gBl + p * 16);
        if (prec) cpasync16(st + 12288u + ldst, gAl + p * 16);
        CP_COMMIT();
    }

    int aRow = (lane & 15), aC = lane >> 4;
    int bRowBase = (lane & 7) + ((lane >> 4) << 3);
    int bC = (lane >> 3) & 1;

    for (int kt = 0; kt < nkt; ++kt) {
        if (kt + 2 < nkt) { CP_WAIT(1); } else { CP_WAIT(0); }
        __syncthreads();

        uint32_t st = sb + (uint32_t)(kt % 3) * STG;
        uint32_t ah[2][4], al[2][4];
#pragma unroll
        for (int t = 0; t < 2; t++) {
            int r = wm * 32 + t * 16 + aRow;
            ldsm4(ah[t], st + phys16(r, aC));
        }
        if (prec) {
#pragma unroll
            for (int t = 0; t < 2; t++) {
                int r = wm * 32 + t * 16 + aRow;
                ldsm4(al[t], st + 12288u + phys16(r, aC));
            }
        }
#pragma unroll
        for (int g = 0; g < 4; g++) {
            int r = wn * 64 + g * 16 + bRowBase;
            uint32_t bh[4], bl[4];
            ldsm4(bh, st + 4096u + phys16(r, bC));
            ldsm4(bl, st + 8192u + phys16(r, bC));
#pragma unroll
            for (int t = 0; t < 2; t++)
#pragma unroll
                for (int jj = 0; jj < 2; jj++) {
                    int j = g * 2 + jj;
                    mma_fp16(acc[t][j], ah[t], &bh[2 * jj]);
                    mma_fp16(acc[t][j], ah[t], &bl[2 * jj]);
                }
            if (prec) {
#pragma unroll
                for (int t = 0; t < 2; t++)
#pragma unroll
                    for (int jj = 0; jj < 2; jj++)
                        mma_fp16(acc[t][g * 2 + jj], al[t], &bh[2 * jj]);
            }
        }

        if (kt + 2 < nkt) {
            uint32_t st2 = sb + (uint32_t)((kt + 2) % 3) * STG;
            int ko = (kt + 2) * 16;
            cpasync16(st2 + ldst,          gA + ko);
            cpasync16(st2 + 4096u + ldst,  gBh + ko);
            cpasync16(st2 + 8192u + ldst,  gBl + ko);
            if (prec) cpasync16(st2 + 12288u + ldst, gAl + ko);
            CP_COMMIT();
        }
    }

    // RoPE epilogue (Q,K head columns only)
    if ((n0 + wn * 64) < 1280) {
#pragma unroll
        for (int j = 0; j < 4; j++) {
#pragma unroll
            for (int e = 0; e < 2; e++) {
                int d = j * 8 + 2 * (lane & 3) + e;
                float invf = expf(-(float)(2 * d) * (9.210340371976184f / 64.f));
#pragma unroll
                for (int mt = 0; mt < 2; mt++) {
#pragma unroll
                    for (int rh = 0; rh < 2; rh++) {
                        int trow = m0 + wm * 32 + mt * 16 + (lane >> 2) + rh * 8;
                        float sn, cs;
                        sincosf((float)trow * invf, &sn, &cs);
                        int k = 2 * rh + e;
                        float a = acc[mt][j][k], b = acc[mt][j + 4][k];
                        acc[mt][j][k]     = a * cs - b * sn;
                        acc[mt][j + 4][k] = b * cs + a * sn;
                    }
                }
            }
        }
    }

    if (!prec) {
        // Q/K/V columns: write split bf16 (stride QKV)
#pragma unroll
        for (int t = 0; t < 2; t++) {
            int r0 = m0 + wm * 32 + t * 16 + (lane >> 2);
#pragma unroll
            for (int j = 0; j < 8; j++) {
                int col = n0 + wn * 64 + j * 8 + 2 * (lane & 3);
                float v0 = acc[t][j][0], v1 = acc[t][j][1];
                float v2 = acc[t][j][2], v3 = acc[t][j][3];
                float h0 = __bfloat162float(__float2bfloat16_rn(v0));
                float h1 = __bfloat162float(__float2bfloat16_rn(v1));
                float h2 = __bfloat162float(__float2bfloat16_rn(v2));
                float h3 = __bfloat162float(__float2bfloat16_rn(v3));
                *reinterpret_cast<uint32_t*>(Ph + (size_t)r0 * QKV + col) = pack2bf(h0, h1);
                *reinterpret_cast<uint32_t*>(Pl + (size_t)r0 * QKV + col) = pack2bf(v0 - h0, v1 - h1);
                *reinterpret_cast<uint32_t*>(Ph + (size_t)(r0 + 8) * QKV + col) = pack2bf(h2, h3);
                *reinterpret_cast<uint32_t*>(Pl + (size_t)(r0 + 8) * QKV + col) = pack2bf(v2 - h2, v3 - h3);
            }
        }
    } else {
        // gate block: write transposed logits G[h][t] (local cols 0..15 only)
        if (wn == 0) {
#pragma unroll
            for (int t = 0; t < 2; t++) {
                int r0 = m0 + wm * 32 + t * 16 + (lane >> 2);
#pragma unroll
                for (int j = 0; j < 2; j++) {
                    int colg = j * 8 + 2 * (lane & 3);
                    G[(size_t)colg * T_SEQ + r0] = acc[t][j][0];
                    G[(size_t)(colg + 1) * T_SEQ + r0] = acc[t][j][1];
                    G[(size_t)colg * T_SEQ + r0 + 8] = acc[t][j][2];
                    G[(size_t)(colg + 1) * T_SEQ + r0 + 8] = acc[t][j][3];
                }
            }
        }
    }
}

// ---------------- out GEMM: fp16 A (single) x (Bh+Bl), 2-term ----------------
__global__ __launch_bounds__(256, 2) void gemm_out_f16(
    const __half* __restrict__ Ah, const __half* __restrict__ Bh,
    const __half* __restrict__ Bl, float* __restrict__ C,
    int M, int N, int K)
{
    extern __shared__ char smc[];
    uint32_t sb = cvta_smem(smc);
    const uint32_t STG = 12288u;

    int tid = threadIdx.x, lane = tid & 31, warp = tid >> 5;
    int wm = warp & 3, wn = warp >> 2;
    int m0 = blockIdx.y * 128, n0 = blockIdx.x * 128;

    int lrow = tid >> 1, lc = tid & 1;
    uint32_t ldst = phys16(lrow, lc);
    const __half* gA = Ah + (size_t)(m0 + lrow) * K + lc * 8;
    const __half* gBh = Bh + (size_t)(n0 + lrow) * K + lc * 8;
    const __half* gBl = Bl + (size_t)(n0 + lrow) * K + lc * 8;

    int nkt = K / 16;
    float acc[2][8][4] = {};

#pragma unroll
    for (int p = 0; p < 2; p++) {
        uint32_t st = sb + (uint32_t)p * STG;
        cpasync16(st + ldst,          gA + p * 16);
        cpasync16(st + 4096u + ldst,  gBh + p * 16);
        cpasync16(st + 8192u + ldst,  gBl + p * 16);
        CP_COMMIT();
    }

    int aRow = (lane & 15), aC = lane >> 4;
    int bRowBase = (lane & 7) + ((lane >> 4) << 3);
    int bC = (lane >> 3) & 1;

    for (int kt = 0; kt < nkt; ++kt) {
        if (kt + 2 < nkt) { CP_WAIT(1); } else { CP_WAIT(0); }
        __syncthreads();

        uint32_t st = sb + (uint32_t)(kt % 3) * STG;
        uint32_t ah[2][4];
#pragma unroll
        for (int t = 0; t < 2; t++) {
            int r = wm * 32 + t * 16 + aRow;
            ldsm4(ah[t], st + phys16(r, aC));
        }
#pragma unroll
        for (int g = 0; g < 4; g++) {
            int r = wn * 64 + g * 16 + bRowBase;
            uint32_t bh[4], bl[4];
            ldsm4(bh, st + 4096u + phys16(r, bC));
            ldsm4(bl, st + 8192u + phys16(r, bC));
#pragma unroll
            for (int t = 0; t < 2; t++)
#pragma unroll
                for (int jj = 0; jj < 2; jj++) {
                    int j = g * 2 + jj;
                    mma_fp16(acc[t][j], ah[t], &bh[2 * jj]);
                    mma_fp16(acc[t][j], ah[t], &bl[2 * jj]);
                }
        }

        if (kt + 2 < nkt) {
            uint32_t st2 = sb + (uint32_t)((kt + 2) % 3) * STG;
            int ko = (kt + 2) * 16;
            cpasync16(st2 + ldst,          gA + ko);
            cpasync16(st2 + 4096u + ldst,  gBh + ko);
            cpasync16(st2 + 8192u + ldst,  gBl + ko);
            CP_COMMIT();
        }
    }

#pragma unroll
    for (int t = 0; t < 2; t++) {
        int r0 = m0 + wm * 32 + t * 16 + (lane >> 2);
#pragma unroll
        for (int j = 0; j < 8; j++) {
            int col = n0 + wn * 64 + j * 8 + 2 * (lane & 3);
            *reinterpret_cast<float2*>(C + (size_t)r0 * N + col) = make_float2(acc[t][j][0], acc[t][j][1]);
            *reinterpret_cast<float2*>(C + (size_t)(r0 + 8) * N + col) = make_float2(acc[t][j][2], acc[t][j][3]);
        }
    }
}

// ---------------- per-head scan (warp-shuffle, coalesced G reads) ----------------
__global__ __launch_bounds__(256) void scan_kernel(
    const float* __restrict__ G, const float* __restrict__ bg,
    float* __restrict__ D, float* __restrict__ L)
{
    int h = blockIdx.x, tid = threadIdx.x, lane = tid & 31, wid = tid >> 5;
    float b = bg[h];
    float4 a0 = *reinterpret_cast<const float4*>(G + (size_t)h * T_SEQ + tid * 8);
    float4 a1 = *reinterpret_cast<const float4*>(G + (size_t)h * T_SEQ + tid * 8 + 4);
    float gv[8] = {a0.x, a0.y, a0.z, a0.w, a1.x, a1.y, a1.z, a1.w};
    float vals[8];
    float run = 0.f;
#pragma unroll
    for (int i = 0; i < 8; i++) {
        float gg = gv[i] + b;
        run += log_sigmoid_f(gg);
        vals[i] = run;
        L[h * T_SEQ + tid * 8 + i] = log_sigmoid_f(-gg);
    }
    float x = run;
#pragma unroll
    for (int off = 1; off < 32; off <<= 1) {
        float y = __shfl_up_sync(0xffffffff, x, off);
        if (lane >= off) x += y;
    }
    __shared__ float wsum[8];
    if (lane == 31) wsum[wid] = x;
    __syncthreads();
    float woff = 0.f;
#pragma unroll
    for (int w = 0; w < 8; w++) if (w < wid) woff += wsum[w];
    float excl = x - run + woff;
#pragma unroll
    for (int i = 0; i < 8; i++) D[h * T_SEQ + tid * 8 + i] = vals[i] + excl;
}

// ---------------- fused attention (register-P, bf16x3, cp.async tiles) ----------------
#define OFF_Q  0u
#define OFF_K  16384u
#define OFF_V  32768u
#define OFF_S  49152u
#define SSTR   132
#define OFF_SC (49152u + 64u * SSTR * 4u)

__device__ __forceinline__ void pv_mma(
    uint32_t sbV, uint32_t pah[2][4], uint32_t pal[2][4],
    float (*oacc)[4], int wn, int lane)
{
#pragma unroll
    for (int u = 0; u < 2; u++) {
        int vrow = wn * 32 + u * 16 + (lane & 15);
        uint32_t vb = sbV + (uint32_t)vrow * 128u;
#pragma unroll
        for (int gg = 0; gg < 4; gg++) {
            int cch = 2 * gg + (lane >> 4);
            uint32_t vh[4], vl[4];
            ldsm4t(vh, vb + (uint32_t)((cch ^ (vrow & 7)) * 16));
            ldsm4t(vl, vb + 8192u + (uint32_t)((cch ^ (vrow & 7)) * 16));
#pragma unroll
            for (int jj = 0; jj < 2; jj++) {
                int j = gg * 2 + jj;
                mma_bf16(oacc[j], pah[u], &vh[2 * jj]);
                mma_bf16(oacc[j], pah[u], &vl[2 * jj]);
                mma_bf16(oacc[j], pal[u], &vh[2 * jj]);
            }
        }
    }
}

__global__ __launch_bounds__(256, 2) void attn_fused(
    const __nv_bfloat16* __restrict__ Ph, const __nv_bfloat16* __restrict__ Pl,
    const float* __restrict__ D, const float* __restrict__ L,
    float* __restrict__ Y)
{
    extern __shared__ char smc[];
    uint32_t sb = cvta_smem(smc);
    float* smS  = reinterpret_cast<float*>(smc + OFF_S);
    float* Dq   = reinterpret_cast<float*>(smc + OFF_SC);
    float* rowE = Dq + 64;
    float* Ds   = rowE + 64;
    float* Ls   = Ds + 64;
    float* colE = Ls + 64;

    int qt = gridDim.x - 1 - blockIdx.x;     // heavy CTAs first
    int h = blockIdx.y;
    int kvh = h >> 2;
    int tid = threadIdx.x, lane = tid & 31, warp = tid >> 5;
    int wm = warp & 3, wn = warp >> 2;
    int t0 = qt * 64;
    int w0 = (t0 / WINSZ) * WINSZ;
    int wt0 = w0 / 64;
    int nk = t0 - w0 + 64;

    cp_tile(Ph + (size_t)t0 * QKV + h * DHD, Pl + (size_t)t0 * QKV + h * DHD,
            sb + OFF_Q, sb + OFF_Q + 8192u, tid);
    CP_COMMIT();
    if (tid < 64) Dq[tid] = D[h * T_SEQ + t0 + tid];
    CP_WAIT(0);
    __syncthreads();
    float dq0 = Dq[0];
    if (tid < 64) rowE[tid] = expf(Dq[tid] - dq0);

    int fr0 = wm * 16 + (lane >> 2);
    int fcb = wn * 32 + 2 * (lane & 3);

    float oacc[8][4] = {};

    for (int st = qt; st >= 0; --st) {
        int s0 = st * 64;
        bool inwin = (st >= wt0);
        if (!inwin) {
            float dend = D[h * T_SEQ + s0 + 63];
            if (dq0 - dend < -88.f) break;
        }
        __syncthreads();

        cp_tile(Ph + (size_t)s0 * QKV + KOFF + kvh * DHD, Pl + (size_t)s0 * QKV + KOFF + kvh * DHD,
                sb + OFF_K, sb + OFF_K + 8192u, tid);
        cp_tile(Ph + (size_t)s0 * QKV + VOFF + kvh * DHD, Pl + (size_t)s0 * QKV + VOFF + kvh * DHD,
                sb + OFF_V, sb + OFF_V + 8192u, tid);
        CP_COMMIT();
        if (tid < 64) {
            float ds = D[h * T_SEQ + s0 + tid];
            float ls = L[h * T_SEQ + s0 + tid];
            Ds[tid] = ds; Ls[tid] = ls;
            colE[tid] = expf(dq0 - ds + ls);
        }
        CP_WAIT(0);
        __syncthreads();

        float sacc[4][4] = {};
        {
            int arow = wm * 16 + (lane & 15);
            int asel = lane >> 4;
            int nrow = wn * 32 + (lane & 7) + ((lane >> 4) << 3);
            int bsel = (lane >> 3) & 1;
#pragma unroll
            for (int ks = 0; ks < 4; ks++) {
                uint32_t ah[4], al[4];
                uint32_t abase = sb + OFF_Q + (uint32_t)arow * 128u;
                ldsm4(ah, abase + (uint32_t)(((2 * ks + asel) ^ (arow & 7)) * 16));
                ldsm4(al, abase + 8192u + (uint32_t)(((2 * ks + asel) ^ (arow & 7)) * 16));
                uint32_t bh[2][4], bl[2][4];
#pragma unroll
                for (int g = 0; g < 2; g++) {
                    int r = nrow + g * 16;
                    uint32_t bbase = sb + OFF_K + (uint32_t)r * 128u;
                    ldsm4(bh[g], bbase + (uint32_t)(((2 * ks + bsel) ^ (r & 7)) * 16));
                    ldsm4(bl[g], bbase + 8192u + (uint32_t)(((2 * ks + bsel) ^ (r & 7)) * 16));
                }
#pragma unroll
                for (int j = 0; j < 4; j++) {
                    const uint32_t* b2h = &bh[j >> 1][2 * (j & 1)];
                    const uint32_t* b2l = &bl[j >> 1][2 * (j & 1)];
                    mma_bf16(sacc[j], ah, b2h);
                    mma_bf16(sacc[j], ah, b2l);
                    mma_bf16(sacc[j], al, b2h);
                }
            }
        }

        uint32_t pah[2][4], pal[2][4];
        {
            int colbase = s0 - w0;
#pragma unroll
            for (int j = 0; j < 4; j++) {
                int cj = fcb + 8 * j;
#pragma unroll
                for (int half = 0; half < 2; half++) {
                    int r = fr0 + half * 8;
                    float v0 = sacc[j][2 * half], v1 = sacc[j][2 * half + 1];
                    if (inwin) {
                        float l0 = (s0 + cj     <= t0 + r) ? v0 * 0.125f : neg_inf();
                        float l1 = (s0 + cj + 1 <= t0 + r) ? v1 * 0.125f : neg_inf();
                        *reinterpret_cast<float2*>(&smS[r * SSTR + colbase + cj]) = make_float2(l0, l1);
                    }
                    float p0, p1;
                    if (st == qt) {
                        p0 = (cj     <= r) ? v0 * expf(Dq[r] - Ds[cj] + Ls[cj]) : 0.f;
                        p1 = (cj + 1 <= r) ? v1 * expf(Dq[r] - Ds[cj + 1] + Ls[cj + 1]) : 0.f;
                    } else {
                        float re = rowE[r];
                        p0 = v0 * (re * colE[cj]);
                        p1 = v1 * (re * colE[cj + 1]);
                    }
                    float h0 = __bfloat162float(__float2bfloat16_rn(p0));
                    float h1 = __bfloat162float(__float2bfloat16_rn(p1));
                    int u = j >> 1, ri = (j & 1) * 2 + half;
                    pah[u][ri] = pack2bf(h0, h1);
                    pal[u][ri] = pack2bf(p0 - h0, p1 - h1);
                }
            }
        }

        pv_mma(sb + OFF_V, pah, pal, oacc, wn, lane);
    }

    __syncthreads();
    {
        int r = tid >> 2, g = tid & 3;
        float m = neg_inf();
        for (int c = g; c < nk; c += 4) m = fmaxf(m, smS[r * SSTR + c]);
        m = fmaxf(m, __shfl_xor_sync(0xffffffff, m, 1));
        m = fmaxf(m, __shfl_xor_sync(0xffffffff, m, 2));
        float sum = 0.f;
        for (int c = g; c < nk; c += 4) {
            float e = expf(smS[r * SSTR + c] - m);
            smS[r * SSTR + c] = e;
            sum += e;
        }
        sum += __shfl_xor_sync(0xffffffff, sum, 1);
        sum += __shfl_xor_sync(0xffffffff, sum, 2);
        float inv = 1.f / sum;
        for (int c = g; c < nk; c += 4) smS[r * SSTR + c] *= inv;
    }

    for (int kh = 0; kh < (nk >> 6); kh++) {
        __syncthreads();
        cp_tile(Ph + (size_t)(w0 + kh * 64) * QKV + VOFF + kvh * DHD,
                Pl + (size_t)(w0 + kh * 64) * QKV + VOFF + kvh * DHD,
                sb + OFF_V, sb + OFF_V + 8192u, tid);
        CP_COMMIT();
        CP_WAIT(0);
        __syncthreads();
        uint32_t pah[2][4], pal[2][4];
#pragma unroll
        for (int u = 0; u < 2; u++) {
            int bc = kh * 64 + wn * 32 + u * 16 + 2 * (lane & 3);
            float2 f0 = *reinterpret_cast<const float2*>(&smS[fr0 * SSTR + bc]);
            float2 f1 = *reinterpret_cast<const float2*>(&smS[(fr0 + 8) * SSTR + bc]);
            float2 f2 = *reinterpret_cast<const float2*>(&smS[fr0 * SSTR + bc + 8]);
            float2 f3 = *reinterpret_cast<const float2*>(&smS[(fr0 + 8) * SSTR + bc + 8]);
            float h, h2;
            h = __bfloat162float(__float2bfloat16_rn(f0.x));
            h2 = __bfloat162float(__float2bfloat16_rn(f0.y));
            pah[u][0] = pack2bf(h, h2); pal[u][0] = pack2bf(f0.x - h, f0.y - h2);
            h = __bfloat162float(__float2bfloat16_rn(f1.x));
            h2 = __bfloat162float(__float2bfloat16_rn(f1.y));
            pah[u][1] = pack2bf(h, h2); pal[u][1] = pack2bf(f1.x - h, f1.y - h2);
            h = __bfloat162float(__float2bfloat16_rn(f2.x));
            h2 = __bfloat162float(__float2bfloat16_rn(f2.y));
            pah[u][2] = pack2bf(h, h2); pal[u][2] = pack2bf(f2.x - h, f2.y - h2);
            h = __bfloat162float(__float2bfloat16_rn(f3.x));
            h2 = __bfloat162float(__float2bfloat16_rn(f3.y));
            pah[u][3] = pack2bf(h, h2); pal[u][3] = pack2bf(f3.x - h, f3.y - h2);
        }
        pv_mma(sb + OFF_V, pah, pal, oacc, wn, lane);
    }

    __syncthreads();
    float* redb = reinterpret_cast<float*>(smc + OFF_K);
    if (wn == 1) {
        int base = (wm * 32 + lane) * 32;
#pragma unroll
        for (int j = 0; j < 8; j++)
#pragma unroll
            for (int k = 0; k < 4; k++) redb[base + j * 4 + k] = oacc[j][k];
    }
    __syncthreads();
    if (wn == 0) {
        int base = (wm * 32 + lane) * 32;
#pragma unroll
        for (int j = 0; j < 8; j++) {
            float o0 = oacc[j][0] + redb[base + j * 4 + 0];
            float o1 = oacc[j][1] + redb[base + j * 4 + 1];
            float o2 = oacc[j][2] + redb[base + j * 4 + 2];
            float o3 = oacc[j][3] + redb[base + j * 4 + 3];
            int col = h * DHD + j * 8 + 2 * (lane & 3);
            *reinterpret_cast<float2*>(Y + (size_t)(t0 + fr0) * C_DIM + col) = make_float2(o0, o1);
            *reinterpret_cast<float2*>(Y + (size_t)(t0 + fr0 + 8) * C_DIM + col) = make_float2(o2, o3);
        }
    }
}

// ---------------- launch ----------------
extern "C" void kernel_launch(void* const* d_in, const int* in_sizes, int n_in,
                              void* d_out, int out_size)
{
    (void)in_sizes; (void)n_in; (void)out_size;
    const float* x    = (const float*)d_in[0];
    const float* Wq   = (const float*)d_in[1];
    const float* Wk   = (const float*)d_in[2];
    const float* Wv   = (const float*)d_in[3];
    const float* Wc   = (const float*)d_in[4];
    const float* Wg   = (const float*)d_in[5];
    const float* bg   = (const float*)d_in[6];
    const float* rmsw = (const float*)d_in[7];
    float* out = (float*)d_out;

    float *G, *D, *L, *Y;
    __nv_bfloat16 *Ph, *Pl;
    __half *Xh, *Xl, *Yh, *Wph, *Wpl, *Wch, *Wcl;
    cudaGetSymbolAddress((void**)&G, g_G);
    cudaGetSymbolAddress((void**)&Ph, g_Ph);
    cudaGetSymbolAddress((void**)&Pl, g_Pl);
    cudaGetSymbolAddress((void**)&D, g_D);
    cudaGetSymbolAddress((void**)&L, g_L);
    cudaGetSymbolAddress((void**)&Y, g_Y);
    cudaGetSymbolAddress((void**)&Xh, g_Xh);
    cudaGetSymbolAddress((void**)&Xl, g_Xl);
    cudaGetSymbolAddress((void**)&Yh, g_Yh);
    cudaGetSymbolAddress((void**)&Wph, g_Wp_h);
    cudaGetSymbolAddress((void**)&Wpl, g_Wp_l);
    cudaGetSymbolAddress((void**)&Wch, g_Wc_h);
    cudaGetSymbolAddress((void**)&Wcl, g_Wc_l);

    prepass_all<<<dim3(32, 32, 6), 256>>>(Wq, Wk, Wv, Wc, Wg, rmsw, x,
                                          Wph, Wpl, Wch, Wcl, Xh, Xl);

    size_t smemP = 3 * 16384;
    cudaFuncSetAttribute(gemm_proj_f16, cudaFuncAttributeMaxDynamicSharedMemorySize, (int)smemP);
    gemm_proj_f16<<<dim3(PSTR / 128, T_SEQ / 128), 256, smemP>>>(Xh, Xl, Wph, Wpl, G, Ph, Pl, T_SEQ, PSTR, C_DIM);

    scan_kernel<<<NH, 256>>>(G, bg, D, L);

    size_t smemA = OFF_SC + 6 * 64 * sizeof(float);
    cudaFuncSetAttribute(attn_fused, cudaFuncAttributeMaxDynamicSharedMemorySize, (int)smemA);
    attn_fused<<<dim3(T_SEQ / 64, NH), 256, smemA>>>(Ph, Pl, D, L, Y);

    norm_to_fp16<<<T_SEQ, 256>>>(Y, Yh);

    size_t smemO = 3 * 12288;
    cudaFuncSetAttribute(gemm_out_f16, cudaFuncAttributeMaxDynamicSharedMemorySize, (int)smemO);
    gemm_out_f16<<<dim3(C_DIM / 128, T_SEQ / 128), 256, smemO>>>(Yh, Wch, Wcl, out, T_SEQ, C_DIM, C_DIM);
}

// round 16
// speedup vs baseline: 1.2657x; 1.0414x over previous
#include <cuda_runtime.h>
#include <cuda_bf16.h>
#include <cuda_fp16.h>
#include <math.h>
#include <stdint.h>

#define T_SEQ 2048
#define C_DIM 1024
#define NH    16
#define NKV   4
#define DHD   64
#define WINSZ 128
#define PSTR  1664          /* proj GEMM N (gate cols at GOFF) */
#define QKV   1536          /* split bf16 P stride: Q(1024)|K(256)|V(256) */
#define KOFF  1024
#define VOFF  1280
#define GOFF  1536
#define GATE_BLK 12
#define DECAY_CUTOFF (-25.f)   /* dropped weights < e^-25; contribution ~1e-9 abs */

// ---------------- scratch ----------------
__device__ __nv_bfloat16 g_Ph[T_SEQ * QKV];         // Q|K|V hi
__device__ __nv_bfloat16 g_Pl[T_SEQ * QKV];         // Q|K|V lo
__device__ float g_G[NH * T_SEQ];                   // gate logits, [h][t]
__device__ float g_D[NH * T_SEQ];
__device__ float g_L[NH * T_SEQ];
__device__ float g_Y[T_SEQ * C_DIM];
__device__ __half g_Xh[T_SEQ * C_DIM];
__device__ __half g_Xl[T_SEQ * C_DIM];
__device__ __half g_Yh[T_SEQ * C_DIM];
__device__ __half g_Wp_h[PSTR * C_DIM];
__device__ __half g_Wp_l[PSTR * C_DIM];
__device__ __half g_Wc_h[C_DIM * C_DIM];
__device__ __half g_Wc_l[C_DIM * C_DIM];

__device__ __forceinline__ float neg_inf() { return __int_as_float(0xff800000); }
__device__ __forceinline__ float log_sigmoid_f(float x) {
    return fminf(x, 0.f) - log1pf(expf(-fabsf(x)));
}
__device__ __forceinline__ uint32_t cvta_smem(const void* p) {
    uint32_t a;
    asm("{ .reg .u64 t; cvta.to.shared.u64 t, %1; cvt.u32.u64 %0, t; }" : "=r"(a) : "l"(p));
    return a;
}
__device__ __forceinline__ uint32_t pack2bf(float a, float b) {
    __nv_bfloat162 t = __floats2bfloat162_rn(a, b);
    return *reinterpret_cast<uint32_t*>(&t);
}
__device__ __forceinline__ uint32_t pack2h(float a, float b) {
    __half2 t = __floats2half2_rn(a, b);
    return *reinterpret_cast<uint32_t*>(&t);
}
__device__ __forceinline__ void ldsm4(uint32_t* r, uint32_t addr) {
    asm volatile("ldmatrix.sync.aligned.m8n8.x4.shared.b16 {%0,%1,%2,%3}, [%4];"
                 : "=r"(r[0]), "=r"(r[1]), "=r"(r[2]), "=r"(r[3]) : "r"(addr));
}
__device__ __forceinline__ void ldsm4t(uint32_t* r, uint32_t addr) {
    asm volatile("ldmatrix.sync.aligned.m8n8.x4.trans.shared.b16 {%0,%1,%2,%3}, [%4];"
                 : "=r"(r[0]), "=r"(r[1]), "=r"(r[2]), "=r"(r[3]) : "r"(addr));
}
__device__ __forceinline__ void mma_bf16(float* c, const uint32_t* a, const uint32_t* b) {
    asm volatile(
        "mma.sync.aligned.m16n8k16.row.col.f32.bf16.bf16.f32 "
        "{%0,%1,%2,%3}, {%4,%5,%6,%7}, {%8,%9}, {%0,%1,%2,%3};"
        : "+f"(c[0]), "+f"(c[1]), "+f"(c[2]), "+f"(c[3])
        : "r"(a[0]), "r"(a[1]), "r"(a[2]), "r"(a[3]), "r"(b[0]), "r"(b[1]));
}
__device__ __forceinline__ void mma_fp16(float* c, const uint32_t* a, const uint32_t* b) {
    asm volatile(
        "mma.sync.aligned.m16n8k16.row.col.f32.f16.f16.f32 "
        "{%0,%1,%2,%3}, {%4,%5,%6,%7}, {%8,%9}, {%0,%1,%2,%3};"
        : "+f"(c[0]), "+f"(c[1]), "+f"(c[2]), "+f"(c[3])
        : "r"(a[0]), "r"(a[1]), "r"(a[2]), "r"(a[3]), "r"(b[0]), "r"(b[1]));
}
__device__ __forceinline__ void cpasync16(uint32_t dst, const void* src) {
    asm volatile("cp.async.cg.shared.global [%0], [%1], 16;" :: "r"(dst), "l"(src) : "memory");
}
#define CP_COMMIT() asm volatile("cp.async.commit_group;" ::: "memory")
#define CP_WAIT(n)  asm volatile("cp.async.wait_group %0;" :: "n"(n) : "memory")

// swizzled offset within a 128x16 (16-bit elem) tile (4KB)
__device__ __forceinline__ uint32_t phys16(int row, int c) {
    return (uint32_t)((row >> 2) * 128 + (((((row & 3) * 2) + c) ^ ((row >> 2) & 1)) * 16));
}

// cp.async a 64x64 bf16 tile pair (hi/lo) from pre-split global into swizzled smem.
__device__ __forceinline__ void cp_tile(
    const __nv_bfloat16* __restrict__ gh, const __nv_bfloat16* __restrict__ gl,
    uint32_t smH, uint32_t smL, int tid)
{
#pragma unroll
    for (int i = 0; i < 2; i++) {
        int f = tid + i * 256;           // chunk id 0..511
        int r = f >> 3, c = f & 7;
        uint32_t off = (uint32_t)r * 128u + (uint32_t)((c ^ (r & 7)) * 16);
        cpasync16(smH + off, gh + (size_t)r * QKV + c * 8);
        cpasync16(smL + off, gl + (size_t)r * QKV + c * 8);
    }
}

// ---------------- merged prepass: weight transpose + fp16 split + x split ----------------
__global__ __launch_bounds__(256) void prepass_all(
    const float* __restrict__ Wq, const float* __restrict__ Wk,
    const float* __restrict__ Wv, const float* __restrict__ Wc,
    const float* __restrict__ Wg, const float* __restrict__ rmsw,
    const float* __restrict__ x,
    __half* __restrict__ Wph, __half* __restrict__ Wpl,
    __half* __restrict__ Wch, __half* __restrict__ Wcl,
    __half* __restrict__ Xh, __half* __restrict__ Xl)
{
    int z = blockIdx.z;
    if (z == 5) {
        int blk = blockIdx.y * 32 + blockIdx.x;
        int tid = threadIdx.x;
#pragma unroll
        for (int rr = 0; rr < 2; rr++) {
            int t = blk * 2 + rr;
            float4 v = *reinterpret_cast<const float4*>(x + (size_t)t * C_DIM + tid * 4);
            float h0 = __half2float(__float2half_rn(v.x));
            float h1 = __half2float(__float2half_rn(v.y));
            float h2 = __half2float(__float2half_rn(v.z));
            float h3 = __half2float(__float2half_rn(v.w));
            uint2 hh = make_uint2(pack2h(h0, h1), pack2h(h2, h3));
            uint2 ll = make_uint2(pack2h(v.x - h0, v.y - h1), pack2h(v.z - h2, v.w - h3));
            *reinterpret_cast<uint2*>(Xh + (size_t)t * C_DIM + tid * 4) = hh;
            *reinterpret_cast<uint2*>(Xl + (size_t)t * C_DIM + tid * 4) = ll;
        }
        return;
    }
    const float* W; __half *Th, *Tl; int N, rowOff = 0; bool useScale = false;
    if (z == 0)      { W = Wq; Th = Wph; Tl = Wpl; N = 1024; }
    else if (z == 1) { W = Wk; Th = Wph; Tl = Wpl; N = 256; rowOff = KOFF; }
    else if (z == 2) { W = Wv; Th = Wph; Tl = Wpl; N = 256; rowOff = VOFF; }
    else if (z == 3) { W = Wc; Th = Wch; Tl = Wcl; N = 1024; useScale = true; }
    else             { W = Wg; Th = Wph; Tl = Wpl; N = 16;  rowOff = GOFF; }
    int n0 = blockIdx.x * 32;
    if (n0 >= N) return;
    int k0 = blockIdx.y * 32;

    __shared__ float s[32][33];
    int tx = threadIdx.x & 31, ty = threadIdx.x >> 5;
#pragma unroll
    for (int i = 0; i < 4; i++) {
        int r = ty + i * 8;
        if (n0 + tx < N) {
            float v = W[(size_t)(k0 + r) * N + n0 + tx];
            if (useScale) v *= rmsw[k0 + r];
            s[r][tx] = v;
        }
    }
    __syncthreads();
#pragma unroll
    for (int i = 0; i < 4; i++) {
        int r = ty + i * 8;
        if (n0 + r < N) {
            float v = s[tx][r];
            __half h = __float2half_rn(v);
            Th[(size_t)(rowOff + n0 + r) * C_DIM + k0 + tx] = h;
            Tl[(size_t)(rowOff + n0 + r) * C_DIM + k0 + tx] = __float2half_rn(v - __half2float(h));
        }
    }
}

// ---------------- Y -> fp16 with fused RMSNorm row scale ----------------
__global__ __launch_bounds__(256) void norm_to_fp16(
    const float* __restrict__ X, __half* __restrict__ Ah)
{
    int t = blockIdx.x, tid = threadIdx.x;
    float4 v = *reinterpret_cast<const float4*>(X + (size_t)t * C_DIM + tid * 4);
    float ss = v.x * v.x + v.y * v.y + v.z * v.z + v.w * v.w;
#pragma unroll
    for (int off = 16; off; off >>= 1) ss += __shfl_xor_sync(0xffffffff, ss, off);
    __shared__ float red[8];
    if ((tid & 31) == 0) red[tid >> 5] = ss;
    __syncthreads();
    float s = red[0];
#pragma unroll
    for (int i = 1; i < 8; i++) s += red[i];
    float scale = rsqrtf(s * (1.f / (float)C_DIM) + 1e-5f);
    uint2 hh = make_uint2(pack2h(v.x * scale, v.y * scale), pack2h(v.z * scale, v.w * scale));
    *reinterpret_cast<uint2*>(Ah + (size_t)t * C_DIM + tid * 4) = hh;
}

// ---------------- proj GEMM: fp16 A x (Bh+Bl) 2-term; gate block adds al*bh ----------------
__global__ __launch_bounds__(256, 2) void gemm_proj_f16(
    const __half* __restrict__ Ah, const __half* __restrict__ Al,
    const __half* __restrict__ Bh, const __half* __restrict__ Bl,
    float* __restrict__ G, __nv_bfloat16* __restrict__ Ph,
    __nv_bfloat16* __restrict__ Pl, int M, int N, int K)
{
    extern __shared__ char smc[];
    uint32_t sb = cvta_smem(smc);
    const uint32_t STG = 16384u;

    int tid = threadIdx.x, lane = tid & 31, warp = tid >> 5;
    int wm = warp & 3, wn = warp >> 2;
    int m0 = blockIdx.y * 128, n0 = blockIdx.x * 128;
    bool prec = ((int)blockIdx.x == GATE_BLK);

    int lrow = tid >> 1, lc = tid & 1;
    uint32_t ldst = phys16(lrow, lc);
    const __half* gA  = Ah + (size_t)(m0 + lrow) * K + lc * 8;
    const __half* gAl = Al + (size_t)(m0 + lrow) * K + lc * 8;
    const __half* gBh = Bh + (size_t)(n0 + lrow) * K + lc * 8;
    const __half* gBl = Bl + (size_t)(n0 + lrow) * K + lc * 8;

    int nkt = K / 16;
    float acc[2][8][4] = {};

#pragma unroll
    for (int p = 0; p < 2; p++) {
        uint32_t st = sb + (uint32_t)p * STG;
        cpasync16(st + ldst,          gA + p * 16);
        cpasync16(st + 4096u + ldst,  gBh + p * 16);
        cpasync16(st + 8192u + ldst,  gBl + p * 16);
        if (prec) cpasync16(st + 12288u + ldst, gAl + p * 16);
        CP_COMMIT();
    }

    int aRow = (lane & 15), aC = lane >> 4;
    int bRowBase = (lane & 7) + ((lane >> 4) << 3);
    int bC = (lane >> 3) & 1;

    for (int kt = 0; kt < nkt; ++kt) {
        if (kt + 2 < nkt) { CP_WAIT(1); } else { CP_WAIT(0); }
        __syncthreads();

        uint32_t st = sb + (uint32_t)(kt % 3) * STG;
        uint32_t ah[2][4], al[2][4];
#pragma unroll
        for (int t = 0; t < 2; t++) {
            int r = wm * 32 + t * 16 + aRow;
            ldsm4(ah[t], st + phys16(r, aC));
        }
        if (prec) {
#pragma unroll
            for (int t = 0; t < 2; t++) {
                int r = wm * 32 + t * 16 + aRow;
                ldsm4(al[t], st + 12288u + phys16(r, aC));
            }
        }
#pragma unroll
        for (int g = 0; g < 4; g++) {
            int r = wn * 64 + g * 16 + bRowBase;
            uint32_t bh[4], bl[4];
            ldsm4(bh, st + 4096u + phys16(r, bC));
            ldsm4(bl, st + 8192u + phys16(r, bC));
#pragma unroll
            for (int t = 0; t < 2; t++)
#pragma unroll
                for (int jj = 0; jj < 2; jj++) {
                    int j = g * 2 + jj;
                    mma_fp16(acc[t][j], ah[t], &bh[2 * jj]);
                    mma_fp16(acc[t][j], ah[t], &bl[2 * jj]);
                }
            if (prec) {
#pragma unroll
                for (int t = 0; t < 2; t++)
#pragma unroll
                    for (int jj = 0; jj < 2; jj++)
                        mma_fp16(acc[t][g * 2 + jj], al[t], &bh[2 * jj]);
            }
        }

        if (kt + 2 < nkt) {
            uint32_t st2 = sb + (uint32_t)((kt + 2) % 3) * STG;
            int ko = (kt + 2) * 16;
            cpasync16(st2 + ldst,          gA + ko);
            cpasync16(st2 + 4096u + ldst,  gBh + ko);
            cpasync16(st2 + 8192u + ldst,  gBl + ko);
            if (prec) cpasync16(st2 + 12288u + ldst, gAl + ko);
            CP_COMMIT();
        }
    }

    // RoPE epilogue (Q,K head columns only)
    if ((n0 + wn * 64) < 1280) {
#pragma unroll
        for (int j = 0; j < 4; j++) {
#pragma unroll
            for (int e = 0; e < 2; e++) {
                int d = j * 8 + 2 * (lane & 3) + e;
                float invf = expf(-(float)(2 * d) * (9.210340371976184f / 64.f));
#pragma unroll
                for (int mt = 0; mt < 2; mt++) {
#pragma unroll
                    for (int rh = 0; rh < 2; rh++) {
                        int trow = m0 + wm * 32 + mt * 16 + (lane >> 2) + rh * 8;
                        float sn, cs;
                        sincosf((float)trow * invf, &sn, &cs);
                        int k = 2 * rh + e;
                        float a = acc[mt][j][k], b = acc[mt][j + 4][k];
                        acc[mt][j][k]     = a * cs - b * sn;
                        acc[mt][j + 4][k] = b * cs + a * sn;
                    }
                }
            }
        }
    }

    if (!prec) {
#pragma unroll
        for (int t = 0; t < 2; t++) {
            int r0 = m0 + wm * 32 + t * 16 + (lane >> 2);
#pragma unroll
            for (int j = 0; j < 8; j++) {
                int col = n0 + wn * 64 + j * 8 + 2 * (lane & 3);
                float v0 = acc[t][j][0], v1 = acc[t][j][1];
                float v2 = acc[t][j][2], v3 = acc[t][j][3];
                float h0 = __bfloat162float(__float2bfloat16_rn(v0));
                float h1 = __bfloat162float(__float2bfloat16_rn(v1));
                float h2 = __bfloat162float(__float2bfloat16_rn(v2));
                float h3 = __bfloat162float(__float2bfloat16_rn(v3));
                *reinterpret_cast<uint32_t*>(Ph + (size_t)r0 * QKV + col) = pack2bf(h0, h1);
                *reinterpret_cast<uint32_t*>(Pl + (size_t)r0 * QKV + col) = pack2bf(v0 - h0, v1 - h1);
                *reinterpret_cast<uint32_t*>(Ph + (size_t)(r0 + 8) * QKV + col) = pack2bf(h2, h3);
                *reinterpret_cast<uint32_t*>(Pl + (size_t)(r0 + 8) * QKV + col) = pack2bf(v2 - h2, v3 - h3);
            }
        }
    } else {
        if (wn == 0) {
#pragma unroll
            for (int t = 0; t < 2; t++) {
                int r0 = m0 + wm * 32 + t * 16 + (lane >> 2);
#pragma unroll
                for (int j = 0; j < 2; j++) {
                    int colg = j * 8 + 2 * (lane & 3);
                    G[(size_t)colg * T_SEQ + r0] = acc[t][j][0];
                    G[(size_t)(colg + 1) * T_SEQ + r0] = acc[t][j][1];
                    G[(size_t)colg * T_SEQ + r0 + 8] = acc[t][j][2];
                    G[(size_t)(colg + 1) * T_SEQ + r0 + 8] = acc[t][j][3];
                }
            }
        }
    }
}

// ---------------- out GEMM: fp16 A (single) x (Bh+Bl), 2-term ----------------
__global__ __launch_bounds__(256, 2) void gemm_out_f16(
    const __half* __restrict__ Ah, const __half* __restrict__ Bh,
    const __half* __restrict__ Bl, float* __restrict__ C,
    int M, int N, int K)
{
    extern __shared__ char smc[];
    uint32_t sb = cvta_smem(smc);
    const uint32_t STG = 12288u;

    int tid = threadIdx.x, lane = tid & 31, warp = tid >> 5;
    int wm = warp & 3, wn = warp >> 2;
    int m0 = blockIdx.y * 128, n0 = blockIdx.x * 128;

    int lrow = tid >> 1, lc = tid & 1;
    uint32_t ldst = phys16(lrow, lc);
    const __half* gA = Ah + (size_t)(m0 + lrow) * K + lc * 8;
    const __half* gBh = Bh + (size_t)(n0 + lrow) * K + lc * 8;
    const __half* gBl = Bl + (size_t)(n0 + lrow) * K + lc * 8;

    int nkt = K / 16;
    float acc[2][8][4] = {};

#pragma unroll
    for (int p = 0; p < 2; p++) {
        uint32_t st = sb + (uint32_t)p * STG;
        cpasync16(st + ldst,          gA + p * 16);
        cpasync16(st + 4096u + ldst,  gBh + p * 16);
        cpasync16(st + 8192u + ldst,  gBl + p * 16);
        CP_COMMIT();
    }

    int aRow = (lane & 15), aC = lane >> 4;
    int bRowBase = (lane & 7) + ((lane >> 4) << 3);
    int bC = (lane >> 3) & 1;

    for (int kt = 0; kt < nkt; ++kt) {
        if (kt + 2 < nkt) { CP_WAIT(1); } else { CP_WAIT(0); }
        __syncthreads();

        uint32_t st = sb + (uint32_t)(kt % 3) * STG;
        uint32_t ah[2][4];
#pragma unroll
        for (int t = 0; t < 2; t++) {
            int r = wm * 32 + t * 16 + aRow;
            ldsm4(ah[t], st + phys16(r, aC));
        }
#pragma unroll
        for (int g = 0; g < 4; g++) {
            int r = wn * 64 + g * 16 + bRowBase;
            uint32_t bh[4], bl[4];
            ldsm4(bh, st + 4096u + phys16(r, bC));
            ldsm4(bl, st + 8192u + phys16(r, bC));
#pragma unroll
            for (int t = 0; t < 2; t++)
#pragma unroll
                for (int jj = 0; jj < 2; jj++) {
                    int j = g * 2 + jj;
                    mma_fp16(acc[t][j], ah[t], &bh[2 * jj]);
                    mma_fp16(acc[t][j], ah[t], &bl[2 * jj]);
                }
        }

        if (kt + 2 < nkt) {
            uint32_t st2 = sb + (uint32_t)((kt + 2) % 3) * STG;
            int ko = (kt + 2) * 16;
            cpasync16(st2 + ldst,          gA + ko);
            cpasync16(st2 + 4096u + ldst,  gBh + ko);
            cpasync16(st2 + 8192u + ldst,  gBl + ko);
            CP_COMMIT();
        }
    }

#pragma unroll
    for (int t = 0; t < 2; t++) {
        int r0 = m0 + wm * 32 + t * 16 + (lane >> 2);
#pragma unroll
        for (int j = 0; j < 8; j++) {
            int col = n0 + wn * 64 + j * 8 + 2 * (lane & 3);
            *reinterpret_cast<float2*>(C + (size_t)r0 * N + col) = make_float2(acc[t][j][0], acc[t][j][1]);
            *reinterpret_cast<float2*>(C + (size_t)(r0 + 8) * N + col) = make_float2(acc[t][j][2], acc[t][j][3]);
        }
    }
}

// ---------------- per-head scan (warp-shuffle, coalesced G reads) ----------------
__global__ __launch_bounds__(256) void scan_kernel(
    const float* __restrict__ G, const float* __restrict__ bg,
    float* __restrict__ D, float* __restrict__ L)
{
    int h = blockIdx.x, tid = threadIdx.x, lane = tid & 31, wid = tid >> 5;
    float b = bg[h];
    float4 a0 = *reinterpret_cast<const float4*>(G + (size_t)h * T_SEQ + tid * 8);
    float4 a1 = *reinterpret_cast<const float4*>(G + (size_t)h * T_SEQ + tid * 8 + 4);
    float gv[8] = {a0.x, a0.y, a0.z, a0.w, a1.x, a1.y, a1.z, a1.w};
    float vals[8];
    float run = 0.f;
#pragma unroll
    for (int i = 0; i < 8; i++) {
        float gg = gv[i] + b;
        run += log_sigmoid_f(gg);
        vals[i] = run;
        L[h * T_SEQ + tid * 8 + i] = log_sigmoid_f(-gg);
    }
    float x = run;
#pragma unroll
    for (int off = 1; off < 32; off <<= 1) {
        float y = __shfl_up_sync(0xffffffff, x, off);
        if (lane >= off) x += y;
    }
    __shared__ float wsum[8];
    if (lane == 31) wsum[wid] = x;
    __syncthreads();
    float woff = 0.f;
#pragma unroll
    for (int w = 0; w < 8; w++) if (w < wid) woff += wsum[w];
    float excl = x - run + woff;
#pragma unroll
    for (int i = 0; i < 8; i++) D[h * T_SEQ + tid * 8 + i] = vals[i] + excl;
}

// ---------------- fused attention (register-P, bf16x3, cp.async tiles) ----------------
#define OFF_Q  0u
#define OFF_K  16384u
#define OFF_V  32768u
#define OFF_S  49152u
#define SSTR   132
#define OFF_SC (49152u + 64u * SSTR * 4u)

__device__ __forceinline__ void pv_mma(
    uint32_t sbV, uint32_t pah[2][4], uint32_t pal[2][4],
    float (*oacc)[4], int wn, int lane)
{
#pragma unroll
    for (int u = 0; u < 2; u++) {
        int vrow = wn * 32 + u * 16 + (lane & 15);
        uint32_t vb = sbV + (uint32_t)vrow * 128u;
#pragma unroll
        for (int gg = 0; gg < 4; gg++) {
            int cch = 2 * gg + (lane >> 4);
            uint32_t vh[4], vl[4];
            ldsm4t(vh, vb + (uint32_t)((cch ^ (vrow & 7)) * 16));
            ldsm4t(vl, vb + 8192u + (uint32_t)((cch ^ (vrow & 7)) * 16));
#pragma unroll
            for (int jj = 0; jj < 2; jj++) {
                int j = gg * 2 + jj;
                mma_bf16(oacc[j], pah[u], &vh[2 * jj]);
                mma_bf16(oacc[j], pah[u], &vl[2 * jj]);
                mma_bf16(oacc[j], pal[u], &vh[2 * jj]);
            }
        }
    }
}

__global__ __launch_bounds__(256, 2) void attn_fused(
    const __nv_bfloat16* __restrict__ Ph, const __nv_bfloat16* __restrict__ Pl,
    const float* __restrict__ D, const float* __restrict__ L,
    float* __restrict__ Y)
{
    extern __shared__ char smc[];
    uint32_t sb = cvta_smem(smc);
    float* smS  = reinterpret_cast<float*>(smc + OFF_S);
    float* Dq   = reinterpret_cast<float*>(smc + OFF_SC);
    float* rowE = Dq + 64;
    float* Ds   = rowE + 64;
    float* Ls   = Ds + 64;
    float* colE = Ls + 64;

    int qt = blockIdx.x, h = blockIdx.y;
    int kvh = h >> 2;
    int tid = threadIdx.x, lane = tid & 31, warp = tid >> 5;
    int wm = warp & 3, wn = warp >> 2;
    int t0 = qt * 64;
    int w0 = (t0 / WINSZ) * WINSZ;
    int wt0 = w0 / 64;
    int nk = t0 - w0 + 64;

    cp_tile(Ph + (size_t)t0 * QKV + h * DHD, Pl + (size_t)t0 * QKV + h * DHD,
            sb + OFF_Q, sb + OFF_Q + 8192u, tid);
    CP_COMMIT();
    if (tid < 64) Dq[tid] = D[h * T_SEQ + t0 + tid];
    CP_WAIT(0);
    __syncthreads();
    float dq0 = Dq[0];
    if (tid < 64) rowE[tid] = expf(Dq[tid] - dq0);

    int fr0 = wm * 16 + (lane >> 2);
    int fcb = wn * 32 + 2 * (lane & 3);

    float oacc[8][4] = {};

    for (int st = qt; st >= 0; --st) {
        int s0 = st * 64;
        bool inwin = (st >= wt0);
        if (!inwin) {
            float dend = D[h * T_SEQ + s0 + 63];
            if (dq0 - dend < DECAY_CUTOFF) break;
        }
        __syncthreads();

        cp_tile(Ph + (size_t)s0 * QKV + KOFF + kvh * DHD, Pl + (size_t)s0 * QKV + KOFF + kvh * DHD,
                sb + OFF_K, sb + OFF_K + 8192u, tid);
        cp_tile(Ph + (size_t)s0 * QKV + VOFF + kvh * DHD, Pl + (size_t)s0 * QKV + VOFF + kvh * DHD,
                sb + OFF_V, sb + OFF_V + 8192u, tid);
        CP_COMMIT();
        if (tid < 64) {
            float ds = D[h * T_SEQ + s0 + tid];
            float ls = L[h * T_SEQ + s0 + tid];
            Ds[tid] = ds; Ls[tid] = ls;
            colE[tid] = expf(dq0 - ds + ls);
        }
        CP_WAIT(0);
        __syncthreads();

        float sacc[4][4] = {};
        {
            int arow = wm * 16 + (lane & 15);
            int asel = lane >> 4;
            int nrow = wn * 32 + (lane & 7) + ((lane >> 4) << 3);
            int bsel = (lane >> 3) & 1;
#pragma unroll
            for (int ks = 0; ks < 4; ks++) {
                uint32_t ah[4], al[4];
                uint32_t abase = sb + OFF_Q + (uint32_t)arow * 128u;
                ldsm4(ah, abase + (uint32_t)(((2 * ks + asel) ^ (arow & 7)) * 16));
                ldsm4(al, abase + 8192u + (uint32_t)(((2 * ks + asel) ^ (arow & 7)) * 16));
                uint32_t bh[2][4], bl[2][4];
#pragma unroll
                for (int g = 0; g < 2; g++) {
                    int r = nrow + g * 16;
                    uint32_t bbase = sb + OFF_K + (uint32_t)r * 128u;
                    ldsm4(bh[g], bbase + (uint32_t)(((2 * ks + bsel) ^ (r & 7)) * 16));
                    ldsm4(bl[g], bbase + 8192u + (uint32_t)(((2 * ks + bsel) ^ (r & 7)) * 16));
                }
#pragma unroll
                for (int j = 0; j < 4; j++) {
                    const uint32_t* b2h = &bh[j >> 1][2 * (j & 1)];
                    const uint32_t* b2l = &bl[j >> 1][2 * (j & 1)];
                    mma_bf16(sacc[j], ah, b2h);
                    mma_bf16(sacc[j], ah, b2l);
                    mma_bf16(sacc[j], al, b2h);
                }
            }
        }

        uint32_t pah[2][4], pal[2][4];
        {
            int colbase = s0 - w0;
#pragma unroll
            for (int j = 0; j < 4; j++) {
                int cj = fcb + 8 * j;
#pragma unroll
                for (int half = 0; half < 2; half++) {
                    int r = fr0 + half * 8;
                    float v0 = sacc[j][2 * half], v1 = sacc[j][2 * half + 1];
                    if (inwin) {
                        float l0 = (s0 + cj     <= t0 + r) ? v0 * 0.125f : neg_inf();
                        float l1 = (s0 + cj + 1 <= t0 + r) ? v1 * 0.125f : neg_inf();
                        *reinterpret_cast<float2*>(&smS[r * SSTR + colbase + cj]) = make_float2(l0, l1);
                    }
                    float p0, p1;
                    if (st == qt) {
                        p0 = (cj     <= r) ? v0 * expf(Dq[r] - Ds[cj] + Ls[cj]) : 0.f;
                        p1 = (cj + 1 <= r) ? v1 * expf(Dq[r] - Ds[cj + 1] + Ls[cj + 1]) : 0.f;
                    } else {
                        float re = rowE[r];
                        p0 = v0 * (re * colE[cj]);
                        p1 = v1 * (re * colE[cj + 1]);
                    }
                    float h0 = __bfloat162float(__float2bfloat16_rn(p0));
                    float h1 = __bfloat162float(__float2bfloat16_rn(p1));
                    int u = j >> 1, ri = (j & 1) * 2 + half;
                    pah[u][ri] = pack2bf(h0, h1);
                    pal[u][ri] = pack2bf(p0 - h0, p1 - h1);
                }
            }
        }

        pv_mma(sb + OFF_V, pah, pal, oacc, wn, lane);
    }

    __syncthreads();
    {
        int r = tid >> 2, g = tid & 3;
        float m = neg_inf();
        for (int c = g; c < nk; c += 4) m = fmaxf(m, smS[r * SSTR + c]);
        m = fmaxf(m, __shfl_xor_sync(0xffffffff, m, 1));
        m = fmaxf(m, __shfl_xor_sync(0xffffffff, m, 2));
        float sum = 0.f;
        for (int c = g; c < nk; c += 4) {
            float e = expf(smS[r * SSTR + c] - m);
            smS[r * SSTR + c] = e;
            sum += e;
        }
        sum += __shfl_xor_sync(0xffffffff, sum, 1);
        sum += __shfl_xor_sync(0xffffffff, sum, 2);
        float inv = 1.f / sum;
        for (int c = g; c < nk; c += 4) smS[r * SSTR + c] *= inv;
    }

    for (int kh = 0; kh < (nk >> 6); kh++) {
        __syncthreads();
        cp_tile(Ph + (size_t)(w0 + kh * 64) * QKV + VOFF + kvh * DHD,
                Pl + (size_t)(w0 + kh * 64) * QKV + VOFF + kvh * DHD,
                sb + OFF_V, sb + OFF_V + 8192u, tid);
        CP_COMMIT();
        CP_WAIT(0);
        __syncthreads();
        uint32_t pah[2][4], pal[2][4];
#pragma unroll
        for (int u = 0; u < 2; u++) {
            int bc = kh * 64 + wn * 32 + u * 16 + 2 * (lane & 3);
            float2 f0 = *reinterpret_cast<const float2*>(&smS[fr0 * SSTR + bc]);
            float2 f1 = *reinterpret_cast<const float2*>(&smS[(fr0 + 8) * SSTR + bc]);
            float2 f2 = *reinterpret_cast<const float2*>(&smS[fr0 * SSTR + bc + 8]);
            float2 f3 = *reinterpret_cast<const float2*>(&smS[(fr0 + 8) * SSTR + bc + 8]);
            float h, h2;
            h = __bfloat162float(__float2bfloat16_rn(f0.x));
            h2 = __bfloat162float(__float2bfloat16_rn(f0.y));
            pah[u][0] = pack2bf(h, h2); pal[u][0] = pack2bf(f0.x - h, f0.y - h2);
            h = __bfloat162float(__float2bfloat16_rn(f1.x));
            h2 = __bfloat162float(__float2bfloat16_rn(f1.y));
            pah[u][1] = pack2bf(h, h2); pal[u][1] = pack2bf(f1.x - h, f1.y - h2);
            h = __bfloat162float(__float2bfloat16_rn(f2.x));
            h2 = __bfloat162float(__float2bfloat16_rn(f2.y));
            pah[u][2] = pack2bf(h, h2); pal[u][2] = pack2bf(f2.x - h, f2.y - h2);
            h = __bfloat162float(__float2bfloat16_rn(f3.x));
            h2 = __bfloat162float(__float2bfloat16_rn(f3.y));
            pah[u][3] = pack2bf(h, h2); pal[u][3] = pack2bf(f3.x - h, f3.y - h2);
        }
        pv_mma(sb + OFF_V, pah, pal, oacc, wn, lane);
    }

    __syncthreads();
    float* redb = reinterpret_cast<float*>(smc + OFF_K);
    if (wn == 1) {
        int base = (wm * 32 + lane) * 32;
#pragma unroll
        for (int j = 0; j < 8; j++)
#pragma unroll
            for (int k = 0; k < 4; k++) redb[base + j * 4 + k] = oacc[j][k];
    }
    __syncthreads();
    if (wn == 0) {
        int base = (wm * 32 + lane) * 32;
#pragma unroll
        for (int j = 0; j < 8; j++) {
            float o0 = oacc[j][0] + redb[base + j * 4 + 0];
            float o1 = oacc[j][1] + redb[base + j * 4 + 1];
            float o2 = oacc[j][2] + redb[base + j * 4 + 2];
            float o3 = oacc[j][3] + redb[base + j * 4 + 3];
            int col = h * DHD + j * 8 + 2 * (lane & 3);
            *reinterpret_cast<float2*>(Y + (size_t)(t0 + fr0) * C_DIM + col) = make_float2(o0, o1);
            *reinterpret_cast<float2*>(Y + (size_t)(t0 + fr0 + 8) * C_DIM + col) = make_float2(o2, o3);
        }
    }
}

// ---------------- launch ----------------
extern "C" void kernel_launch(void* const* d_in, const int* in_sizes, int n_in,
                              void* d_out, int out_size)
{
    (void)in_sizes; (void)n_in; (void)out_size;
    const float* x    = (const float*)d_in[0];
    const float* Wq   = (const float*)d_in[1];
    const float* Wk   = (const float*)d_in[2];
    const float* Wv   = (const float*)d_in[3];
    const float* Wc   = (const float*)d_in[4];
    const float* Wg   = (const float*)d_in[5];
    const float* bg   = (const float*)d_in[6];
    const float* rmsw = (const float*)d_in[7];
    float* out = (float*)d_out;

    float *G, *D, *L, *Y;
    __nv_bfloat16 *Ph, *Pl;
    __half *Xh, *Xl, *Yh, *Wph, *Wpl, *Wch, *Wcl;
    cudaGetSymbolAddress((void**)&G, g_G);
    cudaGetSymbolAddress((void**)&Ph, g_Ph);
    cudaGetSymbolAddress((void**)&Pl, g_Pl);
    cudaGetSymbolAddress((void**)&D, g_D);
    cudaGetSymbolAddress((void**)&L, g_L);
    cudaGetSymbolAddress((void**)&Y, g_Y);
    cudaGetSymbolAddress((void**)&Xh, g_Xh);
    cudaGetSymbolAddress((void**)&Xl, g_Xl);
    cudaGetSymbolAddress((void**)&Yh, g_Yh);
    cudaGetSymbolAddress((void**)&Wph, g_Wp_h);
    cudaGetSymbolAddress((void**)&Wpl, g_Wp_l);
    cudaGetSymbolAddress((void**)&Wch, g_Wc_h);
    cudaGetSymbolAddress((void**)&Wcl, g_Wc_l);

    prepass_all<<<dim3(32, 32, 6), 256>>>(Wq, Wk, Wv, Wc, Wg, rmsw, x,
                                          Wph, Wpl, Wch, Wcl, Xh, Xl);

    size_t smemP = 3 * 16384;
    cudaFuncSetAttribute(gemm_proj_f16, cudaFuncAttributeMaxDynamicSharedMemorySize, (int)smemP);
    gemm_proj_f16<<<dim3(PSTR / 128, T_SEQ / 128), 256, smemP>>>(Xh, Xl, Wph, Wpl, G, Ph, Pl, T_SEQ, PSTR, C_DIM);

    scan_kernel<<<NH, 256>>>(G, bg, D, L);

    size_t smemA = OFF_SC + 6 * 64 * sizeof(float);
    cudaFuncSetAttribute(attn_fused, cudaFuncAttributeMaxDynamicSharedMemorySize, (int)smemA);
    attn_fused<<<dim3(T_SEQ / 64, NH), 256, smemA>>>(Ph, Pl, D, L, Y);

    norm_to_fp16<<<T_SEQ, 256>>>(Y, Yh);

    size_t smemO = 3 * 12288;
    cudaFuncSetAttribute(gemm_out_f16, cudaFuncAttributeMaxDynamicSharedMemorySize, (int)smemO);
    gemm_out_f16<<<dim3(C_DIM / 128, T_SEQ / 128), 256, smemO>>>(Yh, Wch, Wcl, out, T_SEQ, C_DIM, C_DIM);
}

// round 17
// speedup vs baseline: 1.3393x; 1.0581x over previous
#include <cuda_runtime.h>
#include <cuda_bf16.h>
#include <cuda_fp16.h>
#include <math.h>
#include <stdint.h>

#define T_SEQ 2048
#define C_DIM 1024
#define NH    16
#define NKV   4
#define DHD   64
#define WINSZ 128
#define PSTR  1664          /* proj weight rows (gate at GOFF, pad above) */
#define QKV   1536          /* split bf16 P stride: Q(1024)|K(256)|V(256) */
#define KOFF  1024
#define VOFF  1280
#define GOFF  1536
#define GATE_BLK 24         /* 64-col block holding gate cols 1536..1551 */
#define DECAY_CUTOFF (-25.f)

// ---------------- scratch ----------------
__device__ __nv_bfloat16 g_Ph[T_SEQ * QKV];
__device__ __nv_bfloat16 g_Pl[T_SEQ * QKV];
__device__ float g_G[NH * T_SEQ];                   // gate logits, [h][t]
__device__ float g_D[NH * T_SEQ];
__device__ float g_L[NH * T_SEQ];
__device__ float g_Y[T_SEQ * C_DIM];
__device__ __half g_Xh[T_SEQ * C_DIM];
__device__ __half g_Xl[T_SEQ * C_DIM];
__device__ __half g_Yh[T_SEQ * C_DIM];
__device__ __half g_Wp_h[PSTR * C_DIM];
__device__ __half g_Wp_l[PSTR * C_DIM];
__device__ __half g_Wc_h[C_DIM * C_DIM];
__device__ __half g_Wc_l[C_DIM * C_DIM];

__device__ __forceinline__ float neg_inf() { return __int_as_float(0xff800000); }
__device__ __forceinline__ float log_sigmoid_f(float x) {
    return fminf(x, 0.f) - log1pf(expf(-fabsf(x)));
}
__device__ __forceinline__ uint32_t cvta_smem(const void* p) {
    uint32_t a;
    asm("{ .reg .u64 t; cvta.to.shared.u64 t, %1; cvt.u32.u64 %0, t; }" : "=r"(a) : "l"(p));
    return a;
}
__device__ __forceinline__ uint32_t pack2bf(float a, float b) {
    __nv_bfloat162 t = __floats2bfloat162_rn(a, b);
    return *reinterpret_cast<uint32_t*>(&t);
}
__device__ __forceinline__ uint32_t pack2h(float a, float b) {
    __half2 t = __floats2half2_rn(a, b);
    return *reinterpret_cast<uint32_t*>(&t);
}
__device__ __forceinline__ void ldsm4(uint32_t* r, uint32_t addr) {
    asm volatile("ldmatrix.sync.aligned.m8n8.x4.shared.b16 {%0,%1,%2,%3}, [%4];"
                 : "=r"(r[0]), "=r"(r[1]), "=r"(r[2]), "=r"(r[3]) : "r"(addr));
}
__device__ __forceinline__ void ldsm4t(uint32_t* r, uint32_t addr) {
    asm volatile("ldmatrix.sync.aligned.m8n8.x4.trans.shared.b16 {%0,%1,%2,%3}, [%4];"
                 : "=r"(r[0]), "=r"(r[1]), "=r"(r[2]), "=r"(r[3]) : "r"(addr));
}
__device__ __forceinline__ void mma_bf16(float* c, const uint32_t* a, const uint32_t* b) {
    asm volatile(
        "mma.sync.aligned.m16n8k16.row.col.f32.bf16.bf16.f32 "
        "{%0,%1,%2,%3}, {%4,%5,%6,%7}, {%8,%9}, {%0,%1,%2,%3};"
        : "+f"(c[0]), "+f"(c[1]), "+f"(c[2]), "+f"(c[3])
        : "r"(a[0]), "r"(a[1]), "r"(a[2]), "r"(a[3]), "r"(b[0]), "r"(b[1]));
}
__device__ __forceinline__ void mma_fp16(float* c, const uint32_t* a, const uint32_t* b) {
    asm volatile(
        "mma.sync.aligned.m16n8k16.row.col.f32.f16.f16.f32 "
        "{%0,%1,%2,%3}, {%4,%5,%6,%7}, {%8,%9}, {%0,%1,%2,%3};"
        : "+f"(c[0]), "+f"(c[1]), "+f"(c[2]), "+f"(c[3])
        : "r"(a[0]), "r"(a[1]), "r"(a[2]), "r"(a[3]), "r"(b[0]), "r"(b[1]));
}
__device__ __forceinline__ void cpasync16(uint32_t dst, const void* src) {
    asm volatile("cp.async.cg.shared.global [%0], [%1], 16;" :: "r"(dst), "l"(src) : "memory");
}
#define CP_COMMIT() asm volatile("cp.async.commit_group;" ::: "memory")
#define CP_WAIT(n)  asm volatile("cp.async.wait_group %0;" :: "n"(n) : "memory")

// swizzled offset within a (rows x 16) 16-bit tile; rows<=128
__device__ __forceinline__ uint32_t phys16(int row, int c) {
    return (uint32_t)((row >> 2) * 128 + (((((row & 3) * 2) + c) ^ ((row >> 2) & 1)) * 16));
}

// cp.async a 64x64 bf16 tile pair (hi/lo) from pre-split global into swizzled smem.
__device__ __forceinline__ void cp_tile(
    const __nv_bfloat16* __restrict__ gh, const __nv_bfloat16* __restrict__ gl,
    uint32_t smH, uint32_t smL, int tid)
{
#pragma unroll
    for (int i = 0; i < 2; i++) {
        int f = tid + i * 256;
        int r = f >> 3, c = f & 7;
        uint32_t off = (uint32_t)r * 128u + (uint32_t)((c ^ (r & 7)) * 16);
        cpasync16(smH + off, gh + (size_t)r * QKV + c * 8);
        cpasync16(smL + off, gl + (size_t)r * QKV + c * 8);
    }
}

// ---------------- merged prepass: weight transpose + fp16 split + x split ----------------
__global__ __launch_bounds__(256) void prepass_all(
    const float* __restrict__ Wq, const float* __restrict__ Wk,
    const float* __restrict__ Wv, const float* __restrict__ Wc,
    const float* __restrict__ Wg, const float* __restrict__ rmsw,
    const float* __restrict__ x,
    __half* __restrict__ Wph, __half* __restrict__ Wpl,
    __half* __restrict__ Wch, __half* __restrict__ Wcl,
    __half* __restrict__ Xh, __half* __restrict__ Xl)
{
    int z = blockIdx.z;
    if (z == 5) {
        int blk = blockIdx.y * 32 + blockIdx.x;
        int tid = threadIdx.x;
#pragma unroll
        for (int rr = 0; rr < 2; rr++) {
            int t = blk * 2 + rr;
            float4 v = *reinterpret_cast<const float4*>(x + (size_t)t * C_DIM + tid * 4);
            float h0 = __half2float(__float2half_rn(v.x));
            float h1 = __half2float(__float2half_rn(v.y));
            float h2 = __half2float(__float2half_rn(v.z));
            float h3 = __half2float(__float2half_rn(v.w));
            uint2 hh = make_uint2(pack2h(h0, h1), pack2h(h2, h3));
            uint2 ll = make_uint2(pack2h(v.x - h0, v.y - h1), pack2h(v.z - h2, v.w - h3));
            *reinterpret_cast<uint2*>(Xh + (size_t)t * C_DIM + tid * 4) = hh;
            *reinterpret_cast<uint2*>(Xl + (size_t)t * C_DIM + tid * 4) = ll;
        }
        return;
    }
    const float* W; __half *Th, *Tl; int N, rowOff = 0; bool useScale = false;
    if (z == 0)      { W = Wq; Th = Wph; Tl = Wpl; N = 1024; }
    else if (z == 1) { W = Wk; Th = Wph; Tl = Wpl; N = 256; rowOff = KOFF; }
    else if (z == 2) { W = Wv; Th = Wph; Tl = Wpl; N = 256; rowOff = VOFF; }
    else if (z == 3) { W = Wc; Th = Wch; Tl = Wcl; N = 1024; useScale = true; }
    else             { W = Wg; Th = Wph; Tl = Wpl; N = 16;  rowOff = GOFF; }
    int n0 = blockIdx.x * 32;
    if (n0 >= N) return;
    int k0 = blockIdx.y * 32;

    __shared__ float s[32][33];
    int tx = threadIdx.x & 31, ty = threadIdx.x >> 5;
#pragma unroll
    for (int i = 0; i < 4; i++) {
        int r = ty + i * 8;
        if (n0 + tx < N) {
            float v = W[(size_t)(k0 + r) * N + n0 + tx];
            if (useScale) v *= rmsw[k0 + r];
            s[r][tx] = v;
        }
    }
    __syncthreads();
#pragma unroll
    for (int i = 0; i < 4; i++) {
        int r = ty + i * 8;
        if (n0 + r < N) {
            float v = s[tx][r];
            __half h = __float2half_rn(v);
            Th[(size_t)(rowOff + n0 + r) * C_DIM + k0 + tx] = h;
            Tl[(size_t)(rowOff + n0 + r) * C_DIM + k0 + tx] = __float2half_rn(v - __half2float(h));
        }
    }
}

// ---------------- Y -> fp16 with fused RMSNorm row scale ----------------
__global__ __launch_bounds__(256) void norm_to_fp16(
    const float* __restrict__ X, __half* __restrict__ Ah)
{
    int t = blockIdx.x, tid = threadIdx.x;
    float4 v = *reinterpret_cast<const float4*>(X + (size_t)t * C_DIM + tid * 4);
    float ss = v.x * v.x + v.y * v.y + v.z * v.z + v.w * v.w;
#pragma unroll
    for (int off = 16; off; off >>= 1) ss += __shfl_xor_sync(0xffffffff, ss, off);
    __shared__ float red[8];
    if ((tid & 31) == 0) red[tid >> 5] = ss;
    __syncthreads();
    float s = red[0];
#pragma unroll
    for (int i = 1; i < 8; i++) s += red[i];
    float scale = rsqrtf(s * (1.f / (float)C_DIM) + 1e-5f);
    uint2 hh = make_uint2(pack2h(v.x * scale, v.y * scale), pack2h(v.z * scale, v.w * scale));
    *reinterpret_cast<uint2*>(Ah + (size_t)t * C_DIM + tid * 4) = hh;
}

// ---------------- proj GEMM: 128x64 tiles (tile-count rebalance) ----------------
// grid (25, 16). Warps: 8 m-slices of 16 rows, each warp owns the full 64 cols
// (= one head, so RoPE pairs stay in-warp). 2-term fp16; gate block adds al*bh.
// stage 12KB: A@0 (4K) | Bh@4K (2K) | Bl@6K (2K) | Al@8K (4K, gate only); 3 stages.
__global__ __launch_bounds__(256, 2) void gemm_proj_f16(
    const __half* __restrict__ Ah, const __half* __restrict__ Al,
    const __half* __restrict__ Bh, const __half* __restrict__ Bl,
    float* __restrict__ G, __nv_bfloat16* __restrict__ Ph,
    __nv_bfloat16* __restrict__ Pl, int K)
{
    extern __shared__ char smc[];
    uint32_t sb = cvta_smem(smc);
    const uint32_t STG = 12288u;

    int tid = threadIdx.x, lane = tid & 31, wm = tid >> 5;
    int m0 = blockIdx.y * 128, n0 = blockIdx.x * 64;
    bool prec = ((int)blockIdx.x == GATE_BLK);

    // A mapping: 256 chunks (128 rows x 2)
    int lrow = tid >> 1, lc = tid & 1;
    uint32_t ldstA = phys16(lrow, lc);
    const __half* gA  = Ah + (size_t)(m0 + lrow) * K + lc * 8;
    const __half* gAl = Al + (size_t)(m0 + lrow) * K + lc * 8;
    // B mapping: 128 chunks each for Bh and Bl (64 rows x 2)
    int bt = tid & 127, brow = bt >> 1, bc2 = bt & 1;
    uint32_t ldstB = phys16(brow, bc2);
    bool isBl = tid >= 128;
    const __half* gB = (isBl ? Bl : Bh) + (size_t)(n0 + brow) * K + bc2 * 8;
    uint32_t bOff = isBl ? 6144u : 4096u;

    int nkt = K / 16;
    float acc[8][4] = {};

#pragma unroll
    for (int p = 0; p < 2; p++) {
        uint32_t st = sb + (uint32_t)p * STG;
        cpasync16(st + ldstA, gA + p * 16);
        cpasync16(st + bOff + ldstB, gB + p * 16);
        if (prec) cpasync16(st + 8192u + ldstA, gAl + p * 16);
        CP_COMMIT();
    }

    int aRow = (lane & 15), aC = lane >> 4;
    int bRowBase = (lane & 7) + ((lane >> 4) << 3);
    int bC = (lane >> 3) & 1;

    for (int kt = 0; kt < nkt; ++kt) {
        if (kt + 2 < nkt) { CP_WAIT(1); } else { CP_WAIT(0); }
        __syncthreads();

        uint32_t st = sb + (uint32_t)(kt % 3) * STG;
        uint32_t ah[4], al2[4];
        {
            int r = wm * 16 + aRow;
            ldsm4(ah, st + phys16(r, aC));
            if (prec) ldsm4(al2, st + 8192u + phys16(r, aC));
        }
#pragma unroll
        for (int g = 0; g < 4; g++) {
            int r = g * 16 + bRowBase;
            uint32_t bh4[4], bl4[4];
            ldsm4(bh4, st + 4096u + phys16(r, bC));
            ldsm4(bl4, st + 6144u + phys16(r, bC));
#pragma unroll
            for (int jj = 0; jj < 2; jj++) {
                int j = g * 2 + jj;
                mma_fp16(acc[j], ah, &bh4[2 * jj]);
                mma_fp16(acc[j], ah, &bl4[2 * jj]);
                if (prec) mma_fp16(acc[j], al2, &bh4[2 * jj]);
            }
        }

        if (kt + 2 < nkt) {
            uint32_t st2 = sb + (uint32_t)((kt + 2) % 3) * STG;
            int ko = (kt + 2) * 16;
            cpasync16(st2 + ldstA, gA + ko);
            cpasync16(st2 + bOff + ldstB, gB + ko);
            if (prec) cpasync16(st2 + 8192u + ldstA, gAl + ko);
            CP_COMMIT();
        }
    }

    // RoPE epilogue (Q,K head columns; this CTA = one head when n0 < 1280)
    if (n0 < 1280) {
#pragma unroll
        for (int j = 0; j < 4; j++) {
#pragma unroll
            for (int e = 0; e < 2; e++) {
                int d = j * 8 + 2 * (lane & 3) + e;
                float invf = expf(-(float)(2 * d) * (9.210340371976184f / 64.f));
#pragma unroll
                for (int rh = 0; rh < 2; rh++) {
                    int trow = m0 + wm * 16 + (lane >> 2) + rh * 8;
                    float sn, cs;
                    sincosf((float)trow * invf, &sn, &cs);
                    int k = 2 * rh + e;
                    float a = acc[j][k], b = acc[j + 4][k];
                    acc[j][k]     = a * cs - b * sn;
                    acc[j + 4][k] = b * cs + a * sn;
                }
            }
        }
    }

    if (!prec) {
        int r0 = m0 + wm * 16 + (lane >> 2);
#pragma unroll
        for (int j = 0; j < 8; j++) {
            int col = n0 + j * 8 + 2 * (lane & 3);
            float v0 = acc[j][0], v1 = acc[j][1], v2 = acc[j][2], v3 = acc[j][3];
            float h0 = __bfloat162float(__float2bfloat16_rn(v0));
            float h1 = __bfloat162float(__float2bfloat16_rn(v1));
            float h2 = __bfloat162float(__float2bfloat16_rn(v2));
            float h3 = __bfloat162float(__float2bfloat16_rn(v3));
            *reinterpret_cast<uint32_t*>(Ph + (size_t)r0 * QKV + col) = pack2bf(h0, h1);
            *reinterpret_cast<uint32_t*>(Pl + (size_t)r0 * QKV + col) = pack2bf(v0 - h0, v1 - h1);
            *reinterpret_cast<uint32_t*>(Ph + (size_t)(r0 + 8) * QKV + col) = pack2bf(h2, h3);
            *reinterpret_cast<uint32_t*>(Pl + (size_t)(r0 + 8) * QKV + col) = pack2bf(v2 - h2, v3 - h3);
        }
    } else {
        // gate cols = local 0..15 (j = 0,1); write transposed G[h][t]
        int r0 = m0 + wm * 16 + (lane >> 2);
#pragma unroll
        for (int j = 0; j < 2; j++) {
            int colg = j * 8 + 2 * (lane & 3);
            G[(size_t)colg * T_SEQ + r0] = acc[j][0];
            G[(size_t)(colg + 1) * T_SEQ + r0] = acc[j][1];
            G[(size_t)colg * T_SEQ + r0 + 8] = acc[j][2];
            G[(size_t)(colg + 1) * T_SEQ + r0 + 8] = acc[j][3];
        }
    }
}

// ---------------- out GEMM: fp16 A (single) x (Bh+Bl), 2-term ----------------
__global__ __launch_bounds__(256, 2) void gemm_out_f16(
    const __half* __restrict__ Ah, const __half* __restrict__ Bh,
    const __half* __restrict__ Bl, float* __restrict__ C,
    int M, int N, int K)
{
    extern __shared__ char smc[];
    uint32_t sb = cvta_smem(smc);
    const uint32_t STG = 12288u;

    int tid = threadIdx.x, lane = tid & 31, warp = tid >> 5;
    int wm = warp & 3, wn = warp >> 2;
    int m0 = blockIdx.y * 128, n0 = blockIdx.x * 128;

    int lrow = tid >> 1, lc = tid & 1;
    uint32_t ldst = phys16(lrow, lc);
    const __half* gA = Ah + (size_t)(m0 + lrow) * K + lc * 8;
    const __half* gBh = Bh + (size_t)(n0 + lrow) * K + lc * 8;
    const __half* gBl = Bl + (size_t)(n0 + lrow) * K + lc * 8;

    int nkt = K / 16;
    float acc[2][8][4] = {};

#pragma unroll
    for (int p = 0; p < 2; p++) {
        uint32_t st = sb + (uint32_t)p * STG;
        cpasync16(st + ldst,          gA + p * 16);
        cpasync16(st + 4096u + ldst,  gBh + p * 16);
        cpasync16(st + 8192u + ldst,  gBl + p * 16);
        CP_COMMIT();
    }

    int aRow = (lane & 15), aC = lane >> 4;
    int bRowBase = (lane & 7) + ((lane >> 4) << 3);
    int bC = (lane >> 3) & 1;

    for (int kt = 0; kt < nkt; ++kt) {
        if (kt + 2 < nkt) { CP_WAIT(1); } else { CP_WAIT(0); }
        __syncthreads();

        uint32_t st = sb + (uint32_t)(kt % 3) * STG;
        uint32_t ah[2][4];
#pragma unroll
        for (int t = 0; t < 2; t++) {
            int r = wm * 32 + t * 16 + aRow;
            ldsm4(ah[t], st + phys16(r, aC));
        }
#pragma unroll
        for (int g = 0; g < 4; g++) {
            int r = wn * 64 + g * 16 + bRowBase;
            uint32_t bh[4], bl[4];
            ldsm4(bh, st + 4096u + phys16(r, bC));
            ldsm4(bl, st + 8192u + phys16(r, bC));
#pragma unroll
            for (int t = 0; t < 2; t++)
#pragma unroll
                for (int jj = 0; jj < 2; jj++) {
                    int j = g * 2 + jj;
                    mma_fp16(acc[t][j], ah[t], &bh[2 * jj]);
                    mma_fp16(acc[t][j], ah[t], &bl[2 * jj]);
                }
        }

        if (kt + 2 < nkt) {
            uint32_t st2 = sb + (uint32_t)((kt + 2) % 3) * STG;
            int ko = (kt + 2) * 16;
            cpasync16(st2 + ldst,          gA + ko);
            cpasync16(st2 + 4096u + ldst,  gBh + ko);
            cpasync16(st2 + 8192u + ldst,  gBl + ko);
            CP_COMMIT();
        }
    }

#pragma unroll
    for (int t = 0; t < 2; t++) {
        int r0 = m0 + wm * 32 + t * 16 + (lane >> 2);
#pragma unroll
        for (int j = 0; j < 8; j++) {
            int col = n0 + wn * 64 + j * 8 + 2 * (lane & 3);
            *reinterpret_cast<float2*>(C + (size_t)r0 * N + col) = make_float2(acc[t][j][0], acc[t][j][1]);
            *reinterpret_cast<float2*>(C + (size_t)(r0 + 8) * N + col) = make_float2(acc[t][j][2], acc[t][j][3]);
        }
    }
}

// ---------------- per-head scan (warp-shuffle, coalesced G reads) ----------------
__global__ __launch_bounds__(256) void scan_kernel(
    const float* __restrict__ G, const float* __restrict__ bg,
    float* __restrict__ D, float* __restrict__ L)
{
    int h = blockIdx.x, tid = threadIdx.x, lane = tid & 31, wid = tid >> 5;
    float b = bg[h];
    float4 a0 = *reinterpret_cast<const float4*>(G + (size_t)h * T_SEQ + tid * 8);
    float4 a1 = *reinterpret_cast<const float4*>(G + (size_t)h * T_SEQ + tid * 8 + 4);
    float gv[8] = {a0.x, a0.y, a0.z, a0.w, a1.x, a1.y, a1.z, a1.w};
    float vals[8];
    float run = 0.f;
#pragma unroll
    for (int i = 0; i < 8; i++) {
        float gg = gv[i] + b;
        run += log_sigmoid_f(gg);
        vals[i] = run;
        L[h * T_SEQ + tid * 8 + i] = log_sigmoid_f(-gg);
    }
    float x = run;
#pragma unroll
    for (int off = 1; off < 32; off <<= 1) {
        float y = __shfl_up_sync(0xffffffff, x, off);
        if (lane >= off) x += y;
    }
    __shared__ float wsum[8];
    if (lane == 31) wsum[wid] = x;
    __syncthreads();
    float woff = 0.f;
#pragma unroll
    for (int w = 0; w < 8; w++) if (w < wid) woff += wsum[w];
    float excl = x - run + woff;
#pragma unroll
    for (int i = 0; i < 8; i++) D[h * T_SEQ + tid * 8 + i] = vals[i] + excl;
}

// ---------------- fused attention (register-P, bf16x3, cp.async tiles) ----------------
#define OFF_Q  0u
#define OFF_K  16384u
#define OFF_V  32768u
#define OFF_S  49152u
#define SSTR   132
#define OFF_SC (49152u + 64u * SSTR * 4u)

__device__ __forceinline__ void pv_mma(
    uint32_t sbV, uint32_t pah[2][4], uint32_t pal[2][4],
    float (*oacc)[4], int wn, int lane)
{
#pragma unroll
    for (int u = 0; u < 2; u++) {
        int vrow = wn * 32 + u * 16 + (lane & 15);
        uint32_t vb = sbV + (uint32_t)vrow * 128u;
#pragma unroll
        for (int gg = 0; gg < 4; gg++) {
            int cch = 2 * gg + (lane >> 4);
            uint32_t vh[4], vl[4];
            ldsm4t(vh, vb + (uint32_t)((cch ^ (vrow & 7)) * 16));
            ldsm4t(vl, vb + 8192u + (uint32_t)((cch ^ (vrow & 7)) * 16));
#pragma unroll
            for (int jj = 0; jj < 2; jj++) {
                int j = gg * 2 + jj;
                mma_bf16(oacc[j], pah[u], &vh[2 * jj]);
                mma_bf16(oacc[j], pah[u], &vl[2 * jj]);
                mma_bf16(oacc[j], pal[u], &vh[2 * jj]);
            }
        }
    }
}

__global__ __launch_bounds__(256, 2) void attn_fused(
    const __nv_bfloat16* __restrict__ Ph, const __nv_bfloat16* __restrict__ Pl,
    const float* __restrict__ D, const float* __restrict__ L,
    float* __restrict__ Y)
{
    extern __shared__ char smc[];
    uint32_t sb = cvta_smem(smc);
    float* smS  = reinterpret_cast<float*>(smc + OFF_S);
    float* Dq   = reinterpret_cast<float*>(smc + OFF_SC);
    float* rowE = Dq + 64;
    float* Ds   = rowE + 64;
    float* Ls   = Ds + 64;
    float* colE = Ls + 64;

    int qt = blockIdx.x, h = blockIdx.y;
    int kvh = h >> 2;
    int tid = threadIdx.x, lane = tid & 31, warp = tid >> 5;
    int wm = warp & 3, wn = warp >> 2;
    int t0 = qt * 64;
    int w0 = (t0 / WINSZ) * WINSZ;
    int wt0 = w0 / 64;
    int nk = t0 - w0 + 64;

    cp_tile(Ph + (size_t)t0 * QKV + h * DHD, Pl + (size_t)t0 * QKV + h * DHD,
            sb + OFF_Q, sb + OFF_Q + 8192u, tid);
    CP_COMMIT();
    if (tid < 64) Dq[tid] = D[h * T_SEQ + t0 + tid];
    CP_WAIT(0);
    __syncthreads();
    float dq0 = Dq[0];
    if (tid < 64) rowE[tid] = expf(Dq[tid] - dq0);

    int fr0 = wm * 16 + (lane >> 2);
    int fcb = wn * 32 + 2 * (lane & 3);

    float oacc[8][4] = {};

    for (int st = qt; st >= 0; --st) {
        int s0 = st * 64;
        bool inwin = (st >= wt0);
        if (!inwin) {
            float dend = D[h * T_SEQ + s0 + 63];
            if (dq0 - dend < DECAY_CUTOFF) break;
        }
        __syncthreads();

        cp_tile(Ph + (size_t)s0 * QKV + KOFF + kvh * DHD, Pl + (size_t)s0 * QKV + KOFF + kvh * DHD,
                sb + OFF_K, sb + OFF_K + 8192u, tid);
        cp_tile(Ph + (size_t)s0 * QKV + VOFF + kvh * DHD, Pl + (size_t)s0 * QKV + VOFF + kvh * DHD,
                sb + OFF_V, sb + OFF_V + 8192u, tid);
        CP_COMMIT();
        if (tid < 64) {
            float ds = D[h * T_SEQ + s0 + tid];
            float ls = L[h * T_SEQ + s0 + tid];
            Ds[tid] = ds; Ls[tid] = ls;
            colE[tid] = expf(dq0 - ds + ls);
        }
        CP_WAIT(0);
        __syncthreads();

        float sacc[4][4] = {};
        {
            int arow = wm * 16 + (lane & 15);
            int asel = lane >> 4;
            int nrow = wn * 32 + (lane & 7) + ((lane >> 4) << 3);
            int bsel = (lane >> 3) & 1;
#pragma unroll
            for (int ks = 0; ks < 4; ks++) {
                uint32_t ah[4], al[4];
                uint32_t abase = sb + OFF_Q + (uint32_t)arow * 128u;
                ldsm4(ah, abase + (uint32_t)(((2 * ks + asel) ^ (arow & 7)) * 16));
                ldsm4(al, abase + 8192u + (uint32_t)(((2 * ks + asel) ^ (arow & 7)) * 16));
                uint32_t bh[2][4], bl[2][4];
#pragma unroll
                for (int g = 0; g < 2; g++) {
                    int r = nrow + g * 16;
                    uint32_t bbase = sb + OFF_K + (uint32_t)r * 128u;
                    ldsm4(bh[g], bbase + (uint32_t)(((2 * ks + bsel) ^ (r & 7)) * 16));
                    ldsm4(bl[g], bbase + 8192u + (uint32_t)(((2 * ks + bsel) ^ (r & 7)) * 16));
                }
#pragma unroll
                for (int j = 0; j < 4; j++) {
                    const uint32_t* b2h = &bh[j >> 1][2 * (j & 1)];
                    const uint32_t* b2l = &bl[j >> 1][2 * (j & 1)];
                    mma_bf16(sacc[j], ah, b2h);
                    mma_bf16(sacc[j], ah, b2l);
                    mma_bf16(sacc[j], al, b2h);
                }
            }
        }

        uint32_t pah[2][4], pal[2][4];
        {
            int colbase = s0 - w0;
#pragma unroll
            for (int j = 0; j < 4; j++) {
                int cj = fcb + 8 * j;
#pragma unroll
                for (int half = 0; half < 2; half++) {
                    int r = fr0 + half * 8;
                    float v0 = sacc[j][2 * half], v1 = sacc[j][2 * half + 1];
                    if (inwin) {
                        float l0 = (s0 + cj     <= t0 + r) ? v0 * 0.125f : neg_inf();
                        float l1 = (s0 + cj + 1 <= t0 + r) ? v1 * 0.125f : neg_inf();
                        *reinterpret_cast<float2*>(&smS[r * SSTR + colbase + cj]) = make_float2(l0, l1);
                    }
                    float p0, p1;
                    if (st == qt) {
                        p0 = (cj     <= r) ? v0 * expf(Dq[r] - Ds[cj] + Ls[cj]) : 0.f;
                        p1 = (cj + 1 <= r) ? v1 * expf(Dq[r] - Ds[cj + 1] + Ls[cj + 1]) : 0.f;
                    } else {
                        float re = rowE[r];
                        p0 = v0 * (re * colE[cj]);
                        p1 = v1 * (re * colE[cj + 1]);
                    }
                    float h0 = __bfloat162float(__float2bfloat16_rn(p0));
                    float h1 = __bfloat162float(__float2bfloat16_rn(p1));
                    int u = j >> 1, ri = (j & 1) * 2 + half;
                    pah[u][ri] = pack2bf(h0, h1);
                    pal[u][ri] = pack2bf(p0 - h0, p1 - h1);
                }
            }
        }

        pv_mma(sb + OFF_V, pah, pal, oacc, wn, lane);
    }

    __syncthreads();
    {
        int r = tid >> 2, g = tid & 3;
        float m = neg_inf();
        for (int c = g; c < nk; c += 4) m = fmaxf(m, smS[r * SSTR + c]);
        m = fmaxf(m, __shfl_xor_sync(0xffffffff, m, 1));
        m = fmaxf(m, __shfl_xor_sync(0xffffffff, m, 2));
        float sum = 0.f;
        for (int c = g; c < nk; c += 4) {
            float e = expf(smS[r * SSTR + c] - m);
            smS[r * SSTR + c] = e;
            sum += e;
        }
        sum += __shfl_xor_sync(0xffffffff, sum, 1);
        sum += __shfl_xor_sync(0xffffffff, sum, 2);
        float inv = 1.f / sum;
        for (int c = g; c < nk; c += 4) smS[r * SSTR + c] *= inv;
    }

    for (int kh = 0; kh < (nk >> 6); kh++) {
        __syncthreads();
        cp_tile(Ph + (size_t)(w0 + kh * 64) * QKV + VOFF + kvh * DHD,
                Pl + (size_t)(w0 + kh * 64) * QKV + VOFF + kvh * DHD,
                sb + OFF_V, sb + OFF_V + 8192u, tid);
        CP_COMMIT();
        CP_WAIT(0);
        __syncthreads();
        uint32_t pah[2][4], pal[2][4];
#pragma unroll
        for (int u = 0; u < 2; u++) {
            int bc = kh * 64 + wn * 32 + u * 16 + 2 * (lane & 3);
            float2 f0 = *reinterpret_cast<const float2*>(&smS[fr0 * SSTR + bc]);
            float2 f1 = *reinterpret_cast<const float2*>(&smS[(fr0 + 8) * SSTR + bc]);
            float2 f2 = *reinterpret_cast<const float2*>(&smS[fr0 * SSTR + bc + 8]);
            float2 f3 = *reinterpret_cast<const float2*>(&smS[(fr0 + 8) * SSTR + bc + 8]);
            float h, h2;
            h = __bfloat162float(__float2bfloat16_rn(f0.x));
            h2 = __bfloat162float(__float2bfloat16_rn(f0.y));
            pah[u][0] = pack2bf(h, h2); pal[u][0] = pack2bf(f0.x - h, f0.y - h2);
            h = __bfloat162float(__float2bfloat16_rn(f1.x));
            h2 = __bfloat162float(__float2bfloat16_rn(f1.y));
            pah[u][1] = pack2bf(h, h2); pal[u][1] = pack2bf(f1.x - h, f1.y - h2);
            h = __bfloat162float(__float2bfloat16_rn(f2.x));
            h2 = __bfloat162float(__float2bfloat16_rn(f2.y));
            pah[u][2] = pack2bf(h, h2); pal[u][2] = pack2bf(f2.x - h, f2.y - h2);
            h = __bfloat162float(__float2bfloat16_rn(f3.x));
            h2 = __bfloat162float(__float2bfloat16_rn(f3.y));
            pah[u][3] = pack2bf(h, h2); pal[u][3] = pack2bf(f3.x - h, f3.y - h2);
        }
        pv_mma(sb + OFF_V, pah, pal, oacc, wn, lane);
    }

    __syncthreads();
    float* redb = reinterpret_cast<float*>(smc + OFF_K);
    if (wn == 1) {
        int base = (wm * 32 + lane) * 32;
#pragma unroll
        for (int j = 0; j < 8; j++)
#pragma unroll
            for (int k = 0; k < 4; k++) redb[base + j * 4 + k] = oacc[j][k];
    }
    __syncthreads();
    if (wn == 0) {
        int base = (wm * 32 + lane) * 32;
#pragma unroll
        for (int j = 0; j < 8; j++) {
            float o0 = oacc[j][0] + redb[base + j * 4 + 0];
            float o1 = oacc[j][1] + redb[base + j * 4 + 1];
            float o2 = oacc[j][2] + redb[base + j * 4 + 2];
            float o3 = oacc[j][3] + redb[base + j * 4 + 3];
            int col = h * DHD + j * 8 + 2 * (lane & 3);
            *reinterpret_cast<float2*>(Y + (size_t)(t0 + fr0) * C_DIM + col) = make_float2(o0, o1);
            *reinterpret_cast<float2*>(Y + (size_t)(t0 + fr0 + 8) * C_DIM + col) = make_float2(o2, o3);
        }
    }
}

// ---------------- launch ----------------
extern "C" void kernel_launch(void* const* d_in, const int* in_sizes, int n_in,
                              void* d_out, int out_size)
{
    (void)in_sizes; (void)n_in; (void)out_size;
    const float* x    = (const float*)d_in[0];
    const float* Wq   = (const float*)d_in[1];
    const float* Wk   = (const float*)d_in[2];
    const float* Wv   = (const float*)d_in[3];
    const float* Wc   = (const float*)d_in[4];
    const float* Wg   = (const float*)d_in[5];
    const float* bg   = (const float*)d_in[6];
    const float* rmsw = (const float*)d_in[7];
    float* out = (float*)d_out;

    float *G, *D, *L, *Y;
    __nv_bfloat16 *Ph, *Pl;
    __half *Xh, *Xl, *Yh, *Wph, *Wpl, *Wch, *Wcl;
    cudaGetSymbolAddress((void**)&G, g_G);
    cudaGetSymbolAddress((void**)&Ph, g_Ph);
    cudaGetSymbolAddress((void**)&Pl, g_Pl);
    cudaGetSymbolAddress((void**)&D, g_D);
    cudaGetSymbolAddress((void**)&L, g_L);
    cudaGetSymbolAddress((void**)&Y, g_Y);
    cudaGetSymbolAddress((void**)&Xh, g_Xh);
    cudaGetSymbolAddress((void**)&Xl, g_Xl);
    cudaGetSymbolAddress((void**)&Yh, g_Yh);
    cudaGetSymbolAddress((void**)&Wph, g_Wp_h);
    cudaGetSymbolAddress((void**)&Wpl, g_Wp_l);
    cudaGetSymbolAddress((void**)&Wch, g_Wc_h);
    cudaGetSymbolAddress((void**)&Wcl, g_Wc_l);

    prepass_all<<<dim3(32, 32, 6), 256>>>(Wq, Wk, Wv, Wc, Wg, rmsw, x,
                                          Wph, Wpl, Wch, Wcl, Xh, Xl);

    // proj: 128x64 tiles, grid (25,16)=400 CTAs (pad block dropped)
    size_t smemP = 3 * 12288;
    cudaFuncSetAttribute(gemm_proj_f16, cudaFuncAttributeMaxDynamicSharedMemorySize, (int)smemP);
    gemm_proj_f16<<<dim3(25, T_SEQ / 128), 256, smemP>>>(Xh, Xl, Wph, Wpl, G, Ph, Pl, C_DIM);

    scan_kernel<<<NH, 256>>>(G, bg, D, L);

    size_t smemA = OFF_SC + 6 * 64 * sizeof(float);
    cudaFuncSetAttribute(attn_fused, cudaFuncAttributeMaxDynamicSharedMemorySize, (int)smemA);
    attn_fused<<<dim3(T_SEQ / 64, NH), 256, smemA>>>(Ph, Pl, D, L, Y);

    norm_to_fp16<<<T_SEQ, 256>>>(Y, Yh);

    size_t smemO = 3 * 12288;
    cudaFuncSetAttribute(gemm_out_f16, cudaFuncAttributeMaxDynamicSharedMemorySize, (int)smemO);
    gemm_out_f16<<<dim3(C_DIM / 128, T_SEQ / 128), 256, smemO>>>(Yh, Wch, Wcl, out, T_SEQ, C_DIM, C_DIM);
}